// round 12
// baseline (speedup 1.0000x reference)
#include <cuda_runtime.h>
#include <cuda_bf16.h>
#include <math.h>

// Problem constants
#define BB 2
#define TT 4096
#define CC 1024
#define NH 8
#define DD 128
#define CHK 64
#define NCHUNK 64            // T / CHK
#define NCID 1024            // BB*NH*NCHUNK

// ---------------- scratch (device globals; no allocation allowed) ----------------
__device__ float g_qkvz[(size_t)BB*TT*4096];     // x @ W_qkvz      (B,T,8,512)
__device__ float g_conv[(size_t)BB*TT*3072];     // conv+silu [q|k|v]
__device__ float g_g[(size_t)BB*TT*NH];
__device__ float g_beta[(size_t)BB*TT*NH];
__device__ float g_P[(size_t)NCID*64*128];       // qeff - attn@k_cum
__device__ float g_L[(size_t)NCID*64*128];       // attn@v_new
__device__ float g_M[(size_t)NCID*128*128];      // keff^T @ k_cum
__device__ float g_U[(size_t)NCID*128*128];      // keff^T @ v_new
__device__ float g_egl[NCID];                    // exp(g_last)
__device__ float g_core[(size_t)BB*TT*NH*DD];    // delta-rule output

// bf16 hi/lo split operands for the two big GEMMs
__device__ __nv_bfloat16 g_xh[(size_t)BB*TT*CC],  g_xl[(size_t)BB*TT*CC];
__device__ __nv_bfloat16 g_w1h[(size_t)4096*CC],  g_w1l[(size_t)4096*CC];   // W_qkvz^T [N][K]
__device__ __nv_bfloat16 g_w2h[(size_t)1024*CC],  g_w2l[(size_t)1024*CC];   // W_out^T  [N][K]
__device__ __nv_bfloat16 g_hh[(size_t)BB*TT*1024], g_hl[(size_t)BB*TT*1024];

// ---------------- split/transpose conversion kernels ----------------------------
__global__ __launch_bounds__(256) void cvt_split_kernel(const float* __restrict__ in,
        __nv_bfloat16* __restrict__ oh, __nv_bfloat16* __restrict__ ol)
{
    int i = blockIdx.x * 256 + threadIdx.x;            // indexes float4
    float4 v = ((const float4*)in)[i];
    float f[4] = {v.x, v.y, v.z, v.w};
    __nv_bfloat16 h[4], l[4];
#pragma unroll
    for (int e = 0; e < 4; e++) {
        h[e] = __float2bfloat16_rn(f[e]);
        l[e] = __float2bfloat16_rn(f[e] - __bfloat162float(h[e]));
    }
    __nv_bfloat162 h0; h0.x = h[0]; h0.y = h[1];
    __nv_bfloat162 h1; h1.x = h[2]; h1.y = h[3];
    __nv_bfloat162 l0; l0.x = l[0]; l0.y = l[1];
    __nv_bfloat162 l1; l1.x = l[2]; l1.y = l[3];
    ((__nv_bfloat162*)oh)[i * 2]     = h0;
    ((__nv_bfloat162*)oh)[i * 2 + 1] = h1;
    ((__nv_bfloat162*)ol)[i * 2]     = l0;
    ((__nv_bfloat162*)ol)[i * 2 + 1] = l1;
}

// W [K][N] f32 -> Wt [N][K] bf16 hi/lo
__global__ __launch_bounds__(256) void transpose_split_kernel(const float* __restrict__ W,
        __nv_bfloat16* __restrict__ oh, __nv_bfloat16* __restrict__ ol, int K, int N)
{
    __shared__ float tile[32][33];
    int n0 = blockIdx.x * 32, k0 = blockIdx.y * 32;
    int tx = threadIdx.x & 31, ty0 = threadIdx.x >> 5;
#pragma unroll
    for (int ty = ty0; ty < 32; ty += 8)
        tile[ty][tx] = W[(size_t)(k0 + ty) * N + n0 + tx];
    __syncthreads();
#pragma unroll
    for (int ty = ty0; ty < 32; ty += 8) {
        float v = tile[tx][ty];
        __nv_bfloat16 h = __float2bfloat16_rn(v);
        size_t o = (size_t)(n0 + ty) * K + k0 + tx;
        oh[o] = h;
        ol[o] = __float2bfloat16_rn(v - __bfloat162float(h));
    }
}

// ---------------- asm helpers ----------------------------------------------------
#define MMA_BF16(C, Ar, Br)                                                    \
    asm volatile("mma.sync.aligned.m16n8k16.row.col.f32.bf16.bf16.f32 "        \
        "{%0,%1,%2,%3}, {%4,%5,%6,%7}, {%8,%9}, {%0,%1,%2,%3};"                \
        : "+f"((C)[0]), "+f"((C)[1]), "+f"((C)[2]), "+f"((C)[3])               \
        : "r"((Ar)[0]), "r"((Ar)[1]), "r"((Ar)[2]), "r"((Ar)[3]),              \
          "r"((Br)[0]), "r"((Br)[1]))

#define LDSM4(R0, R1, R2, R3, ADDR)                                            \
    asm volatile("ldmatrix.sync.aligned.m8n8.x4.shared.b16 {%0,%1,%2,%3}, [%4];" \
        : "=r"(R0), "=r"(R1), "=r"(R2), "=r"(R3) : "r"(ADDR))

#define CP_ASYNC16(DST, SRC)                                                   \
    asm volatile("cp.async.cg.shared.global [%0], [%1], 16;" :: "r"(DST), "l"(SRC))
#define CP_COMMIT() asm volatile("cp.async.commit_group;" ::: "memory")
#define CP_WAIT0()  asm volatile("cp.async.wait_group 0;" ::: "memory")
#define CP_WAIT1()  asm volatile("cp.async.wait_group 1;" ::: "memory")

// ---------------- 3xBF16-split GEMM: C = A(MxK)@B^T(NxK), pre-split bf16 --------
// 128(M) x 256(N) tile per block, 512 threads, 1 block/SM.
// 40% less L2 staging traffic per HMMA than the 128x128 variant.
#define GKS 40                                   // bf16 k-stride (80B rows, conflict-free)
#define A_BYT (128 * GKS * 2)                    // 10240 bytes per A array
#define B_BYT (256 * GKS * 2)                    // 20480 bytes per B array
#define STG2  (2 * A_BYT + 2 * B_BYT)            // 61440 bytes per stage
#define GEMM_SMEM (2 * STG2)                     // 122880 bytes

__global__ __launch_bounds__(512, 1) void bf16gemm256(int M, int N, int K,
        const __nv_bfloat16* __restrict__ Ah_, const __nv_bfloat16* __restrict__ Al_,
        const __nv_bfloat16* __restrict__ Bth_, const __nv_bfloat16* __restrict__ Btl_,
        float* __restrict__ Cm)
{
    extern __shared__ __nv_bfloat16 gsm[];
    unsigned smemBase = (unsigned)__cvta_generic_to_shared(gsm);

    int tid = threadIdx.x;
    int brow = blockIdx.y * 128, bcol = blockIdx.x * 256;
    int warp = tid >> 5, lane = tid & 31;
    int wm = (warp & 1) * 64, wn = (warp >> 1) * 32;       // 2 x 8 warp grid
    int lr = lane >> 2, lc2 = (lane & 3) * 2;

    // staging indices: A 1 chunk/thread/array, B 2 chunks/thread/array
    int rA = tid >> 2, kgA = (tid & 3) * 8;
    unsigned dA = (unsigned)(rA * GKS + kgA) * 2;
    int rB0 = tid >> 2, rB1 = rB0 + 128;                   // B rows 0..255
    unsigned dB0 = (unsigned)(rB0 * GKS + kgA) * 2;
    unsigned dB1 = (unsigned)(rB1 * GKS + kgA) * 2;
    const __nv_bfloat16* sAh = Ah_  + (size_t)(brow + rA)  * K + kgA;
    const __nv_bfloat16* sAl = Al_  + (size_t)(brow + rA)  * K + kgA;
    const __nv_bfloat16* sB0h = Bth_ + (size_t)(bcol + rB0) * K + kgA;
    const __nv_bfloat16* sB1h = Bth_ + (size_t)(bcol + rB1) * K + kgA;
    const __nv_bfloat16* sB0l = Btl_ + (size_t)(bcol + rB0) * K + kgA;
    const __nv_bfloat16* sB1l = Btl_ + (size_t)(bcol + rB1) * K + kgA;

    // ldmatrix per-lane byte offsets (within an array)
    unsigned aoff = (unsigned)(((wm + (lane & 15)) * GKS) + ((lane >> 4) * 8)) * 2;
    unsigned boff = (unsigned)(((wn + (lane & 7) + (((lane >> 4) & 1) * 8)) * GKS)
                               + (((lane >> 3) & 1) * 8)) * 2;

    float c[4][4][4];
#pragma unroll
    for (int mt = 0; mt < 4; mt++)
#pragma unroll
        for (int nt = 0; nt < 4; nt++)
#pragma unroll
            for (int e = 0; e < 4; e++) c[mt][nt][e] = 0.f;

    // prologue: stage chunk 0 into buffer 0
    {
        unsigned sb = smemBase;
        CP_ASYNC16(sb + dA,                          sAh);
        CP_ASYNC16(sb + A_BYT + dA,                  sAl);
        CP_ASYNC16(sb + 2 * A_BYT + dB0,             sB0h);
        CP_ASYNC16(sb + 2 * A_BYT + dB1,             sB1h);
        CP_ASYNC16(sb + 2 * A_BYT + B_BYT + dB0,     sB0l);
        CP_ASYNC16(sb + 2 * A_BYT + B_BYT + dB1,     sB1l);
        CP_COMMIT();
    }

    int buf = 0;
    for (int k0 = 0; k0 < K; k0 += 32) {
        bool hasNext = (k0 + 32) < K;
        if (hasNext) {
            unsigned sb = smemBase + (buf ^ 1) * STG2;
            int kn = k0 + 32;
            CP_ASYNC16(sb + dA,                          sAh + kn);
            CP_ASYNC16(sb + A_BYT + dA,                  sAl + kn);
            CP_ASYNC16(sb + 2 * A_BYT + dB0,             sB0h + kn);
            CP_ASYNC16(sb + 2 * A_BYT + dB1,             sB1h + kn);
            CP_ASYNC16(sb + 2 * A_BYT + B_BYT + dB0,     sB0l + kn);
            CP_ASYNC16(sb + 2 * A_BYT + B_BYT + dB1,     sB1l + kn);
            CP_COMMIT();
            CP_WAIT1();
        } else {
            CP_WAIT0();
        }
        __syncthreads();

        unsigned aBh = smemBase + buf * STG2;
        unsigned aBl = aBh + A_BYT;
        unsigned bBh = aBh + 2 * A_BYT;
        unsigned bBl = bBh + B_BYT;

#pragma unroll
        for (int kk = 0; kk < 32; kk += 16) {
            unsigned ah[4][4], al[4][4], bh[2][4], bl[2][4];
#pragma unroll
            for (int mt = 0; mt < 4; mt++) {
                unsigned off = aoff + (unsigned)(mt * 16 * GKS + kk) * 2;
                LDSM4(ah[mt][0], ah[mt][1], ah[mt][2], ah[mt][3], aBh + off);
                LDSM4(al[mt][0], al[mt][1], al[mt][2], al[mt][3], aBl + off);
            }
#pragma unroll
            for (int p = 0; p < 2; p++) {
                unsigned off = boff + (unsigned)(p * 16 * GKS + kk) * 2;
                LDSM4(bh[p][0], bh[p][1], bh[p][2], bh[p][3], bBh + off);
                LDSM4(bl[p][0], bl[p][1], bl[p][2], bl[p][3], bBl + off);
            }
#pragma unroll
            for (int mt = 0; mt < 4; mt++)
#pragma unroll
                for (int nt = 0; nt < 4; nt++) {
                    unsigned* bhp = &bh[nt >> 1][(nt & 1) * 2];
                    unsigned* blp = &bl[nt >> 1][(nt & 1) * 2];
                    MMA_BF16(c[mt][nt], ah[mt], bhp);
                    MMA_BF16(c[mt][nt], al[mt], bhp);
                    MMA_BF16(c[mt][nt], ah[mt], blp);
                }
        }
        __syncthreads();
        buf ^= 1;
    }

#pragma unroll
    for (int mt = 0; mt < 4; mt++) {
        int r0 = brow + wm + mt * 16 + lr;
#pragma unroll
        for (int nt = 0; nt < 4; nt++) {
            int cn = bcol + wn + nt * 8 + lc2;
            *(float2*)(Cm + (size_t)r0 * N + cn)       = make_float2(c[mt][nt][0], c[mt][nt][1]);
            *(float2*)(Cm + (size_t)(r0 + 8) * N + cn) = make_float2(c[mt][nt][2], c[mt][nt][3]);
        }
    }
}

// ---------------- fused ba = x @ W_ba -> g, beta ---------------------------------
__global__ __launch_bounds__(256) void ba_gbeta_kernel(const float* __restrict__ x,
        const float* __restrict__ Wba, const float* __restrict__ dtb,
        const float* __restrict__ Alog, float* __restrict__ g, float* __restrict__ beta)
{
    int bt = blockIdx.x;
    __shared__ float xs[1024];
    const float* xrow = x + (size_t)bt * 1024;
    for (int i = threadIdx.x; i < 256; i += 256)
        ((float4*)xs)[i] = ((const float4*)xrow)[i];
    __syncthreads();
    int o = threadIdx.x >> 4, p = threadIdx.x & 15;
    float acc = 0.f;
    for (int k = p; k < 1024; k += 16) acc += xs[k] * Wba[(size_t)k * 16 + o];
    acc += __shfl_down_sync(0xffffffffu, acc, 8);
    acc += __shfl_down_sync(0xffffffffu, acc, 4);
    acc += __shfl_down_sync(0xffffffffu, acc, 2);
    acc += __shfl_down_sync(0xffffffffu, acc, 1);
    if (p == 0) {
        int h = o >> 1;
        if ((o & 1) == 0) {
            beta[(size_t)bt * 8 + h] = 1.f / (1.f + expf(-acc));
        } else {
            float xx = acc + dtb[h];
            float sp = (xx > 20.f) ? xx : log1pf(expf(xx));
            g[(size_t)bt * 8 + h] = -expf(Alog[h]) * sp;
        }
    }
}

// ---------------- causal depthwise conv (K=4) + silu ----------------------------
__global__ __launch_bounds__(256) void conv_silu_kernel(const float* __restrict__ qkvz,
        const float* __restrict__ cw, float* __restrict__ out)
{
    int idx = blockIdx.x * 256 + threadIdx.x;
    int ch = idx % 3072;
    int btrow = idx / 3072;
    int t = btrow & (TT - 1);
    int part = ch >> 10;
    int hc = (ch & 1023) >> 7;
    int d = ch & 127;
    int po = (part == 0) ? 0 : (part == 1) ? 128 : 256;
    float acc = 0.f;
#pragma unroll
    for (int j = 0; j < 4; j++) {
        int tt2 = t - 3 + j;
        if (tt2 >= 0) {
            float v = qkvz[(((size_t)(btrow - 3 + j)) * 8 + hc) * 512 + po + d];
            acc += v * cw[ch * 4 + j];
        }
    }
    out[(size_t)idx] = acc / (1.f + __expf(-acc));
}

// ---------------- Phase A: per-chunk local operators (register-tiled) -----------
#define KST 68
#define ASD 65
#define PA_SMEM ((128*KST*2 + 64*256 + 64*ASD + 256) * 4)

__global__ __launch_bounds__(256) void phaseA_kernel(const float* __restrict__ conv,
        const float* __restrict__ gbuf, const float* __restrict__ betabuf,
        float* __restrict__ Pout, float* __restrict__ Lout,
        float* __restrict__ Mout, float* __restrict__ Uout, float* __restrict__ eglout)
{
    extern __shared__ float sm[];
    float* kst = sm;
    float* qst = kst + 128 * KST;
    float* ws  = qst + 128 * KST;
    float* As  = ws + 64 * 256;          // 64 x ASD
    float* gc  = As + 64 * ASD;
    float* egc = gc + 64;
    float* egr = egc + 64;
    float* bts = egr + 64;

    int cid = blockIdx.x;
    int n = cid & 63, bh = cid >> 6, h = bh & 7, b = bh >> 3;
    int tid = threadIdx.x;
    int warp = tid >> 5, lane = tid & 31;
    int t0 = n * 64;

    if (tid < 64) {
        int t = t0 + tid;
        gc[tid]  = gbuf[((size_t)(b * TT + t)) * 8 + h];
        bts[tid] = betabuf[((size_t)(b * TT + t)) * 8 + h];
    }
    __syncthreads();
#pragma unroll
    for (int off = 1; off < 64; off <<= 1) {
        float v = 0.f;
        if (tid < 64 && tid >= off) v = gc[tid - off];
        __syncthreads();
        if (tid < 64 && tid >= off) gc[tid] += v;
        __syncthreads();
    }
    if (tid < 64) {
        egc[tid] = __expf(gc[tid]);
        egr[tid] = __expf(gc[63] - gc[tid]);
    }
    __syncthreads();

    for (int r = warp; r < 64; r += 8) {
        int t = t0 + r;
        const float* base = conv + ((size_t)(b * TT + t)) * 3072 + h * 128;
        float qv[4], kv[4];
        float ssq = 0.f, ssk = 0.f;
#pragma unroll
        for (int u = 0; u < 4; u++) {
            qv[u] = base[lane + u * 32];
            kv[u] = base[1024 + lane + u * 32];
            ssq += qv[u] * qv[u];
            ssk += kv[u] * kv[u];
        }
#pragma unroll
        for (int off = 16; off; off >>= 1) {
            ssq += __shfl_xor_sync(0xffffffffu, ssq, off);
            ssk += __shfl_xor_sync(0xffffffffu, ssk, off);
        }
        float rq = rsqrtf(ssq + 1e-6f) * 0.08838834764831845f;
        float rk = rsqrtf(ssk + 1e-6f);
        float bbv = bts[r], egv = egc[r];
#pragma unroll
        for (int u = 0; u < 4; u++) {
            int d = lane + u * 32;
            qst[d * KST + r] = qv[u] * rq;
            float kn = kv[u] * rk;
            kst[d * KST + r] = kn;
            ws[r * 256 + d]       = base[2048 + d] * bbv;
            ws[r * 256 + 128 + d] = kn * bbv * egv;
        }
    }
    __syncthreads();

    int ti = tid >> 4, tj = tid & 15;

    // A[i][j] = beta_i (k_i . k_j) exp(gc_i - gc_j), j < i; else 0
    {
        float acc[4][4];
#pragma unroll
        for (int r = 0; r < 4; r++)
#pragma unroll
            for (int s = 0; s < 4; s++) acc[r][s] = 0.f;
        const float* ka = kst + ti * 4;
        const float* kb = kst + tj * 4;
#pragma unroll 4
        for (int d = 0; d < 128; d++) {
            float4 a = *(const float4*)(ka + d * KST);
            float4 bq = *(const float4*)(kb + d * KST);
            float ra[4] = {a.x, a.y, a.z, a.w};
            float rb[4] = {bq.x, bq.y, bq.z, bq.w};
#pragma unroll
            for (int r = 0; r < 4; r++)
#pragma unroll
                for (int s = 0; s < 4; s++) acc[r][s] += ra[r] * rb[s];
        }
#pragma unroll
        for (int r = 0; r < 4; r++) {
            int i = ti * 4 + r;
#pragma unroll
            for (int s = 0; s < 4; s++) {
                int j = tj * 4 + s;
                As[i * ASD + j] = (j < i) ? acc[r][s] * bts[i] * __expf(gc[i] - gc[j]) : 0.f;
            }
        }
    }
    __syncthreads();

    // blocked forward substitution: ws <- (I+A)^{-1} ws
    for (int blk = 0; blk < 4; blk++) {
        if (blk) {
            int tr = tid >> 7, tc = tid & 127;
            float acc[8][2];
#pragma unroll
            for (int r = 0; r < 8; r++) { acc[r][0] = 0.f; acc[r][1] = 0.f; }
            for (int j = 0; j < blk * 16; j++) {
                float2 wv = *(const float2*)(ws + j * 256 + tc * 2);
#pragma unroll
                for (int r = 0; r < 8; r++) {
                    float a = As[(blk * 16 + tr * 8 + r) * ASD + j];
                    acc[r][0] += a * wv.x;
                    acc[r][1] += a * wv.y;
                }
            }
#pragma unroll
            for (int r = 0; r < 8; r++) {
                float* w = ws + (blk * 16 + tr * 8 + r) * 256 + tc * 2;
                w[0] -= acc[r][0];
                w[1] -= acc[r][1];
            }
            __syncthreads();
        }
        {
            int c = tid;
            int i0 = blk * 16;
            for (int i = i0 + 1; i < i0 + 16; i++) {
                float acc = 0.f;
                for (int j = i0; j < i; j++) acc += As[i * ASD + j] * ws[j * 256 + c];
                ws[i * 256 + c] -= acc;
            }
        }
        __syncthreads();
    }

    // attn[i][j] = (q_i . k_j) exp(gc_i - gc_j), j <= i; else 0 (overwrite As)
    {
        float acc[4][4];
#pragma unroll
        for (int r = 0; r < 4; r++)
#pragma unroll
            for (int s = 0; s < 4; s++) acc[r][s] = 0.f;
        const float* qa = qst + ti * 4;
        const float* kb = kst + tj * 4;
#pragma unroll 4
        for (int d = 0; d < 128; d++) {
            float4 a = *(const float4*)(qa + d * KST);
            float4 bq = *(const float4*)(kb + d * KST);
            float ra[4] = {a.x, a.y, a.z, a.w};
            float rb[4] = {bq.x, bq.y, bq.z, bq.w};
#pragma unroll
            for (int r = 0; r < 4; r++)
#pragma unroll
                for (int s = 0; s < 4; s++) acc[r][s] += ra[r] * rb[s];
        }
#pragma unroll
        for (int r = 0; r < 4; r++) {
            int i = ti * 4 + r;
#pragma unroll
            for (int s = 0; s < 4; s++) {
                int j = tj * 4 + s;
                As[i * ASD + j] = (j <= i) ? acc[r][s] * __expf(gc[i] - gc[j]) : 0.f;
            }
        }
    }
    __syncthreads();

    // [L | attn@k_cum] = attn @ ws ;  P = q*e^gc - attn@k_cum
    {
        int tr = warp;
        int tc = lane;
        float acc[8][8];
#pragma unroll
        for (int r = 0; r < 8; r++)
#pragma unroll
            for (int u = 0; u < 8; u++) acc[r][u] = 0.f;
        int jmax = tr * 8 + 8;
        for (int j = 0; j < jmax; j++) {
            float av[8];
#pragma unroll
            for (int r = 0; r < 8; r++) av[r] = As[(tr * 8 + r) * ASD + j];
            float4 w0 = *(const float4*)(ws + j * 256 + tc * 8);
            float4 w1 = *(const float4*)(ws + j * 256 + tc * 8 + 4);
            float rb[8] = {w0.x, w0.y, w0.z, w0.w, w1.x, w1.y, w1.z, w1.w};
#pragma unroll
            for (int r = 0; r < 8; r++)
#pragma unroll
                for (int u = 0; u < 8; u++) acc[r][u] += av[r] * rb[u];
        }
        if (tc < 16) {
#pragma unroll
            for (int r = 0; r < 8; r++) {
                int i = tr * 8 + r;
                float* dst = Lout + ((size_t)cid * 64 + i) * 128 + tc * 8;
                *(float4*)(dst)     = make_float4(acc[r][0], acc[r][1], acc[r][2], acc[r][3]);
                *(float4*)(dst + 4) = make_float4(acc[r][4], acc[r][5], acc[r][6], acc[r][7]);
            }
        } else {
            int c0 = tc * 8 - 128;
#pragma unroll
            for (int r = 0; r < 8; r++) {
                int i = tr * 8 + r;
                float eg = egc[i];
                float v[8];
#pragma unroll
                for (int u = 0; u < 8; u++)
                    v[u] = qst[(c0 + u) * KST + i] * eg - acc[r][u];
                float* dst = Pout + ((size_t)cid * 64 + i) * 128 + c0;
                *(float4*)(dst)     = make_float4(v[0], v[1], v[2], v[3]);
                *(float4*)(dst + 4) = make_float4(v[4], v[5], v[6], v[7]);
            }
        }
    }

    // M = keff^T @ k_cum ; U = keff^T @ v_new ; keff[i][a] = k[i][a]*egr[i]
    {
        int ta = tid >> 4;
        int te = tid & 15;
#pragma unroll
        for (int pass = 0; pass < 2; pass++) {
            float acc[8][8];
#pragma unroll
            for (int r = 0; r < 8; r++)
#pragma unroll
                for (int u = 0; u < 8; u++) acc[r][u] = 0.f;
            for (int i = 0; i < 64; i++) {
                float er = egr[i];
                float av[8];
#pragma unroll
                for (int r = 0; r < 8; r++) av[r] = kst[(ta * 8 + r) * KST + i] * er;
                float4 w0 = *(const float4*)(ws + i * 256 + pass * 128 + te * 8);
                float4 w1 = *(const float4*)(ws + i * 256 + pass * 128 + te * 8 + 4);
                float rb[8] = {w0.x, w0.y, w0.z, w0.w, w1.x, w1.y, w1.z, w1.w};
#pragma unroll
                for (int r = 0; r < 8; r++)
#pragma unroll
                    for (int u = 0; u < 8; u++) acc[r][u] += av[r] * rb[u];
            }
            float* dstb = pass ? Mout : Uout;
#pragma unroll
            for (int r = 0; r < 8; r++) {
                float* dst = dstb + ((size_t)cid * 128 + ta * 8 + r) * 128 + te * 8;
                *(float4*)(dst)     = make_float4(acc[r][0], acc[r][1], acc[r][2], acc[r][3]);
                *(float4*)(dst + 4) = make_float4(acc[r][4], acc[r][5], acc[r][6], acc[r][7]);
            }
        }
    }
    if (tid == 0) eglout[cid] = __expf(gc[63]);
}

// ---------------- Phase B: sequential scan over chunks, DV split ----------------
#define MSD 132
#define PB_SMEM ((128*MSD + 64*MSD + 128*16) * 4)

__global__ __launch_bounds__(256) void phaseB_kernel(const float* __restrict__ Pm,
        const float* __restrict__ Lm, const float* __restrict__ Mm,
        const float* __restrict__ Um, const float* __restrict__ eglv,
        float* __restrict__ core)
{
    extern __shared__ float sm[];
    float* Ms = sm;                  // 128 x MSD
    float* Ps = Ms + 128 * MSD;      // 64 x MSD
    float* Ss = Ps + 64 * MSD;       // 128 x 16

    int bh = blockIdx.x, gg = blockIdx.y;
    int b = bh >> 3, h = bh & 7;
    int tid = threadIdx.x;
    int c4g = tid & 3;
    int a0 = tid >> 2;
    int c0 = gg * 16;

    for (int i = tid; i < 128 * 16; i += 256) Ss[i] = 0.f;
    __syncthreads();

    for (int n = 0; n < 64; n++) {
        size_t cid = (size_t)bh * 64 + n;
        const float4* Mg = (const float4*)(Mm + cid * 16384);
        for (int i = tid; i < 4096; i += 256) {
            int row = i >> 5, col = (i & 31) * 4;
            *(float4*)(Ms + row * MSD + col) = Mg[i];
        }
        const float4* Pg = (const float4*)(Pm + cid * 8192);
        for (int i = tid; i < 2048; i += 256) {
            int row = i >> 5, col = (i & 31) * 4;
            *(float4*)(Ps + row * MSD + col) = Pg[i];
        }
        __syncthreads();

        // out[i][c] = L[i][c] + sum_a P[i][a] * S[a][c]   (i = a0)
        {
            float4 acc = *(const float4*)(Lm + cid * 8192 + a0 * 128 + c0 + c4g * 4);
            for (int a = 0; a < 128; a++) {
                float p = Ps[a0 * MSD + a];
                float4 s = *(const float4*)(Ss + a * 16 + c4g * 4);
                acc.x += p * s.x; acc.y += p * s.y; acc.z += p * s.z; acc.w += p * s.w;
            }
            int t = n * 64 + a0;
            *(float4*)(core + (((size_t)(b * TT + t)) * 8 + h) * 128 + c0 + c4g * 4) = acc;
        }

        // S' = egl*S + U - M@S  (rows a0 and a0+64)
        float eg = eglv[cid];
        float4 s0 = *(const float4*)(Ss + a0 * 16 + c4g * 4);
        float4 s1 = *(const float4*)(Ss + (a0 + 64) * 16 + c4g * 4);
        float4 ns0 = *(const float4*)(Um + cid * 16384 + (size_t)a0 * 128 + c0 + c4g * 4);
        float4 ns1 = *(const float4*)(Um + cid * 16384 + (size_t)(a0 + 64) * 128 + c0 + c4g * 4);
        ns0.x += eg * s0.x; ns0.y += eg * s0.y; ns0.z += eg * s0.z; ns0.w += eg * s0.w;
        ns1.x += eg * s1.x; ns1.y += eg * s1.y; ns1.z += eg * s1.z; ns1.w += eg * s1.w;
        for (int ap = 0; ap < 128; ap++) {
            float4 s = *(const float4*)(Ss + ap * 16 + c4g * 4);
            float m0 = Ms[a0 * MSD + ap];
            float m1 = Ms[(a0 + 64) * MSD + ap];
            ns0.x -= m0 * s.x; ns0.y -= m0 * s.y; ns0.z -= m0 * s.z; ns0.w -= m0 * s.w;
            ns1.x -= m1 * s.x; ns1.y -= m1 * s.y; ns1.z -= m1 * s.z; ns1.w -= m1 * s.w;
        }
        __syncthreads();
        *(float4*)(Ss + a0 * 16 + c4g * 4) = ns0;
        *(float4*)(Ss + (a0 + 64) * 16 + c4g * 4) = ns1;
        __syncthreads();
    }
}

// ---------------- gated RMSNorm * silu(z) -> bf16 hi/lo --------------------------
__global__ __launch_bounds__(128) void norm_kernel(const float* __restrict__ core,
        const float* __restrict__ qkvz, const float* __restrict__ nw,
        __nv_bfloat16* __restrict__ hh, __nv_bfloat16* __restrict__ hl)
{
    int bth = blockIdx.x;
    int d = threadIdx.x;
    float cv = core[(size_t)bth * 128 + d];
    float ss = cv * cv;
#pragma unroll
    for (int o = 16; o; o >>= 1) ss += __shfl_xor_sync(0xffffffffu, ss, o);
    __shared__ float red[4];
    if ((d & 31) == 0) red[d >> 5] = ss;
    __syncthreads();
    float tot = red[0] + red[1] + red[2] + red[3];
    float r = rsqrtf(tot * (1.f / 128.f) + 1e-6f);
    float zz = qkvz[(size_t)bth * 512 + 384 + d];
    float sz = zz / (1.f + __expf(-zz));
    float hv = nw[d] * cv * r * sz;
    __nv_bfloat16 h = __float2bfloat16_rn(hv);
    size_t o = (size_t)bth * 128 + d;
    hh[o] = h;
    hl[o] = __float2bfloat16_rn(hv - __bfloat162float(h));
}

// ---------------- launch ---------------------------------------------------------
extern "C" void kernel_launch(void* const* d_in, const int* in_sizes, int n_in,
                              void* d_out, int out_size)
{
    (void)in_sizes; (void)n_in; (void)out_size;
    const float* x    = (const float*)d_in[0];
    const float* Wq   = (const float*)d_in[1];
    const float* Wba  = (const float*)d_in[2];
    const float* cw   = (const float*)d_in[3];
    const float* dtb  = (const float*)d_in[4];
    const float* Alog = (const float*)d_in[5];
    const float* nw   = (const float*)d_in[6];
    const float* Wout = (const float*)d_in[7];
    float* out = (float*)d_out;

    float *qkvz, *convb, *gb, *betab, *Pb, *Lb, *Mb, *Ub, *eglb, *coreb;
    __nv_bfloat16 *xh, *xl, *w1h, *w1l, *w2h, *w2l, *hh, *hl;
    cudaGetSymbolAddress((void**)&qkvz,  g_qkvz);
    cudaGetSymbolAddress((void**)&convb, g_conv);
    cudaGetSymbolAddress((void**)&gb,    g_g);
    cudaGetSymbolAddress((void**)&betab, g_beta);
    cudaGetSymbolAddress((void**)&Pb,    g_P);
    cudaGetSymbolAddress((void**)&Lb,    g_L);
    cudaGetSymbolAddress((void**)&Mb,    g_M);
    cudaGetSymbolAddress((void**)&Ub,    g_U);
    cudaGetSymbolAddress((void**)&eglb,  g_egl);
    cudaGetSymbolAddress((void**)&coreb, g_core);
    cudaGetSymbolAddress((void**)&xh,  g_xh);
    cudaGetSymbolAddress((void**)&xl,  g_xl);
    cudaGetSymbolAddress((void**)&w1h, g_w1h);
    cudaGetSymbolAddress((void**)&w1l, g_w1l);
    cudaGetSymbolAddress((void**)&w2h, g_w2h);
    cudaGetSymbolAddress((void**)&w2l, g_w2l);
    cudaGetSymbolAddress((void**)&hh,  g_hh);
    cudaGetSymbolAddress((void**)&hl,  g_hl);

    cudaFuncSetAttribute(phaseA_kernel, cudaFuncAttributeMaxDynamicSharedMemorySize, PA_SMEM);
    cudaFuncSetAttribute(phaseB_kernel, cudaFuncAttributeMaxDynamicSharedMemorySize, PB_SMEM);
    cudaFuncSetAttribute(bf16gemm256, cudaFuncAttributeMaxDynamicSharedMemorySize, GEMM_SMEM);

    // 0. operand conversion (bandwidth-bound)
    cvt_split_kernel<<<(BB * TT * CC / 4) / 256, 256>>>(x, xh, xl);
    transpose_split_kernel<<<dim3(4096 / 32, CC / 32), 256>>>(Wq, w1h, w1l, CC, 4096);
    transpose_split_kernel<<<dim3(1024 / 32, CC / 32), 256>>>(Wout, w2h, w2l, CC, 1024);

    // 1. qkvz = x @ W_qkvz  (128x256 tiles)
    dim3 g1(4096 / 256, 8192 / 128);
    bf16gemm256<<<g1, 512, GEMM_SMEM>>>(BB * TT, 4096, CC, xh, xl, w1h, w1l, qkvz);
    // 2. ba = x @ W_ba fused with g/beta
    ba_gbeta_kernel<<<BB * TT, 256>>>(x, Wba, dtb, Alog, gb, betab);
    // 3. conv + silu
    conv_silu_kernel<<<(BB * TT * 3072) / 256, 256>>>(qkvz, cw, convb);
    // 4. phase A
    phaseA_kernel<<<NCID, 256, PA_SMEM>>>(convb, gb, betab, Pb, Lb, Mb, Ub, eglb);
    // 5. phase B
    dim3 gB(16, 8);
    phaseB_kernel<<<gB, 256, PB_SMEM>>>(Pb, Lb, Mb, Ub, eglb, coreb);
    // 6. gated RMSNorm * silu(z) -> bf16 hi/lo
    norm_kernel<<<BB * TT * NH, 128>>>(coreb, qkvz, nw, hh, hl);
    // 7. final projection (128x256 tiles)
    dim3 g2(1024 / 256, 8192 / 128);
    bf16gemm256<<<g2, 512, GEMM_SMEM>>>(BB * TT, 1024, CC, hh, hl, w2h, w2l, out);
}

// round 13
// speedup vs baseline: 1.0079x; 1.0079x over previous
#include <cuda_runtime.h>
#include <cuda_bf16.h>
#include <math.h>

// Problem constants
#define BB 2
#define TT 4096
#define CC 1024
#define NH 8
#define DD 128
#define CHK 64
#define NCHUNK 64            // T / CHK
#define NCID 1024            // BB*NH*NCHUNK

// ---------------- scratch (device globals; no allocation allowed) ----------------
__device__ float g_qkvz[(size_t)BB*TT*4096];     // x @ W_qkvz      (B,T,8,512)
__device__ float g_g[(size_t)BB*TT*NH];
__device__ float g_beta[(size_t)BB*TT*NH];
__device__ float g_P[(size_t)NCID*64*128];       // qeff - attn@k_cum
__device__ float g_L[(size_t)NCID*64*128];       // attn@v_new
__device__ float g_M[(size_t)NCID*128*128];      // keff^T @ k_cum
__device__ float g_U[(size_t)NCID*128*128];      // keff^T @ v_new
__device__ float g_egl[NCID];                    // exp(g_last)
__device__ float g_core[(size_t)BB*TT*NH*DD];    // delta-rule output

// bf16 hi/lo split operands for the two big GEMMs
__device__ __nv_bfloat16 g_xh[(size_t)BB*TT*CC],  g_xl[(size_t)BB*TT*CC];
__device__ __nv_bfloat16 g_w1h[(size_t)4096*CC],  g_w1l[(size_t)4096*CC];   // W_qkvz^T [N][K]
__device__ __nv_bfloat16 g_w2h[(size_t)1024*CC],  g_w2l[(size_t)1024*CC];   // W_out^T  [N][K]
__device__ __nv_bfloat16 g_hh[(size_t)BB*TT*1024], g_hl[(size_t)BB*TT*1024];

// ---------------- split/transpose conversion kernels ----------------------------
__global__ __launch_bounds__(256) void cvt_split_kernel(const float* __restrict__ in,
        __nv_bfloat16* __restrict__ oh, __nv_bfloat16* __restrict__ ol)
{
    int i = blockIdx.x * 256 + threadIdx.x;            // indexes float4
    float4 v = ((const float4*)in)[i];
    float f[4] = {v.x, v.y, v.z, v.w};
    __nv_bfloat16 h[4], l[4];
#pragma unroll
    for (int e = 0; e < 4; e++) {
        h[e] = __float2bfloat16_rn(f[e]);
        l[e] = __float2bfloat16_rn(f[e] - __bfloat162float(h[e]));
    }
    __nv_bfloat162 h0; h0.x = h[0]; h0.y = h[1];
    __nv_bfloat162 h1; h1.x = h[2]; h1.y = h[3];
    __nv_bfloat162 l0; l0.x = l[0]; l0.y = l[1];
    __nv_bfloat162 l1; l1.x = l[2]; l1.y = l[3];
    ((__nv_bfloat162*)oh)[i * 2]     = h0;
    ((__nv_bfloat162*)oh)[i * 2 + 1] = h1;
    ((__nv_bfloat162*)ol)[i * 2]     = l0;
    ((__nv_bfloat162*)ol)[i * 2 + 1] = l1;
}

// W [K][N] f32 -> Wt [N][K] bf16 hi/lo
__global__ __launch_bounds__(256) void transpose_split_kernel(const float* __restrict__ W,
        __nv_bfloat16* __restrict__ oh, __nv_bfloat16* __restrict__ ol, int K, int N)
{
    __shared__ float tile[32][33];
    int n0 = blockIdx.x * 32, k0 = blockIdx.y * 32;
    int tx = threadIdx.x & 31, ty0 = threadIdx.x >> 5;
#pragma unroll
    for (int ty = ty0; ty < 32; ty += 8)
        tile[ty][tx] = W[(size_t)(k0 + ty) * N + n0 + tx];
    __syncthreads();
#pragma unroll
    for (int ty = ty0; ty < 32; ty += 8) {
        float v = tile[tx][ty];
        __nv_bfloat16 h = __float2bfloat16_rn(v);
        size_t o = (size_t)(n0 + ty) * K + k0 + tx;
        oh[o] = h;
        ol[o] = __float2bfloat16_rn(v - __bfloat162float(h));
    }
}

// ---------------- asm helpers ----------------------------------------------------
#define MMA_BF16(C, Ar, Br)                                                    \
    asm volatile("mma.sync.aligned.m16n8k16.row.col.f32.bf16.bf16.f32 "        \
        "{%0,%1,%2,%3}, {%4,%5,%6,%7}, {%8,%9}, {%0,%1,%2,%3};"                \
        : "+f"((C)[0]), "+f"((C)[1]), "+f"((C)[2]), "+f"((C)[3])               \
        : "r"((Ar)[0]), "r"((Ar)[1]), "r"((Ar)[2]), "r"((Ar)[3]),              \
          "r"((Br)[0]), "r"((Br)[1]))

#define LDSM4(R0, R1, R2, R3, ADDR)                                            \
    asm volatile("ldmatrix.sync.aligned.m8n8.x4.shared.b16 {%0,%1,%2,%3}, [%4];" \
        : "=r"(R0), "=r"(R1), "=r"(R2), "=r"(R3) : "r"(ADDR))

#define CP_ASYNC16(DST, SRC)                                                   \
    asm volatile("cp.async.cg.shared.global [%0], [%1], 16;" :: "r"(DST), "l"(SRC))
#define CP_COMMIT() asm volatile("cp.async.commit_group;" ::: "memory")
#define CP_WAIT0()  asm volatile("cp.async.wait_group 0;" ::: "memory")
#define CP_WAIT1()  asm volatile("cp.async.wait_group 1;" ::: "memory")

// ---------------- 3xBF16-split GEMM: C = A(MxK)@B^T(NxK), pre-split bf16 --------
// R11-proven: ldmatrix + cp.async double-buffer, 128x128 tile, 2 blocks/SM.
#define GKS 40                                   // bf16 k-stride (80B rows, conflict-free)
#define STG_ELEM (4 * 128 * GKS)                 // elements per stage (4 arrays)
#define STG_BYTES (STG_ELEM * 2)                 // 40960 bytes
#define ARR_BYTES (128 * GKS * 2)                // 10240 bytes per array
#define GEMM_SMEM (2 * STG_BYTES)                // 81920 bytes

__global__ __launch_bounds__(256, 2) void bf16gemm128(int M, int N, int K,
        const __nv_bfloat16* __restrict__ Ah_, const __nv_bfloat16* __restrict__ Al_,
        const __nv_bfloat16* __restrict__ Bth_, const __nv_bfloat16* __restrict__ Btl_,
        float* __restrict__ Cm)
{
    extern __shared__ __nv_bfloat16 gsm[];
    unsigned smemBase = (unsigned)__cvta_generic_to_shared(gsm);

    int tid = threadIdx.x;
    int brow = blockIdx.y * 128, bcol = blockIdx.x * 128;
    int warp = tid >> 5, lane = tid & 31;
    int wm = (warp & 1) * 64, wn = (warp >> 1) * 32;
    int lr = lane >> 2, lc2 = (lane & 3) * 2;

    int r0s = tid >> 2, kg0 = (tid & 3) * 8;
    int r1s = (tid + 256) >> 2, kg1 = (tid & 3) * 8;
    unsigned d0 = (unsigned)(r0s * GKS + kg0) * 2;
    unsigned d1 = (unsigned)(r1s * GKS + kg1) * 2;
    const __nv_bfloat16* srcA0h = Ah_  + (size_t)(brow + r0s) * K + kg0;
    const __nv_bfloat16* srcA1h = Ah_  + (size_t)(brow + r1s) * K + kg1;
    const __nv_bfloat16* srcA0l = Al_  + (size_t)(brow + r0s) * K + kg0;
    const __nv_bfloat16* srcA1l = Al_  + (size_t)(brow + r1s) * K + kg1;
    const __nv_bfloat16* srcB0h = Bth_ + (size_t)(bcol + r0s) * K + kg0;
    const __nv_bfloat16* srcB1h = Bth_ + (size_t)(bcol + r1s) * K + kg1;
    const __nv_bfloat16* srcB0l = Btl_ + (size_t)(bcol + r0s) * K + kg0;
    const __nv_bfloat16* srcB1l = Btl_ + (size_t)(bcol + r1s) * K + kg1;

    unsigned aoff = (unsigned)(((wm + (lane & 15)) * GKS) + ((lane >> 4) * 8)) * 2;
    unsigned boff = (unsigned)(((wn + (lane & 7) + (((lane >> 4) & 1) * 8)) * GKS)
                               + (((lane >> 3) & 1) * 8)) * 2;

    float c[4][4][4];
#pragma unroll
    for (int mt = 0; mt < 4; mt++)
#pragma unroll
        for (int nt = 0; nt < 4; nt++)
#pragma unroll
            for (int e = 0; e < 4; e++) c[mt][nt][e] = 0.f;

    {
        unsigned sb = smemBase;
        CP_ASYNC16(sb + d0,                 srcA0h);
        CP_ASYNC16(sb + d1,                 srcA1h);
        CP_ASYNC16(sb + ARR_BYTES + d0,     srcA0l);
        CP_ASYNC16(sb + ARR_BYTES + d1,     srcA1l);
        CP_ASYNC16(sb + 2 * ARR_BYTES + d0, srcB0h);
        CP_ASYNC16(sb + 2 * ARR_BYTES + d1, srcB1h);
        CP_ASYNC16(sb + 3 * ARR_BYTES + d0, srcB0l);
        CP_ASYNC16(sb + 3 * ARR_BYTES + d1, srcB1l);
        CP_COMMIT();
    }

    int buf = 0;
    for (int k0 = 0; k0 < K; k0 += 32) {
        bool hasNext = (k0 + 32) < K;
        if (hasNext) {
            unsigned sb = smemBase + (buf ^ 1) * STG_BYTES;
            int kn = k0 + 32;
            CP_ASYNC16(sb + d0,                 srcA0h + kn);
            CP_ASYNC16(sb + d1,                 srcA1h + kn);
            CP_ASYNC16(sb + ARR_BYTES + d0,     srcA0l + kn);
            CP_ASYNC16(sb + ARR_BYTES + d1,     srcA1l + kn);
            CP_ASYNC16(sb + 2 * ARR_BYTES + d0, srcB0h + kn);
            CP_ASYNC16(sb + 2 * ARR_BYTES + d1, srcB1h + kn);
            CP_ASYNC16(sb + 3 * ARR_BYTES + d0, srcB0l + kn);
            CP_ASYNC16(sb + 3 * ARR_BYTES + d1, srcB1l + kn);
            CP_COMMIT();
            CP_WAIT1();
        } else {
            CP_WAIT0();
        }
        __syncthreads();

        unsigned aBh = smemBase + buf * STG_BYTES;
        unsigned aBl = aBh + ARR_BYTES;
        unsigned bBh = aBh + 2 * ARR_BYTES;
        unsigned bBl = aBh + 3 * ARR_BYTES;

#pragma unroll
        for (int kk = 0; kk < 32; kk += 16) {
            unsigned ah[4][4], al[4][4], bh[2][4], bl[2][4];
#pragma unroll
            for (int mt = 0; mt < 4; mt++) {
                unsigned off = aoff + (unsigned)(mt * 16 * GKS + kk) * 2;
                LDSM4(ah[mt][0], ah[mt][1], ah[mt][2], ah[mt][3], aBh + off);
                LDSM4(al[mt][0], al[mt][1], al[mt][2], al[mt][3], aBl + off);
            }
#pragma unroll
            for (int p = 0; p < 2; p++) {
                unsigned off = boff + (unsigned)(p * 16 * GKS + kk) * 2;
                LDSM4(bh[p][0], bh[p][1], bh[p][2], bh[p][3], bBh + off);
                LDSM4(bl[p][0], bl[p][1], bl[p][2], bl[p][3], bBl + off);
            }
#pragma unroll
            for (int mt = 0; mt < 4; mt++)
#pragma unroll
                for (int nt = 0; nt < 4; nt++)
                    MMA_BF16(c[mt][nt], ah[mt], (&bh[nt >> 1][(nt & 1) * 2]));
#pragma unroll
            for (int mt = 0; mt < 4; mt++)
#pragma unroll
                for (int nt = 0; nt < 4; nt++)
                    MMA_BF16(c[mt][nt], al[mt], (&bh[nt >> 1][(nt & 1) * 2]));
#pragma unroll
            for (int mt = 0; mt < 4; mt++)
#pragma unroll
                for (int nt = 0; nt < 4; nt++)
                    MMA_BF16(c[mt][nt], ah[mt], (&bl[nt >> 1][(nt & 1) * 2]));
        }
        __syncthreads();
        buf ^= 1;
    }

#pragma unroll
    for (int mt = 0; mt < 4; mt++) {
        int r0 = brow + wm + mt * 16 + lr;
#pragma unroll
        for (int nt = 0; nt < 4; nt++) {
            int cn = bcol + wn + nt * 8 + lc2;
            *(float2*)(Cm + (size_t)r0 * N + cn)       = make_float2(c[mt][nt][0], c[mt][nt][1]);
            *(float2*)(Cm + (size_t)(r0 + 8) * N + cn) = make_float2(c[mt][nt][2], c[mt][nt][3]);
        }
    }
}

// ---------------- fused ba = x @ W_ba -> g, beta ---------------------------------
__global__ __launch_bounds__(256) void ba_gbeta_kernel(const float* __restrict__ x,
        const float* __restrict__ Wba, const float* __restrict__ dtb,
        const float* __restrict__ Alog, float* __restrict__ g, float* __restrict__ beta)
{
    int bt = blockIdx.x;
    __shared__ float xs[1024];
    const float* xrow = x + (size_t)bt * 1024;
    for (int i = threadIdx.x; i < 256; i += 256)
        ((float4*)xs)[i] = ((const float4*)xrow)[i];
    __syncthreads();
    int o = threadIdx.x >> 4, p = threadIdx.x & 15;
    float acc = 0.f;
    for (int k = p; k < 1024; k += 16) acc += xs[k] * Wba[(size_t)k * 16 + o];
    acc += __shfl_down_sync(0xffffffffu, acc, 8);
    acc += __shfl_down_sync(0xffffffffu, acc, 4);
    acc += __shfl_down_sync(0xffffffffu, acc, 2);
    acc += __shfl_down_sync(0xffffffffu, acc, 1);
    if (p == 0) {
        int h = o >> 1;
        if ((o & 1) == 0) {
            beta[(size_t)bt * 8 + h] = 1.f / (1.f + expf(-acc));
        } else {
            float xx = acc + dtb[h];
            float sp = (xx > 20.f) ? xx : log1pf(expf(xx));
            g[(size_t)bt * 8 + h] = -expf(Alog[h]) * sp;
        }
    }
}

// ---------------- Phase A: fused conv+silu + per-chunk local operators ----------
#define KST 68
#define ASD 65
#define PA_SMEM ((128*KST*2 + 64*256 + 64*ASD + 256) * 4)

__global__ __launch_bounds__(256) void phaseA_kernel(const float* __restrict__ qkvz,
        const float* __restrict__ cw,
        const float* __restrict__ gbuf, const float* __restrict__ betabuf,
        float* __restrict__ Pout, float* __restrict__ Lout,
        float* __restrict__ Mout, float* __restrict__ Uout, float* __restrict__ eglout)
{
    extern __shared__ float sm[];
    float* kst = sm;
    float* qst = kst + 128 * KST;
    float* ws  = qst + 128 * KST;
    float* As  = ws + 64 * 256;          // 64 x ASD
    float* gc  = As + 64 * ASD;
    float* egc = gc + 64;
    float* egr = egc + 64;
    float* bts = egr + 64;

    int cid = blockIdx.x;
    int n = cid & 63, bh = cid >> 6, h = bh & 7, b = bh >> 3;
    int tid = threadIdx.x;
    int warp = tid >> 5, lane = tid & 31;
    int t0 = n * 64;

    if (tid < 64) {
        int t = t0 + tid;
        gc[tid]  = gbuf[((size_t)(b * TT + t)) * 8 + h];
        bts[tid] = betabuf[((size_t)(b * TT + t)) * 8 + h];
    }
    __syncthreads();
#pragma unroll
    for (int off = 1; off < 64; off <<= 1) {
        float v = 0.f;
        if (tid < 64 && tid >= off) v = gc[tid - off];
        __syncthreads();
        if (tid < 64 && tid >= off) gc[tid] += v;
        __syncthreads();
    }
    if (tid < 64) {
        egc[tid] = __expf(gc[tid]);
        egr[tid] = __expf(gc[63] - gc[tid]);
    }
    __syncthreads();

    // fused causal depthwise conv (K=4) + silu + l2norm staging
    for (int r = warp; r < 64; r += 8) {
        int t = t0 + r;
        size_t btrow = (size_t)b * TT + t;
        float qv[4], kv[4], vv[4];
        float ssq = 0.f, ssk = 0.f;
#pragma unroll
        for (int u = 0; u < 4; u++) {
            int d = lane + u * 32;
            float aq = 0.f, ak = 0.f, av = 0.f;
#pragma unroll
            for (int j = 0; j < 4; j++) {
                int tt = t - 3 + j;
                if (tt >= 0) {
                    const float* row = qkvz + ((btrow - 3 + j) * 8 + h) * 512;
                    aq += row[d]       * cw[(0 * 1024 + h * 128 + d) * 4 + j];
                    ak += row[128 + d] * cw[(1 * 1024 + h * 128 + d) * 4 + j];
                    av += row[256 + d] * cw[(2 * 1024 + h * 128 + d) * 4 + j];
                }
            }
            qv[u] = aq / (1.f + __expf(-aq));
            kv[u] = ak / (1.f + __expf(-ak));
            vv[u] = av / (1.f + __expf(-av));
            ssq += qv[u] * qv[u];
            ssk += kv[u] * kv[u];
        }
#pragma unroll
        for (int off = 16; off; off >>= 1) {
            ssq += __shfl_xor_sync(0xffffffffu, ssq, off);
            ssk += __shfl_xor_sync(0xffffffffu, ssk, off);
        }
        float rq = rsqrtf(ssq + 1e-6f) * 0.08838834764831845f;
        float rk = rsqrtf(ssk + 1e-6f);
        float bbv = bts[r], egv = egc[r];
#pragma unroll
        for (int u = 0; u < 4; u++) {
            int d = lane + u * 32;
            qst[d * KST + r] = qv[u] * rq;
            float kn = kv[u] * rk;
            kst[d * KST + r] = kn;
            ws[r * 256 + d]       = vv[u] * bbv;
            ws[r * 256 + 128 + d] = kn * bbv * egv;
        }
    }
    __syncthreads();

    int ti = tid >> 4, tj = tid & 15;

    // A[i][j] = beta_i (k_i . k_j) exp(gc_i - gc_j), j < i; else 0
    {
        float acc[4][4];
#pragma unroll
        for (int r = 0; r < 4; r++)
#pragma unroll
            for (int s = 0; s < 4; s++) acc[r][s] = 0.f;
        const float* ka = kst + ti * 4;
        const float* kb = kst + tj * 4;
#pragma unroll 4
        for (int d = 0; d < 128; d++) {
            float4 a = *(const float4*)(ka + d * KST);
            float4 bq = *(const float4*)(kb + d * KST);
            float ra[4] = {a.x, a.y, a.z, a.w};
            float rb[4] = {bq.x, bq.y, bq.z, bq.w};
#pragma unroll
            for (int r = 0; r < 4; r++)
#pragma unroll
                for (int s = 0; s < 4; s++) acc[r][s] += ra[r] * rb[s];
        }
#pragma unroll
        for (int r = 0; r < 4; r++) {
            int i = ti * 4 + r;
#pragma unroll
            for (int s = 0; s < 4; s++) {
                int j = tj * 4 + s;
                As[i * ASD + j] = (j < i) ? acc[r][s] * bts[i] * __expf(gc[i] - gc[j]) : 0.f;
            }
        }
    }
    __syncthreads();

    // blocked forward substitution: ws <- (I+A)^{-1} ws
    for (int blk = 0; blk < 4; blk++) {
        if (blk) {
            int tr = tid >> 7, tc = tid & 127;
            float acc[8][2];
#pragma unroll
            for (int r = 0; r < 8; r++) { acc[r][0] = 0.f; acc[r][1] = 0.f; }
            for (int j = 0; j < blk * 16; j++) {
                float2 wv = *(const float2*)(ws + j * 256 + tc * 2);
#pragma unroll
                for (int r = 0; r < 8; r++) {
                    float a = As[(blk * 16 + tr * 8 + r) * ASD + j];
                    acc[r][0] += a * wv.x;
                    acc[r][1] += a * wv.y;
                }
            }
#pragma unroll
            for (int r = 0; r < 8; r++) {
                float* w = ws + (blk * 16 + tr * 8 + r) * 256 + tc * 2;
                w[0] -= acc[r][0];
                w[1] -= acc[r][1];
            }
            __syncthreads();
        }
        {
            int c = tid;
            int i0 = blk * 16;
            for (int i = i0 + 1; i < i0 + 16; i++) {
                float acc = 0.f;
                for (int j = i0; j < i; j++) acc += As[i * ASD + j] * ws[j * 256 + c];
                ws[i * 256 + c] -= acc;
            }
        }
        __syncthreads();
    }

    // attn[i][j] = (q_i . k_j) exp(gc_i - gc_j), j <= i; else 0 (overwrite As)
    {
        float acc[4][4];
#pragma unroll
        for (int r = 0; r < 4; r++)
#pragma unroll
            for (int s = 0; s < 4; s++) acc[r][s] = 0.f;
        const float* qa = qst + ti * 4;
        const float* kb = kst + tj * 4;
#pragma unroll 4
        for (int d = 0; d < 128; d++) {
            float4 a = *(const float4*)(qa + d * KST);
            float4 bq = *(const float4*)(kb + d * KST);
            float ra[4] = {a.x, a.y, a.z, a.w};
            float rb[4] = {bq.x, bq.y, bq.z, bq.w};
#pragma unroll
            for (int r = 0; r < 4; r++)
#pragma unroll
                for (int s = 0; s < 4; s++) acc[r][s] += ra[r] * rb[s];
        }
#pragma unroll
        for (int r = 0; r < 4; r++) {
            int i = ti * 4 + r;
#pragma unroll
            for (int s = 0; s < 4; s++) {
                int j = tj * 4 + s;
                As[i * ASD + j] = (j <= i) ? acc[r][s] * __expf(gc[i] - gc[j]) : 0.f;
            }
        }
    }
    __syncthreads();

    // [L | attn@k_cum] = attn @ ws ;  P = q*e^gc - attn@k_cum
    {
        int tr = warp;
        int tc = lane;
        float acc[8][8];
#pragma unroll
        for (int r = 0; r < 8; r++)
#pragma unroll
            for (int u = 0; u < 8; u++) acc[r][u] = 0.f;
        int jmax = tr * 8 + 8;
        for (int j = 0; j < jmax; j++) {
            float av[8];
#pragma unroll
            for (int r = 0; r < 8; r++) av[r] = As[(tr * 8 + r) * ASD + j];
            float4 w0 = *(const float4*)(ws + j * 256 + tc * 8);
            float4 w1 = *(const float4*)(ws + j * 256 + tc * 8 + 4);
            float rb[8] = {w0.x, w0.y, w0.z, w0.w, w1.x, w1.y, w1.z, w1.w};
#pragma unroll
            for (int r = 0; r < 8; r++)
#pragma unroll
                for (int u = 0; u < 8; u++) acc[r][u] += av[r] * rb[u];
        }
        if (tc < 16) {
#pragma unroll
            for (int r = 0; r < 8; r++) {
                int i = tr * 8 + r;
                float* dst = Lout + ((size_t)cid * 64 + i) * 128 + tc * 8;
                *(float4*)(dst)     = make_float4(acc[r][0], acc[r][1], acc[r][2], acc[r][3]);
                *(float4*)(dst + 4) = make_float4(acc[r][4], acc[r][5], acc[r][6], acc[r][7]);
            }
        } else {
            int c0 = tc * 8 - 128;
#pragma unroll
            for (int r = 0; r < 8; r++) {
                int i = tr * 8 + r;
                float eg = egc[i];
                float v[8];
#pragma unroll
                for (int u = 0; u < 8; u++)
                    v[u] = qst[(c0 + u) * KST + i] * eg - acc[r][u];
                float* dst = Pout + ((size_t)cid * 64 + i) * 128 + c0;
                *(float4*)(dst)     = make_float4(v[0], v[1], v[2], v[3]);
                *(float4*)(dst + 4) = make_float4(v[4], v[5], v[6], v[7]);
            }
        }
    }

    // M = keff^T @ k_cum ; U = keff^T @ v_new ; keff[i][a] = k[i][a]*egr[i]
    {
        int ta = tid >> 4;
        int te = tid & 15;
#pragma unroll
        for (int pass = 0; pass < 2; pass++) {
            float acc[8][8];
#pragma unroll
            for (int r = 0; r < 8; r++)
#pragma unroll
                for (int u = 0; u < 8; u++) acc[r][u] = 0.f;
            for (int i = 0; i < 64; i++) {
                float er = egr[i];
                float av[8];
#pragma unroll
                for (int r = 0; r < 8; r++) av[r] = kst[(ta * 8 + r) * KST + i] * er;
                float4 w0 = *(const float4*)(ws + i * 256 + pass * 128 + te * 8);
                float4 w1 = *(const float4*)(ws + i * 256 + pass * 128 + te * 8 + 4);
                float rb[8] = {w0.x, w0.y, w0.z, w0.w, w1.x, w1.y, w1.z, w1.w};
#pragma unroll
                for (int r = 0; r < 8; r++)
#pragma unroll
                    for (int u = 0; u < 8; u++) acc[r][u] += av[r] * rb[u];
            }
            float* dstb = pass ? Mout : Uout;
#pragma unroll
            for (int r = 0; r < 8; r++) {
                float* dst = dstb + ((size_t)cid * 128 + ta * 8 + r) * 128 + te * 8;
                *(float4*)(dst)     = make_float4(acc[r][0], acc[r][1], acc[r][2], acc[r][3]);
                *(float4*)(dst + 4) = make_float4(acc[r][4], acc[r][5], acc[r][6], acc[r][7]);
            }
        }
    }
    if (tid == 0) eglout[cid] = __expf(gc[63]);
}

// ---------------- Phase B: sequential scan over chunks, DV split ----------------
#define MSD 132
#define PB_SMEM ((128*MSD + 64*MSD + 128*16) * 4)

__global__ __launch_bounds__(256) void phaseB_kernel(const float* __restrict__ Pm,
        const float* __restrict__ Lm, const float* __restrict__ Mm,
        const float* __restrict__ Um, const float* __restrict__ eglv,
        float* __restrict__ core)
{
    extern __shared__ float sm[];
    float* Ms = sm;                  // 128 x MSD
    float* Ps = Ms + 128 * MSD;      // 64 x MSD
    float* Ss = Ps + 64 * MSD;       // 128 x 16

    int bh = blockIdx.x, gg = blockIdx.y;
    int b = bh >> 3, h = bh & 7;
    int tid = threadIdx.x;
    int c4g = tid & 3;
    int a0 = tid >> 2;
    int c0 = gg * 16;

    for (int i = tid; i < 128 * 16; i += 256) Ss[i] = 0.f;
    __syncthreads();

    for (int n = 0; n < 64; n++) {
        size_t cid = (size_t)bh * 64 + n;
        const float4* Mg = (const float4*)(Mm + cid * 16384);
        for (int i = tid; i < 4096; i += 256) {
            int row = i >> 5, col = (i & 31) * 4;
            *(float4*)(Ms + row * MSD + col) = Mg[i];
        }
        const float4* Pg = (const float4*)(Pm + cid * 8192);
        for (int i = tid; i < 2048; i += 256) {
            int row = i >> 5, col = (i & 31) * 4;
            *(float4*)(Ps + row * MSD + col) = Pg[i];
        }
        __syncthreads();

        {
            float4 acc = *(const float4*)(Lm + cid * 8192 + a0 * 128 + c0 + c4g * 4);
            for (int a = 0; a < 128; a++) {
                float p = Ps[a0 * MSD + a];
                float4 s = *(const float4*)(Ss + a * 16 + c4g * 4);
                acc.x += p * s.x; acc.y += p * s.y; acc.z += p * s.z; acc.w += p * s.w;
            }
            int t = n * 64 + a0;
            *(float4*)(core + (((size_t)(b * TT + t)) * 8 + h) * 128 + c0 + c4g * 4) = acc;
        }

        float eg = eglv[cid];
        float4 s0 = *(const float4*)(Ss + a0 * 16 + c4g * 4);
        float4 s1 = *(const float4*)(Ss + (a0 + 64) * 16 + c4g * 4);
        float4 ns0 = *(const float4*)(Um + cid * 16384 + (size_t)a0 * 128 + c0 + c4g * 4);
        float4 ns1 = *(const float4*)(Um + cid * 16384 + (size_t)(a0 + 64) * 128 + c0 + c4g * 4);
        ns0.x += eg * s0.x; ns0.y += eg * s0.y; ns0.z += eg * s0.z; ns0.w += eg * s0.w;
        ns1.x += eg * s1.x; ns1.y += eg * s1.y; ns1.z += eg * s1.z; ns1.w += eg * s1.w;
        for (int ap = 0; ap < 128; ap++) {
            float4 s = *(const float4*)(Ss + ap * 16 + c4g * 4);
            float m0 = Ms[a0 * MSD + ap];
            float m1 = Ms[(a0 + 64) * MSD + ap];
            ns0.x -= m0 * s.x; ns0.y -= m0 * s.y; ns0.z -= m0 * s.z; ns0.w -= m0 * s.w;
            ns1.x -= m1 * s.x; ns1.y -= m1 * s.y; ns1.z -= m1 * s.z; ns1.w -= m1 * s.w;
        }
        __syncthreads();
        *(float4*)(Ss + a0 * 16 + c4g * 4) = ns0;
        *(float4*)(Ss + (a0 + 64) * 16 + c4g * 4) = ns1;
        __syncthreads();
    }
}

// ---------------- gated RMSNorm * silu(z) -> bf16 hi/lo --------------------------
__global__ __launch_bounds__(128) void norm_kernel(const float* __restrict__ core,
        const float* __restrict__ qkvz, const float* __restrict__ nw,
        __nv_bfloat16* __restrict__ hh, __nv_bfloat16* __restrict__ hl)
{
    int bth = blockIdx.x;
    int d = threadIdx.x;
    float cv = core[(size_t)bth * 128 + d];
    float ss = cv * cv;
#pragma unroll
    for (int o = 16; o; o >>= 1) ss += __shfl_xor_sync(0xffffffffu, ss, o);
    __shared__ float red[4];
    if ((d & 31) == 0) red[d >> 5] = ss;
    __syncthreads();
    float tot = red[0] + red[1] + red[2] + red[3];
    float r = rsqrtf(tot * (1.f / 128.f) + 1e-6f);
    float zz = qkvz[(size_t)bth * 512 + 384 + d];
    float sz = zz / (1.f + __expf(-zz));
    float hv = nw[d] * cv * r * sz;
    __nv_bfloat16 h = __float2bfloat16_rn(hv);
    size_t o = (size_t)bth * 128 + d;
    hh[o] = h;
    hl[o] = __float2bfloat16_rn(hv - __bfloat162float(h));
}

// ---------------- launch ---------------------------------------------------------
extern "C" void kernel_launch(void* const* d_in, const int* in_sizes, int n_in,
                              void* d_out, int out_size)
{
    (void)in_sizes; (void)n_in; (void)out_size;
    const float* x    = (const float*)d_in[0];
    const float* Wq   = (const float*)d_in[1];
    const float* Wba  = (const float*)d_in[2];
    const float* cw   = (const float*)d_in[3];
    const float* dtb  = (const float*)d_in[4];
    const float* Alog = (const float*)d_in[5];
    const float* nw   = (const float*)d_in[6];
    const float* Wout = (const float*)d_in[7];
    float* out = (float*)d_out;

    float *qkvz, *gb, *betab, *Pb, *Lb, *Mb, *Ub, *eglb, *coreb;
    __nv_bfloat16 *xh, *xl, *w1h, *w1l, *w2h, *w2l, *hh, *hl;
    cudaGetSymbolAddress((void**)&qkvz,  g_qkvz);
    cudaGetSymbolAddress((void**)&gb,    g_g);
    cudaGetSymbolAddress((void**)&betab, g_beta);
    cudaGetSymbolAddress((void**)&Pb,    g_P);
    cudaGetSymbolAddress((void**)&Lb,    g_L);
    cudaGetSymbolAddress((void**)&Mb,    g_M);
    cudaGetSymbolAddress((void**)&Ub,    g_U);
    cudaGetSymbolAddress((void**)&eglb,  g_egl);
    cudaGetSymbolAddress((void**)&coreb, g_core);
    cudaGetSymbolAddress((void**)&xh,  g_xh);
    cudaGetSymbolAddress((void**)&xl,  g_xl);
    cudaGetSymbolAddress((void**)&w1h, g_w1h);
    cudaGetSymbolAddress((void**)&w1l, g_w1l);
    cudaGetSymbolAddress((void**)&w2h, g_w2h);
    cudaGetSymbolAddress((void**)&w2l, g_w2l);
    cudaGetSymbolAddress((void**)&hh,  g_hh);
    cudaGetSymbolAddress((void**)&hl,  g_hl);

    cudaFuncSetAttribute(phaseA_kernel, cudaFuncAttributeMaxDynamicSharedMemorySize, PA_SMEM);
    cudaFuncSetAttribute(phaseB_kernel, cudaFuncAttributeMaxDynamicSharedMemorySize, PB_SMEM);
    cudaFuncSetAttribute(bf16gemm128, cudaFuncAttributeMaxDynamicSharedMemorySize, GEMM_SMEM);

    // 0. operand conversion (bandwidth-bound)
    cvt_split_kernel<<<(BB * TT * CC / 4) / 256, 256>>>(x, xh, xl);
    transpose_split_kernel<<<dim3(4096 / 32, CC / 32), 256>>>(Wq, w1h, w1l, CC, 4096);
    transpose_split_kernel<<<dim3(1024 / 32, CC / 32), 256>>>(Wout, w2h, w2l, CC, 1024);

    // 1. qkvz = x @ W_qkvz
    dim3 g1(4096 / 128, 8192 / 128);
    bf16gemm128<<<g1, 256, GEMM_SMEM>>>(BB * TT, 4096, CC, xh, xl, w1h, w1l, qkvz);
    // 2. ba = x @ W_ba fused with g/beta
    ba_gbeta_kernel<<<BB * TT, 256>>>(x, Wba, dtb, Alog, gb, betab);
    // 3. phase A (conv+silu fused inside)
    phaseA_kernel<<<NCID, 256, PA_SMEM>>>(qkvz, cw, gb, betab, Pb, Lb, Mb, Ub, eglb);
    // 4. phase B
    dim3 gB(16, 8);
    phaseB_kernel<<<gB, 256, PB_SMEM>>>(Pb, Lb, Mb, Ub, eglb, coreb);
    // 5. gated RMSNorm * silu(z) -> bf16 hi/lo
    norm_kernel<<<BB * TT * NH, 128>>>(coreb, qkvz, nw, hh, hl);
    // 6. final projection
    dim3 g2(1024 / 128, 8192 / 128);
    bf16gemm128<<<g2, 256, GEMM_SMEM>>>(BB * TT, 1024, CC, hh, hl, w2h, w2l, out);
}

// round 14
// speedup vs baseline: 1.1505x; 1.1415x over previous
#include <cuda_runtime.h>
#include <cuda_bf16.h>
#include <math.h>

// Problem constants
#define BB 2
#define TT 4096
#define CC 1024
#define NH 8
#define DD 128
#define CHK 64
#define NCHUNK 64            // T / CHK
#define NCID 1024            // BB*NH*NCHUNK

// ---------------- scratch (device globals; no allocation allowed) ----------------
__device__ float g_qkvz[(size_t)BB*TT*4096];     // x @ W_qkvz      (B,T,8,512)
__device__ float g_conv[(size_t)BB*TT*3072];     // conv+silu [q|k|v]
__device__ float g_g[(size_t)BB*TT*NH];
__device__ float g_beta[(size_t)BB*TT*NH];
__device__ float g_P[(size_t)NCID*64*128];       // qeff - attn@k_cum
__device__ float g_L[(size_t)NCID*64*128];       // attn@v_new
__device__ float g_vn[(size_t)NCID*64*128];      // v_new
__device__ float g_kc[(size_t)NCID*64*128];      // k_cum
__device__ float g_kf[(size_t)NCID*128*64];      // keff^T  [a][i]
__device__ float g_egl[NCID];                    // exp(g_last)
__device__ float g_core[(size_t)BB*TT*NH*DD];    // delta-rule output

// bf16 hi/lo split operands for the two big GEMMs
__device__ __nv_bfloat16 g_xh[(size_t)BB*TT*CC],  g_xl[(size_t)BB*TT*CC];
__device__ __nv_bfloat16 g_w1h[(size_t)4096*CC],  g_w1l[(size_t)4096*CC];   // W_qkvz^T [N][K]
__device__ __nv_bfloat16 g_w2h[(size_t)1024*CC],  g_w2l[(size_t)1024*CC];   // W_out^T  [N][K]
__device__ __nv_bfloat16 g_hh[(size_t)BB*TT*1024], g_hl[(size_t)BB*TT*1024];

// ---------------- split/transpose conversion kernels ----------------------------
__global__ __launch_bounds__(256) void cvt_split_kernel(const float* __restrict__ in,
        __nv_bfloat16* __restrict__ oh, __nv_bfloat16* __restrict__ ol)
{
    int i = blockIdx.x * 256 + threadIdx.x;            // indexes float4
    float4 v = ((const float4*)in)[i];
    float f[4] = {v.x, v.y, v.z, v.w};
    __nv_bfloat16 h[4], l[4];
#pragma unroll
    for (int e = 0; e < 4; e++) {
        h[e] = __float2bfloat16_rn(f[e]);
        l[e] = __float2bfloat16_rn(f[e] - __bfloat162float(h[e]));
    }
    __nv_bfloat162 h0; h0.x = h[0]; h0.y = h[1];
    __nv_bfloat162 h1; h1.x = h[2]; h1.y = h[3];
    __nv_bfloat162 l0; l0.x = l[0]; l0.y = l[1];
    __nv_bfloat162 l1; l1.x = l[2]; l1.y = l[3];
    ((__nv_bfloat162*)oh)[i * 2]     = h0;
    ((__nv_bfloat162*)oh)[i * 2 + 1] = h1;
    ((__nv_bfloat162*)ol)[i * 2]     = l0;
    ((__nv_bfloat162*)ol)[i * 2 + 1] = l1;
}

// W [K][N] f32 -> Wt [N][K] bf16 hi/lo
__global__ __launch_bounds__(256) void transpose_split_kernel(const float* __restrict__ W,
        __nv_bfloat16* __restrict__ oh, __nv_bfloat16* __restrict__ ol, int K, int N)
{
    __shared__ float tile[32][33];
    int n0 = blockIdx.x * 32, k0 = blockIdx.y * 32;
    int tx = threadIdx.x & 31, ty0 = threadIdx.x >> 5;
#pragma unroll
    for (int ty = ty0; ty < 32; ty += 8)
        tile[ty][tx] = W[(size_t)(k0 + ty) * N + n0 + tx];
    __syncthreads();
#pragma unroll
    for (int ty = ty0; ty < 32; ty += 8) {
        float v = tile[tx][ty];
        __nv_bfloat16 h = __float2bfloat16_rn(v);
        size_t o = (size_t)(n0 + ty) * K + k0 + tx;
        oh[o] = h;
        ol[o] = __float2bfloat16_rn(v - __bfloat162float(h));
    }
}

// ---------------- asm helpers ----------------------------------------------------
#define MMA_BF16(C, Ar, Br)                                                    \
    asm volatile("mma.sync.aligned.m16n8k16.row.col.f32.bf16.bf16.f32 "        \
        "{%0,%1,%2,%3}, {%4,%5,%6,%7}, {%8,%9}, {%0,%1,%2,%3};"                \
        : "+f"((C)[0]), "+f"((C)[1]), "+f"((C)[2]), "+f"((C)[3])               \
        : "r"((Ar)[0]), "r"((Ar)[1]), "r"((Ar)[2]), "r"((Ar)[3]),              \
          "r"((Br)[0]), "r"((Br)[1]))

#define LDSM4(R0, R1, R2, R3, ADDR)                                            \
    asm volatile("ldmatrix.sync.aligned.m8n8.x4.shared.b16 {%0,%1,%2,%3}, [%4];" \
        : "=r"(R0), "=r"(R1), "=r"(R2), "=r"(R3) : "r"(ADDR))

#define CP_ASYNC16(DST, SRC)                                                   \
    asm volatile("cp.async.cg.shared.global [%0], [%1], 16;" :: "r"(DST), "l"(SRC))
#define CP_COMMIT() asm volatile("cp.async.commit_group;" ::: "memory")
#define CP_WAIT0()  asm volatile("cp.async.wait_group 0;" ::: "memory")
#define CP_WAIT1()  asm volatile("cp.async.wait_group 1;" ::: "memory")

// ---------------- 3xBF16-split GEMM: C = A(MxK)@B^T(NxK), pre-split bf16 --------
// R11-proven: ldmatrix + cp.async double-buffer, 128x128 tile, 2 blocks/SM.
#define GKS 40                                   // bf16 k-stride (80B rows, conflict-free)
#define STG_ELEM (4 * 128 * GKS)                 // elements per stage (4 arrays)
#define STG_BYTES (STG_ELEM * 2)                 // 40960 bytes
#define ARR_BYTES (128 * GKS * 2)                // 10240 bytes per array
#define GEMM_SMEM (2 * STG_BYTES)                // 81920 bytes

__global__ __launch_bounds__(256, 2) void bf16gemm128(int M, int N, int K,
        const __nv_bfloat16* __restrict__ Ah_, const __nv_bfloat16* __restrict__ Al_,
        const __nv_bfloat16* __restrict__ Bth_, const __nv_bfloat16* __restrict__ Btl_,
        float* __restrict__ Cm)
{
    extern __shared__ __nv_bfloat16 gsm[];
    unsigned smemBase = (unsigned)__cvta_generic_to_shared(gsm);

    int tid = threadIdx.x;
    int brow = blockIdx.y * 128, bcol = blockIdx.x * 128;
    int warp = tid >> 5, lane = tid & 31;
    int wm = (warp & 1) * 64, wn = (warp >> 1) * 32;
    int lr = lane >> 2, lc2 = (lane & 3) * 2;

    int r0s = tid >> 2, kg0 = (tid & 3) * 8;
    int r1s = (tid + 256) >> 2, kg1 = (tid & 3) * 8;
    unsigned d0 = (unsigned)(r0s * GKS + kg0) * 2;
    unsigned d1 = (unsigned)(r1s * GKS + kg1) * 2;
    const __nv_bfloat16* srcA0h = Ah_  + (size_t)(brow + r0s) * K + kg0;
    const __nv_bfloat16* srcA1h = Ah_  + (size_t)(brow + r1s) * K + kg1;
    const __nv_bfloat16* srcA0l = Al_  + (size_t)(brow + r0s) * K + kg0;
    const __nv_bfloat16* srcA1l = Al_  + (size_t)(brow + r1s) * K + kg1;
    const __nv_bfloat16* srcB0h = Bth_ + (size_t)(bcol + r0s) * K + kg0;
    const __nv_bfloat16* srcB1h = Bth_ + (size_t)(bcol + r1s) * K + kg1;
    const __nv_bfloat16* srcB0l = Btl_ + (size_t)(bcol + r0s) * K + kg0;
    const __nv_bfloat16* srcB1l = Btl_ + (size_t)(bcol + r1s) * K + kg1;

    unsigned aoff = (unsigned)(((wm + (lane & 15)) * GKS) + ((lane >> 4) * 8)) * 2;
    unsigned boff = (unsigned)(((wn + (lane & 7) + (((lane >> 4) & 1) * 8)) * GKS)
                               + (((lane >> 3) & 1) * 8)) * 2;

    float c[4][4][4];
#pragma unroll
    for (int mt = 0; mt < 4; mt++)
#pragma unroll
        for (int nt = 0; nt < 4; nt++)
#pragma unroll
            for (int e = 0; e < 4; e++) c[mt][nt][e] = 0.f;

    {
        unsigned sb = smemBase;
        CP_ASYNC16(sb + d0,                 srcA0h);
        CP_ASYNC16(sb + d1,                 srcA1h);
        CP_ASYNC16(sb + ARR_BYTES + d0,     srcA0l);
        CP_ASYNC16(sb + ARR_BYTES + d1,     srcA1l);
        CP_ASYNC16(sb + 2 * ARR_BYTES + d0, srcB0h);
        CP_ASYNC16(sb + 2 * ARR_BYTES + d1, srcB1h);
        CP_ASYNC16(sb + 3 * ARR_BYTES + d0, srcB0l);
        CP_ASYNC16(sb + 3 * ARR_BYTES + d1, srcB1l);
        CP_COMMIT();
    }

    int buf = 0;
    for (int k0 = 0; k0 < K; k0 += 32) {
        bool hasNext = (k0 + 32) < K;
        if (hasNext) {
            unsigned sb = smemBase + (buf ^ 1) * STG_BYTES;
            int kn = k0 + 32;
            CP_ASYNC16(sb + d0,                 srcA0h + kn);
            CP_ASYNC16(sb + d1,                 srcA1h + kn);
            CP_ASYNC16(sb + ARR_BYTES + d0,     srcA0l + kn);
            CP_ASYNC16(sb + ARR_BYTES + d1,     srcA1l + kn);
            CP_ASYNC16(sb + 2 * ARR_BYTES + d0, srcB0h + kn);
            CP_ASYNC16(sb + 2 * ARR_BYTES + d1, srcB1h + kn);
            CP_ASYNC16(sb + 3 * ARR_BYTES + d0, srcB0l + kn);
            CP_ASYNC16(sb + 3 * ARR_BYTES + d1, srcB1l + kn);
            CP_COMMIT();
            CP_WAIT1();
        } else {
            CP_WAIT0();
        }
        __syncthreads();

        unsigned aBh = smemBase + buf * STG_BYTES;
        unsigned aBl = aBh + ARR_BYTES;
        unsigned bBh = aBh + 2 * ARR_BYTES;
        unsigned bBl = aBh + 3 * ARR_BYTES;

#pragma unroll
        for (int kk = 0; kk < 32; kk += 16) {
            unsigned ah[4][4], al[4][4], bh[2][4], bl[2][4];
#pragma unroll
            for (int mt = 0; mt < 4; mt++) {
                unsigned off = aoff + (unsigned)(mt * 16 * GKS + kk) * 2;
                LDSM4(ah[mt][0], ah[mt][1], ah[mt][2], ah[mt][3], aBh + off);
                LDSM4(al[mt][0], al[mt][1], al[mt][2], al[mt][3], aBl + off);
            }
#pragma unroll
            for (int p = 0; p < 2; p++) {
                unsigned off = boff + (unsigned)(p * 16 * GKS + kk) * 2;
                LDSM4(bh[p][0], bh[p][1], bh[p][2], bh[p][3], bBh + off);
                LDSM4(bl[p][0], bl[p][1], bl[p][2], bl[p][3], bBl + off);
            }
#pragma unroll
            for (int mt = 0; mt < 4; mt++)
#pragma unroll
                for (int nt = 0; nt < 4; nt++)
                    MMA_BF16(c[mt][nt], ah[mt], (&bh[nt >> 1][(nt & 1) * 2]));
#pragma unroll
            for (int mt = 0; mt < 4; mt++)
#pragma unroll
                for (int nt = 0; nt < 4; nt++)
                    MMA_BF16(c[mt][nt], al[mt], (&bh[nt >> 1][(nt & 1) * 2]));
#pragma unroll
            for (int mt = 0; mt < 4; mt++)
#pragma unroll
                for (int nt = 0; nt < 4; nt++)
                    MMA_BF16(c[mt][nt], ah[mt], (&bl[nt >> 1][(nt & 1) * 2]));
        }
        __syncthreads();
        buf ^= 1;
    }

#pragma unroll
    for (int mt = 0; mt < 4; mt++) {
        int r0 = brow + wm + mt * 16 + lr;
#pragma unroll
        for (int nt = 0; nt < 4; nt++) {
            int cn = bcol + wn + nt * 8 + lc2;
            *(float2*)(Cm + (size_t)r0 * N + cn)       = make_float2(c[mt][nt][0], c[mt][nt][1]);
            *(float2*)(Cm + (size_t)(r0 + 8) * N + cn) = make_float2(c[mt][nt][2], c[mt][nt][3]);
        }
    }
}

// ---------------- fused ba = x @ W_ba -> g, beta ---------------------------------
__global__ __launch_bounds__(256) void ba_gbeta_kernel(const float* __restrict__ x,
        const float* __restrict__ Wba, const float* __restrict__ dtb,
        const float* __restrict__ Alog, float* __restrict__ g, float* __restrict__ beta)
{
    int bt = blockIdx.x;
    __shared__ float xs[1024];
    const float* xrow = x + (size_t)bt * 1024;
    for (int i = threadIdx.x; i < 256; i += 256)
        ((float4*)xs)[i] = ((const float4*)xrow)[i];
    __syncthreads();
    int o = threadIdx.x >> 4, p = threadIdx.x & 15;
    float acc = 0.f;
    for (int k = p; k < 1024; k += 16) acc += xs[k] * Wba[(size_t)k * 16 + o];
    acc += __shfl_down_sync(0xffffffffu, acc, 8);
    acc += __shfl_down_sync(0xffffffffu, acc, 4);
    acc += __shfl_down_sync(0xffffffffu, acc, 2);
    acc += __shfl_down_sync(0xffffffffu, acc, 1);
    if (p == 0) {
        int h = o >> 1;
        if ((o & 1) == 0) {
            beta[(size_t)bt * 8 + h] = 1.f / (1.f + expf(-acc));
        } else {
            float xx = acc + dtb[h];
            float sp = (xx > 20.f) ? xx : log1pf(expf(xx));
            g[(size_t)bt * 8 + h] = -expf(Alog[h]) * sp;
        }
    }
}

// ---------------- causal depthwise conv (K=4) + silu ----------------------------
__global__ __launch_bounds__(256) void conv_silu_kernel(const float* __restrict__ qkvz,
        const float* __restrict__ cw, float* __restrict__ out)
{
    int idx = blockIdx.x * 256 + threadIdx.x;
    int ch = idx % 3072;
    int btrow = idx / 3072;
    int t = btrow & (TT - 1);
    int part = ch >> 10;
    int hc = (ch & 1023) >> 7;
    int d = ch & 127;
    int po = (part == 0) ? 0 : (part == 1) ? 128 : 256;
    float acc = 0.f;
#pragma unroll
    for (int j = 0; j < 4; j++) {
        int tt2 = t - 3 + j;
        if (tt2 >= 0) {
            float v = qkvz[(((size_t)(btrow - 3 + j)) * 8 + hc) * 512 + po + d];
            acc += v * cw[ch * 4 + j];
        }
    }
    out[(size_t)idx] = acc / (1.f + __expf(-acc));
}

// ---------------- Phase A: per-chunk local operators (register-tiled) -----------
// Exports P, L, v_new, k_cum, keff^T (no M/U materialization).
#define KST 68
#define ASD 65
#define PA_SMEM ((128*KST*2 + 64*256 + 64*ASD + 256) * 4)

__global__ __launch_bounds__(256) void phaseA_kernel(const float* __restrict__ conv,
        const float* __restrict__ gbuf, const float* __restrict__ betabuf,
        float* __restrict__ Pout, float* __restrict__ Lout,
        float* __restrict__ Vn, float* __restrict__ Kc, float* __restrict__ KfT,
        float* __restrict__ eglout)
{
    extern __shared__ float sm[];
    float* kst = sm;
    float* qst = kst + 128 * KST;
    float* ws  = qst + 128 * KST;
    float* As  = ws + 64 * 256;          // 64 x ASD
    float* gc  = As + 64 * ASD;
    float* egc = gc + 64;
    float* egr = egc + 64;
    float* bts = egr + 64;

    int cid = blockIdx.x;
    int n = cid & 63, bh = cid >> 6, h = bh & 7, b = bh >> 3;
    int tid = threadIdx.x;
    int warp = tid >> 5, lane = tid & 31;
    int t0 = n * 64;

    if (tid < 64) {
        int t = t0 + tid;
        gc[tid]  = gbuf[((size_t)(b * TT + t)) * 8 + h];
        bts[tid] = betabuf[((size_t)(b * TT + t)) * 8 + h];
    }
    __syncthreads();
#pragma unroll
    for (int off = 1; off < 64; off <<= 1) {
        float v = 0.f;
        if (tid < 64 && tid >= off) v = gc[tid - off];
        __syncthreads();
        if (tid < 64 && tid >= off) gc[tid] += v;
        __syncthreads();
    }
    if (tid < 64) {
        egc[tid] = __expf(gc[tid]);
        egr[tid] = __expf(gc[63] - gc[tid]);
    }
    __syncthreads();

    for (int r = warp; r < 64; r += 8) {
        int t = t0 + r;
        const float* base = conv + ((size_t)(b * TT + t)) * 3072 + h * 128;
        float qv[4], kv[4];
        float ssq = 0.f, ssk = 0.f;
#pragma unroll
        for (int u = 0; u < 4; u++) {
            qv[u] = base[lane + u * 32];
            kv[u] = base[1024 + lane + u * 32];
            ssq += qv[u] * qv[u];
            ssk += kv[u] * kv[u];
        }
#pragma unroll
        for (int off = 16; off; off >>= 1) {
            ssq += __shfl_xor_sync(0xffffffffu, ssq, off);
            ssk += __shfl_xor_sync(0xffffffffu, ssk, off);
        }
        float rq = rsqrtf(ssq + 1e-6f) * 0.08838834764831845f;
        float rk = rsqrtf(ssk + 1e-6f);
        float bbv = bts[r], egv = egc[r];
#pragma unroll
        for (int u = 0; u < 4; u++) {
            int d = lane + u * 32;
            qst[d * KST + r] = qv[u] * rq;
            float kn = kv[u] * rk;
            kst[d * KST + r] = kn;
            ws[r * 256 + d]       = base[2048 + d] * bbv;
            ws[r * 256 + 128 + d] = kn * bbv * egv;
        }
    }
    __syncthreads();

    int ti = tid >> 4, tj = tid & 15;

    // A[i][j] = beta_i (k_i . k_j) exp(gc_i - gc_j), j < i; else 0
    {
        float acc[4][4];
#pragma unroll
        for (int r = 0; r < 4; r++)
#pragma unroll
            for (int s = 0; s < 4; s++) acc[r][s] = 0.f;
        const float* ka = kst + ti * 4;
        const float* kb = kst + tj * 4;
#pragma unroll 4
        for (int d = 0; d < 128; d++) {
            float4 a = *(const float4*)(ka + d * KST);
            float4 bq = *(const float4*)(kb + d * KST);
            float ra[4] = {a.x, a.y, a.z, a.w};
            float rb[4] = {bq.x, bq.y, bq.z, bq.w};
#pragma unroll
            for (int r = 0; r < 4; r++)
#pragma unroll
                for (int s = 0; s < 4; s++) acc[r][s] += ra[r] * rb[s];
        }
#pragma unroll
        for (int r = 0; r < 4; r++) {
            int i = ti * 4 + r;
#pragma unroll
            for (int s = 0; s < 4; s++) {
                int j = tj * 4 + s;
                As[i * ASD + j] = (j < i) ? acc[r][s] * bts[i] * __expf(gc[i] - gc[j]) : 0.f;
            }
        }
    }
    __syncthreads();

    // blocked forward substitution: ws <- (I+A)^{-1} ws
    for (int blk = 0; blk < 4; blk++) {
        if (blk) {
            int tr = tid >> 7, tc = tid & 127;
            float acc[8][2];
#pragma unroll
            for (int r = 0; r < 8; r++) { acc[r][0] = 0.f; acc[r][1] = 0.f; }
            for (int j = 0; j < blk * 16; j++) {
                float2 wv = *(const float2*)(ws + j * 256 + tc * 2);
#pragma unroll
                for (int r = 0; r < 8; r++) {
                    float a = As[(blk * 16 + tr * 8 + r) * ASD + j];
                    acc[r][0] += a * wv.x;
                    acc[r][1] += a * wv.y;
                }
            }
#pragma unroll
            for (int r = 0; r < 8; r++) {
                float* w = ws + (blk * 16 + tr * 8 + r) * 256 + tc * 2;
                w[0] -= acc[r][0];
                w[1] -= acc[r][1];
            }
            __syncthreads();
        }
        {
            int c = tid;
            int i0 = blk * 16;
            for (int i = i0 + 1; i < i0 + 16; i++) {
                float acc = 0.f;
                for (int j = i0; j < i; j++) acc += As[i * ASD + j] * ws[j * 256 + c];
                ws[i * 256 + c] -= acc;
            }
        }
        __syncthreads();
    }

    // attn[i][j] = (q_i . k_j) exp(gc_i - gc_j), j <= i; else 0 (overwrite As)
    {
        float acc[4][4];
#pragma unroll
        for (int r = 0; r < 4; r++)
#pragma unroll
            for (int s = 0; s < 4; s++) acc[r][s] = 0.f;
        const float* qa = qst + ti * 4;
        const float* kb = kst + tj * 4;
#pragma unroll 4
        for (int d = 0; d < 128; d++) {
            float4 a = *(const float4*)(qa + d * KST);
            float4 bq = *(const float4*)(kb + d * KST);
            float ra[4] = {a.x, a.y, a.z, a.w};
            float rb[4] = {bq.x, bq.y, bq.z, bq.w};
#pragma unroll
            for (int r = 0; r < 4; r++)
#pragma unroll
                for (int s = 0; s < 4; s++) acc[r][s] += ra[r] * rb[s];
        }
#pragma unroll
        for (int r = 0; r < 4; r++) {
            int i = ti * 4 + r;
#pragma unroll
            for (int s = 0; s < 4; s++) {
                int j = tj * 4 + s;
                As[i * ASD + j] = (j <= i) ? acc[r][s] * __expf(gc[i] - gc[j]) : 0.f;
            }
        }
    }
    __syncthreads();

    // [L | attn@k_cum] = attn @ ws ;  P = q*e^gc - attn@k_cum
    {
        int tr = warp;
        int tc = lane;
        float acc[8][8];
#pragma unroll
        for (int r = 0; r < 8; r++)
#pragma unroll
            for (int u = 0; u < 8; u++) acc[r][u] = 0.f;
        int jmax = tr * 8 + 8;
        for (int j = 0; j < jmax; j++) {
            float av[8];
#pragma unroll
            for (int r = 0; r < 8; r++) av[r] = As[(tr * 8 + r) * ASD + j];
            float4 w0 = *(const float4*)(ws + j * 256 + tc * 8);
            float4 w1 = *(const float4*)(ws + j * 256 + tc * 8 + 4);
            float rb[8] = {w0.x, w0.y, w0.z, w0.w, w1.x, w1.y, w1.z, w1.w};
#pragma unroll
            for (int r = 0; r < 8; r++)
#pragma unroll
                for (int u = 0; u < 8; u++) acc[r][u] += av[r] * rb[u];
        }
        if (tc < 16) {
#pragma unroll
            for (int r = 0; r < 8; r++) {
                int i = tr * 8 + r;
                float* dst = Lout + ((size_t)cid * 64 + i) * 128 + tc * 8;
                *(float4*)(dst)     = make_float4(acc[r][0], acc[r][1], acc[r][2], acc[r][3]);
                *(float4*)(dst + 4) = make_float4(acc[r][4], acc[r][5], acc[r][6], acc[r][7]);
            }
        } else {
            int c0 = tc * 8 - 128;
#pragma unroll
            for (int r = 0; r < 8; r++) {
                int i = tr * 8 + r;
                float eg = egc[i];
                float v[8];
#pragma unroll
                for (int u = 0; u < 8; u++)
                    v[u] = qst[(c0 + u) * KST + i] * eg - acc[r][u];
                float* dst = Pout + ((size_t)cid * 64 + i) * 128 + c0;
                *(float4*)(dst)     = make_float4(v[0], v[1], v[2], v[3]);
                *(float4*)(dst + 4) = make_float4(v[4], v[5], v[6], v[7]);
            }
        }
    }

    // export v_new, k_cum ([i][d], coalesced) and keff^T ([a][i])
    for (int idx = tid; idx < 2048; idx += 256) {
        int row = idx >> 5, col = (idx & 31) * 4;
        *(float4*)(Vn + (size_t)cid * 8192 + row * 128 + col) =
            *(const float4*)(ws + row * 256 + col);
        *(float4*)(Kc + (size_t)cid * 8192 + row * 128 + col) =
            *(const float4*)(ws + row * 256 + 128 + col);
    }
    for (int idx = tid; idx < 2048; idx += 256) {
        int a = idx >> 4, ig = (idx & 15) * 4;
        float4 v;
        v.x = kst[a * KST + ig]     * egr[ig];
        v.y = kst[a * KST + ig + 1] * egr[ig + 1];
        v.z = kst[a * KST + ig + 2] * egr[ig + 2];
        v.w = kst[a * KST + ig + 3] * egr[ig + 3];
        *(float4*)(KfT + (size_t)cid * 8192 + a * 64 + ig) = v;
    }
    if (tid == 0) eglout[cid] = __expf(gc[63]);
}

// ---------------- Phase B: sequential scan over chunks, DV split ----------------
// Two-step update: tmp = v_new - k_cum@S ; out = L + P@S ; S' = egl*S + keff^T@tmp
#define PSD 132
#define KFD 68
#define PB_SMEM ((64*PSD*2 + 128*KFD + 64*16 + 128*16) * 4)

__global__ __launch_bounds__(256) void phaseB_kernel(const float* __restrict__ Pm,
        const float* __restrict__ Lm, const float* __restrict__ Kcm,
        const float* __restrict__ KfTm, const float* __restrict__ Vnm,
        const float* __restrict__ eglv, float* __restrict__ core)
{
    extern __shared__ float sm[];
    float* Ps  = sm;                 // 64 x PSD
    float* Kcs = Ps + 64 * PSD;      // 64 x PSD
    float* Kft = Kcs + 64 * PSD;     // 128 x KFD
    float* Tm  = Kft + 128 * KFD;    // 64 x 16
    float* Ss  = Tm + 64 * 16;       // 128 x 16

    int bh = blockIdx.x, gg = blockIdx.y;
    int b = bh >> 3, h = bh & 7;
    int tid = threadIdx.x;
    int c4g = tid & 3;
    int i0 = tid >> 2;               // 0..63
    int c0 = gg * 16;

    for (int i = tid; i < 128 * 16; i += 256) Ss[i] = 0.f;
    __syncthreads();

    for (int n = 0; n < 64; n++) {
        size_t cid = (size_t)bh * 64 + n;
        const float4* Pg = (const float4*)(Pm + cid * 8192);
        const float4* Kg = (const float4*)(Kcm + cid * 8192);
        for (int i = tid; i < 2048; i += 256) {
            int row = i >> 5, col = (i & 31) * 4;
            *(float4*)(Ps + row * PSD + col) = Pg[i];
            *(float4*)(Kcs + row * PSD + col) = Kg[i];
        }
        const float4* Fg = (const float4*)(KfTm + cid * 8192);
        for (int i = tid; i < 2048; i += 256) {
            int a = i >> 4, ig = (i & 15) * 4;
            *(float4*)(Kft + a * KFD + ig) = Fg[i];
        }
        __syncthreads();

        // step 1+2: out[i][c] = L + P@S ; tmp[i][c] = vn - kc@S  (i = i0)
        {
            float4 accO = *(const float4*)(Lm + cid * 8192 + i0 * 128 + c0 + c4g * 4);
            float4 accT = *(const float4*)(Vnm + cid * 8192 + i0 * 128 + c0 + c4g * 4);
            for (int a = 0; a < 128; a++) {
                float p  = Ps[i0 * PSD + a];
                float kc = Kcs[i0 * PSD + a];
                float4 s = *(const float4*)(Ss + a * 16 + c4g * 4);
                accO.x += p * s.x;  accO.y += p * s.y;  accO.z += p * s.z;  accO.w += p * s.w;
                accT.x -= kc * s.x; accT.y -= kc * s.y; accT.z -= kc * s.z; accT.w -= kc * s.w;
            }
            int t = n * 64 + i0;
            *(float4*)(core + (((size_t)(b * TT + t)) * 8 + h) * 128 + c0 + c4g * 4) = accO;
            *(float4*)(Tm + i0 * 16 + c4g * 4) = accT;
        }
        __syncthreads();

        // step 3: S'[a][c] = egl*S[a][c] + sum_i Kft[a][i]*tmp[i][c]  (a = i0, i0+64)
        float eg = eglv[cid];
        float4 s0 = *(const float4*)(Ss + i0 * 16 + c4g * 4);
        float4 s1 = *(const float4*)(Ss + (i0 + 64) * 16 + c4g * 4);
        float4 ns0 = make_float4(eg * s0.x, eg * s0.y, eg * s0.z, eg * s0.w);
        float4 ns1 = make_float4(eg * s1.x, eg * s1.y, eg * s1.z, eg * s1.w);
        for (int i = 0; i < 64; i++) {
            float4 tv = *(const float4*)(Tm + i * 16 + c4g * 4);
            float f0 = Kft[i0 * KFD + i];
            float f1 = Kft[(i0 + 64) * KFD + i];
            ns0.x += f0 * tv.x; ns0.y += f0 * tv.y; ns0.z += f0 * tv.z; ns0.w += f0 * tv.w;
            ns1.x += f1 * tv.x; ns1.y += f1 * tv.y; ns1.z += f1 * tv.z; ns1.w += f1 * tv.w;
        }
        *(float4*)(Ss + i0 * 16 + c4g * 4) = ns0;
        *(float4*)(Ss + (i0 + 64) * 16 + c4g * 4) = ns1;
        __syncthreads();
    }
}

// ---------------- gated RMSNorm * silu(z) -> bf16 hi/lo --------------------------
__global__ __launch_bounds__(128) void norm_kernel(const float* __restrict__ core,
        const float* __restrict__ qkvz, const float* __restrict__ nw,
        __nv_bfloat16* __restrict__ hh, __nv_bfloat16* __restrict__ hl)
{
    int bth = blockIdx.x;
    int d = threadIdx.x;
    float cv = core[(size_t)bth * 128 + d];
    float ss = cv * cv;
#pragma unroll
    for (int o = 16; o; o >>= 1) ss += __shfl_xor_sync(0xffffffffu, ss, o);
    __shared__ float red[4];
    if ((d & 31) == 0) red[d >> 5] = ss;
    __syncthreads();
    float tot = red[0] + red[1] + red[2] + red[3];
    float r = rsqrtf(tot * (1.f / 128.f) + 1e-6f);
    float zz = qkvz[(size_t)bth * 512 + 384 + d];
    float sz = zz / (1.f + __expf(-zz));
    float hv = nw[d] * cv * r * sz;
    __nv_bfloat16 h = __float2bfloat16_rn(hv);
    size_t o = (size_t)bth * 128 + d;
    hh[o] = h;
    hl[o] = __float2bfloat16_rn(hv - __bfloat162float(h));
}

// ---------------- launch ---------------------------------------------------------
extern "C" void kernel_launch(void* const* d_in, const int* in_sizes, int n_in,
                              void* d_out, int out_size)
{
    (void)in_sizes; (void)n_in; (void)out_size;
    const float* x    = (const float*)d_in[0];
    const float* Wq   = (const float*)d_in[1];
    const float* Wba  = (const float*)d_in[2];
    const float* cw   = (const float*)d_in[3];
    const float* dtb  = (const float*)d_in[4];
    const float* Alog = (const float*)d_in[5];
    const float* nw   = (const float*)d_in[6];
    const float* Wout = (const float*)d_in[7];
    float* out = (float*)d_out;

    float *qkvz, *convb, *gb, *betab, *Pb, *Lb, *vnb, *kcb, *kfb, *eglb, *coreb;
    __nv_bfloat16 *xh, *xl, *w1h, *w1l, *w2h, *w2l, *hh, *hl;
    cudaGetSymbolAddress((void**)&qkvz,  g_qkvz);
    cudaGetSymbolAddress((void**)&convb, g_conv);
    cudaGetSymbolAddress((void**)&gb,    g_g);
    cudaGetSymbolAddress((void**)&betab, g_beta);
    cudaGetSymbolAddress((void**)&Pb,    g_P);
    cudaGetSymbolAddress((void**)&Lb,    g_L);
    cudaGetSymbolAddress((void**)&vnb,   g_vn);
    cudaGetSymbolAddress((void**)&kcb,   g_kc);
    cudaGetSymbolAddress((void**)&kfb,   g_kf);
    cudaGetSymbolAddress((void**)&eglb,  g_egl);
    cudaGetSymbolAddress((void**)&coreb, g_core);
    cudaGetSymbolAddress((void**)&xh,  g_xh);
    cudaGetSymbolAddress((void**)&xl,  g_xl);
    cudaGetSymbolAddress((void**)&w1h, g_w1h);
    cudaGetSymbolAddress((void**)&w1l, g_w1l);
    cudaGetSymbolAddress((void**)&w2h, g_w2h);
    cudaGetSymbolAddress((void**)&w2l, g_w2l);
    cudaGetSymbolAddress((void**)&hh,  g_hh);
    cudaGetSymbolAddress((void**)&hl,  g_hl);

    cudaFuncSetAttribute(phaseA_kernel, cudaFuncAttributeMaxDynamicSharedMemorySize, PA_SMEM);
    cudaFuncSetAttribute(phaseB_kernel, cudaFuncAttributeMaxDynamicSharedMemorySize, PB_SMEM);
    cudaFuncSetAttribute(bf16gemm128, cudaFuncAttributeMaxDynamicSharedMemorySize, GEMM_SMEM);

    // 0. operand conversion (bandwidth-bound)
    cvt_split_kernel<<<(BB * TT * CC / 4) / 256, 256>>>(x, xh, xl);
    transpose_split_kernel<<<dim3(4096 / 32, CC / 32), 256>>>(Wq, w1h, w1l, CC, 4096);
    transpose_split_kernel<<<dim3(1024 / 32, CC / 32), 256>>>(Wout, w2h, w2l, CC, 1024);

    // 1. qkvz = x @ W_qkvz
    dim3 g1(4096 / 128, 8192 / 128);
    bf16gemm128<<<g1, 256, GEMM_SMEM>>>(BB * TT, 4096, CC, xh, xl, w1h, w1l, qkvz);
    // 2. ba = x @ W_ba fused with g/beta
    ba_gbeta_kernel<<<BB * TT, 256>>>(x, Wba, dtb, Alog, gb, betab);
    // 3. conv + silu
    conv_silu_kernel<<<(BB * TT * 3072) / 256, 256>>>(qkvz, cw, convb);
    // 4. phase A (exports P, L, v_new, k_cum, keff^T)
    phaseA_kernel<<<NCID, 256, PA_SMEM>>>(convb, gb, betab, Pb, Lb, vnb, kcb, kfb, eglb);
    // 5. phase B (two-step S update)
    dim3 gB(16, 8);
    phaseB_kernel<<<gB, 256, PB_SMEM>>>(Pb, Lb, kcb, kfb, vnb, eglb, coreb);
    // 6. gated RMSNorm * silu(z) -> bf16 hi/lo
    norm_kernel<<<BB * TT * NH, 128>>>(coreb, qkvz, nw, hh, hl);
    // 7. final projection
    dim3 g2(1024 / 128, 8192 / 128);
    bf16gemm128<<<g2, 256, GEMM_SMEM>>>(BB * TT, 1024, CC, hh, hl, w2h, w2l, out);
}

// round 15
// speedup vs baseline: 1.2799x; 1.1124x over previous
#include <cuda_runtime.h>
#include <cuda_bf16.h>
#include <math.h>

// Problem constants
#define BB 2
#define TT 4096
#define CC 1024
#define NH 8
#define DD 128
#define CHK 64
#define NCHUNK 64            // T / CHK
#define NCID 1024            // BB*NH*NCHUNK

// ---------------- scratch (device globals; no allocation allowed) ----------------
__device__ float g_qkvz[(size_t)BB*TT*4096];     // x @ W_qkvz      (B,T,8,512)
__device__ float g_conv[(size_t)BB*TT*3072];     // conv+silu [q|k|v]
__device__ float g_g[(size_t)BB*TT*NH];
__device__ float g_beta[(size_t)BB*TT*NH];
__device__ float g_P[(size_t)NCID*64*128];       // qeff - attn@k_cum
__device__ float g_L[(size_t)NCID*64*128];       // attn@v_new
__device__ float g_vn[(size_t)NCID*64*128];      // v_new
__device__ float g_kc[(size_t)NCID*64*128];      // k_cum
__device__ float g_kf[(size_t)NCID*128*64];      // keff^T  [a][i]
__device__ float g_egl[NCID];                    // exp(g_last)
__device__ float g_core[(size_t)BB*TT*NH*DD];    // delta-rule output

// bf16 hi/lo split operands for the two big GEMMs
__device__ __nv_bfloat16 g_xh[(size_t)BB*TT*CC],  g_xl[(size_t)BB*TT*CC];
__device__ __nv_bfloat16 g_w1h[(size_t)4096*CC],  g_w1l[(size_t)4096*CC];   // W_qkvz^T [N][K]
__device__ __nv_bfloat16 g_w2h[(size_t)1024*CC],  g_w2l[(size_t)1024*CC];   // W_out^T  [N][K]
__device__ __nv_bfloat16 g_hh[(size_t)BB*TT*1024], g_hl[(size_t)BB*TT*1024];

// ---------------- split/transpose conversion kernels ----------------------------
__global__ __launch_bounds__(256) void cvt_split_kernel(const float* __restrict__ in,
        __nv_bfloat16* __restrict__ oh, __nv_bfloat16* __restrict__ ol)
{
    int i = blockIdx.x * 256 + threadIdx.x;            // indexes float4
    float4 v = ((const float4*)in)[i];
    float f[4] = {v.x, v.y, v.z, v.w};
    __nv_bfloat16 h[4], l[4];
#pragma unroll
    for (int e = 0; e < 4; e++) {
        h[e] = __float2bfloat16_rn(f[e]);
        l[e] = __float2bfloat16_rn(f[e] - __bfloat162float(h[e]));
    }
    __nv_bfloat162 h0; h0.x = h[0]; h0.y = h[1];
    __nv_bfloat162 h1; h1.x = h[2]; h1.y = h[3];
    __nv_bfloat162 l0; l0.x = l[0]; l0.y = l[1];
    __nv_bfloat162 l1; l1.x = l[2]; l1.y = l[3];
    ((__nv_bfloat162*)oh)[i * 2]     = h0;
    ((__nv_bfloat162*)oh)[i * 2 + 1] = h1;
    ((__nv_bfloat162*)ol)[i * 2]     = l0;
    ((__nv_bfloat162*)ol)[i * 2 + 1] = l1;
}

// W [K][N] f32 -> Wt [N][K] bf16 hi/lo
__global__ __launch_bounds__(256) void transpose_split_kernel(const float* __restrict__ W,
        __nv_bfloat16* __restrict__ oh, __nv_bfloat16* __restrict__ ol, int K, int N)
{
    __shared__ float tile[32][33];
    int n0 = blockIdx.x * 32, k0 = blockIdx.y * 32;
    int tx = threadIdx.x & 31, ty0 = threadIdx.x >> 5;
#pragma unroll
    for (int ty = ty0; ty < 32; ty += 8)
        tile[ty][tx] = W[(size_t)(k0 + ty) * N + n0 + tx];
    __syncthreads();
#pragma unroll
    for (int ty = ty0; ty < 32; ty += 8) {
        float v = tile[tx][ty];
        __nv_bfloat16 h = __float2bfloat16_rn(v);
        size_t o = (size_t)(n0 + ty) * K + k0 + tx;
        oh[o] = h;
        ol[o] = __float2bfloat16_rn(v - __bfloat162float(h));
    }
}

// ---------------- asm helpers ----------------------------------------------------
#define MMA_BF16(C, Ar, Br)                                                    \
    asm volatile("mma.sync.aligned.m16n8k16.row.col.f32.bf16.bf16.f32 "        \
        "{%0,%1,%2,%3}, {%4,%5,%6,%7}, {%8,%9}, {%0,%1,%2,%3};"                \
        : "+f"((C)[0]), "+f"((C)[1]), "+f"((C)[2]), "+f"((C)[3])               \
        : "r"((Ar)[0]), "r"((Ar)[1]), "r"((Ar)[2]), "r"((Ar)[3]),              \
          "r"((Br)[0]), "r"((Br)[1]))

#define LDSM4(R0, R1, R2, R3, ADDR)                                            \
    asm volatile("ldmatrix.sync.aligned.m8n8.x4.shared.b16 {%0,%1,%2,%3}, [%4];" \
        : "=r"(R0), "=r"(R1), "=r"(R2), "=r"(R3) : "r"(ADDR))

#define CP_ASYNC16(DST, SRC)                                                   \
    asm volatile("cp.async.cg.shared.global [%0], [%1], 16;" :: "r"(DST), "l"(SRC))
#define CP_COMMIT() asm volatile("cp.async.commit_group;" ::: "memory")
#define CP_WAIT0()  asm volatile("cp.async.wait_group 0;" ::: "memory")
#define CP_WAIT1()  asm volatile("cp.async.wait_group 1;" ::: "memory")

// ---------------- 3xBF16-split GEMM: C = A(MxK)@B^T(NxK), pre-split bf16 --------
// R11-proven: ldmatrix + cp.async double-buffer, 128x128 tile, 2 blocks/SM.
#define GKS 40                                   // bf16 k-stride (80B rows, conflict-free)
#define STG_ELEM (4 * 128 * GKS)                 // elements per stage (4 arrays)
#define STG_BYTES (STG_ELEM * 2)                 // 40960 bytes
#define ARR_BYTES (128 * GKS * 2)                // 10240 bytes per array
#define GEMM_SMEM (2 * STG_BYTES)                // 81920 bytes

__global__ __launch_bounds__(256, 2) void bf16gemm128(int M, int N, int K,
        const __nv_bfloat16* __restrict__ Ah_, const __nv_bfloat16* __restrict__ Al_,
        const __nv_bfloat16* __restrict__ Bth_, const __nv_bfloat16* __restrict__ Btl_,
        float* __restrict__ Cm)
{
    extern __shared__ __nv_bfloat16 gsm[];
    unsigned smemBase = (unsigned)__cvta_generic_to_shared(gsm);

    int tid = threadIdx.x;
    int brow = blockIdx.y * 128, bcol = blockIdx.x * 128;
    int warp = tid >> 5, lane = tid & 31;
    int wm = (warp & 1) * 64, wn = (warp >> 1) * 32;
    int lr = lane >> 2, lc2 = (lane & 3) * 2;

    int r0s = tid >> 2, kg0 = (tid & 3) * 8;
    int r1s = (tid + 256) >> 2, kg1 = (tid & 3) * 8;
    unsigned d0 = (unsigned)(r0s * GKS + kg0) * 2;
    unsigned d1 = (unsigned)(r1s * GKS + kg1) * 2;
    const __nv_bfloat16* srcA0h = Ah_  + (size_t)(brow + r0s) * K + kg0;
    const __nv_bfloat16* srcA1h = Ah_  + (size_t)(brow + r1s) * K + kg1;
    const __nv_bfloat16* srcA0l = Al_  + (size_t)(brow + r0s) * K + kg0;
    const __nv_bfloat16* srcA1l = Al_  + (size_t)(brow + r1s) * K + kg1;
    const __nv_bfloat16* srcB0h = Bth_ + (size_t)(bcol + r0s) * K + kg0;
    const __nv_bfloat16* srcB1h = Bth_ + (size_t)(bcol + r1s) * K + kg1;
    const __nv_bfloat16* srcB0l = Btl_ + (size_t)(bcol + r0s) * K + kg0;
    const __nv_bfloat16* srcB1l = Btl_ + (size_t)(bcol + r1s) * K + kg1;

    unsigned aoff = (unsigned)(((wm + (lane & 15)) * GKS) + ((lane >> 4) * 8)) * 2;
    unsigned boff = (unsigned)(((wn + (lane & 7) + (((lane >> 4) & 1) * 8)) * GKS)
                               + (((lane >> 3) & 1) * 8)) * 2;

    float c[4][4][4];
#pragma unroll
    for (int mt = 0; mt < 4; mt++)
#pragma unroll
        for (int nt = 0; nt < 4; nt++)
#pragma unroll
            for (int e = 0; e < 4; e++) c[mt][nt][e] = 0.f;

    {
        unsigned sb = smemBase;
        CP_ASYNC16(sb + d0,                 srcA0h);
        CP_ASYNC16(sb + d1,                 srcA1h);
        CP_ASYNC16(sb + ARR_BYTES + d0,     srcA0l);
        CP_ASYNC16(sb + ARR_BYTES + d1,     srcA1l);
        CP_ASYNC16(sb + 2 * ARR_BYTES + d0, srcB0h);
        CP_ASYNC16(sb + 2 * ARR_BYTES + d1, srcB1h);
        CP_ASYNC16(sb + 3 * ARR_BYTES + d0, srcB0l);
        CP_ASYNC16(sb + 3 * ARR_BYTES + d1, srcB1l);
        CP_COMMIT();
    }

    int buf = 0;
    for (int k0 = 0; k0 < K; k0 += 32) {
        bool hasNext = (k0 + 32) < K;
        if (hasNext) {
            unsigned sb = smemBase + (buf ^ 1) * STG_BYTES;
            int kn = k0 + 32;
            CP_ASYNC16(sb + d0,                 srcA0h + kn);
            CP_ASYNC16(sb + d1,                 srcA1h + kn);
            CP_ASYNC16(sb + ARR_BYTES + d0,     srcA0l + kn);
            CP_ASYNC16(sb + ARR_BYTES + d1,     srcA1l + kn);
            CP_ASYNC16(sb + 2 * ARR_BYTES + d0, srcB0h + kn);
            CP_ASYNC16(sb + 2 * ARR_BYTES + d1, srcB1h + kn);
            CP_ASYNC16(sb + 3 * ARR_BYTES + d0, srcB0l + kn);
            CP_ASYNC16(sb + 3 * ARR_BYTES + d1, srcB1l + kn);
            CP_COMMIT();
            CP_WAIT1();
        } else {
            CP_WAIT0();
        }
        __syncthreads();

        unsigned aBh = smemBase + buf * STG_BYTES;
        unsigned aBl = aBh + ARR_BYTES;
        unsigned bBh = aBh + 2 * ARR_BYTES;
        unsigned bBl = aBh + 3 * ARR_BYTES;

#pragma unroll
        for (int kk = 0; kk < 32; kk += 16) {
            unsigned ah[4][4], al[4][4], bh[2][4], bl[2][4];
#pragma unroll
            for (int mt = 0; mt < 4; mt++) {
                unsigned off = aoff + (unsigned)(mt * 16 * GKS + kk) * 2;
                LDSM4(ah[mt][0], ah[mt][1], ah[mt][2], ah[mt][3], aBh + off);
                LDSM4(al[mt][0], al[mt][1], al[mt][2], al[mt][3], aBl + off);
            }
#pragma unroll
            for (int p = 0; p < 2; p++) {
                unsigned off = boff + (unsigned)(p * 16 * GKS + kk) * 2;
                LDSM4(bh[p][0], bh[p][1], bh[p][2], bh[p][3], bBh + off);
                LDSM4(bl[p][0], bl[p][1], bl[p][2], bl[p][3], bBl + off);
            }
#pragma unroll
            for (int mt = 0; mt < 4; mt++)
#pragma unroll
                for (int nt = 0; nt < 4; nt++)
                    MMA_BF16(c[mt][nt], ah[mt], (&bh[nt >> 1][(nt & 1) * 2]));
#pragma unroll
            for (int mt = 0; mt < 4; mt++)
#pragma unroll
                for (int nt = 0; nt < 4; nt++)
                    MMA_BF16(c[mt][nt], al[mt], (&bh[nt >> 1][(nt & 1) * 2]));
#pragma unroll
            for (int mt = 0; mt < 4; mt++)
#pragma unroll
                for (int nt = 0; nt < 4; nt++)
                    MMA_BF16(c[mt][nt], ah[mt], (&bl[nt >> 1][(nt & 1) * 2]));
        }
        __syncthreads();
        buf ^= 1;
    }

#pragma unroll
    for (int mt = 0; mt < 4; mt++) {
        int r0 = brow + wm + mt * 16 + lr;
#pragma unroll
        for (int nt = 0; nt < 4; nt++) {
            int cn = bcol + wn + nt * 8 + lc2;
            *(float2*)(Cm + (size_t)r0 * N + cn)       = make_float2(c[mt][nt][0], c[mt][nt][1]);
            *(float2*)(Cm + (size_t)(r0 + 8) * N + cn) = make_float2(c[mt][nt][2], c[mt][nt][3]);
        }
    }
}

// ---------------- fused ba = x @ W_ba -> g, beta ---------------------------------
__global__ __launch_bounds__(256) void ba_gbeta_kernel(const float* __restrict__ x,
        const float* __restrict__ Wba, const float* __restrict__ dtb,
        const float* __restrict__ Alog, float* __restrict__ g, float* __restrict__ beta)
{
    int bt = blockIdx.x;
    __shared__ float xs[1024];
    const float* xrow = x + (size_t)bt * 1024;
    for (int i = threadIdx.x; i < 256; i += 256)
        ((float4*)xs)[i] = ((const float4*)xrow)[i];
    __syncthreads();
    int o = threadIdx.x >> 4, p = threadIdx.x & 15;
    float acc = 0.f;
    for (int k = p; k < 1024; k += 16) acc += xs[k] * Wba[(size_t)k * 16 + o];
    acc += __shfl_down_sync(0xffffffffu, acc, 8);
    acc += __shfl_down_sync(0xffffffffu, acc, 4);
    acc += __shfl_down_sync(0xffffffffu, acc, 2);
    acc += __shfl_down_sync(0xffffffffu, acc, 1);
    if (p == 0) {
        int h = o >> 1;
        if ((o & 1) == 0) {
            beta[(size_t)bt * 8 + h] = 1.f / (1.f + expf(-acc));
        } else {
            float xx = acc + dtb[h];
            float sp = (xx > 20.f) ? xx : log1pf(expf(xx));
            g[(size_t)bt * 8 + h] = -expf(Alog[h]) * sp;
        }
    }
}

// ---------------- causal depthwise conv (K=4) + silu ----------------------------
__global__ __launch_bounds__(256) void conv_silu_kernel(const float* __restrict__ qkvz,
        const float* __restrict__ cw, float* __restrict__ out)
{
    int idx = blockIdx.x * 256 + threadIdx.x;
    int ch = idx % 3072;
    int btrow = idx / 3072;
    int t = btrow & (TT - 1);
    int part = ch >> 10;
    int hc = (ch & 1023) >> 7;
    int d = ch & 127;
    int po = (part == 0) ? 0 : (part == 1) ? 128 : 256;
    float acc = 0.f;
#pragma unroll
    for (int j = 0; j < 4; j++) {
        int tt2 = t - 3 + j;
        if (tt2 >= 0) {
            float v = qkvz[(((size_t)(btrow - 3 + j)) * 8 + hc) * 512 + po + d];
            acc += v * cw[ch * 4 + j];
        }
    }
    out[(size_t)idx] = acc / (1.f + __expf(-acc));
}

// ---------------- Phase A: per-chunk local operators (register-tiled) -----------
// Exports P, L, v_new, k_cum, keff^T (no M/U materialization).
#define KST 68
#define ASD 65
#define PA_SMEM ((128*KST*2 + 64*256 + 64*ASD + 256) * 4)

__global__ __launch_bounds__(256) void phaseA_kernel(const float* __restrict__ conv,
        const float* __restrict__ gbuf, const float* __restrict__ betabuf,
        float* __restrict__ Pout, float* __restrict__ Lout,
        float* __restrict__ Vn, float* __restrict__ Kc, float* __restrict__ KfT,
        float* __restrict__ eglout)
{
    extern __shared__ float sm[];
    float* kst = sm;
    float* qst = kst + 128 * KST;
    float* ws  = qst + 128 * KST;
    float* As  = ws + 64 * 256;          // 64 x ASD
    float* gc  = As + 64 * ASD;
    float* egc = gc + 64;
    float* egr = egc + 64;
    float* bts = egr + 64;

    int cid = blockIdx.x;
    int n = cid & 63, bh = cid >> 6, h = bh & 7, b = bh >> 3;
    int tid = threadIdx.x;
    int warp = tid >> 5, lane = tid & 31;
    int t0 = n * 64;

    if (tid < 64) {
        int t = t0 + tid;
        gc[tid]  = gbuf[((size_t)(b * TT + t)) * 8 + h];
        bts[tid] = betabuf[((size_t)(b * TT + t)) * 8 + h];
    }
    __syncthreads();
#pragma unroll
    for (int off = 1; off < 64; off <<= 1) {
        float v = 0.f;
        if (tid < 64 && tid >= off) v = gc[tid - off];
        __syncthreads();
        if (tid < 64 && tid >= off) gc[tid] += v;
        __syncthreads();
    }
    if (tid < 64) {
        egc[tid] = __expf(gc[tid]);
        egr[tid] = __expf(gc[63] - gc[tid]);
    }
    __syncthreads();

    for (int r = warp; r < 64; r += 8) {
        int t = t0 + r;
        const float* base = conv + ((size_t)(b * TT + t)) * 3072 + h * 128;
        float qv[4], kv[4];
        float ssq = 0.f, ssk = 0.f;
#pragma unroll
        for (int u = 0; u < 4; u++) {
            qv[u] = base[lane + u * 32];
            kv[u] = base[1024 + lane + u * 32];
            ssq += qv[u] * qv[u];
            ssk += kv[u] * kv[u];
        }
#pragma unroll
        for (int off = 16; off; off >>= 1) {
            ssq += __shfl_xor_sync(0xffffffffu, ssq, off);
            ssk += __shfl_xor_sync(0xffffffffu, ssk, off);
        }
        float rq = rsqrtf(ssq + 1e-6f) * 0.08838834764831845f;
        float rk = rsqrtf(ssk + 1e-6f);
        float bbv = bts[r], egv = egc[r];
#pragma unroll
        for (int u = 0; u < 4; u++) {
            int d = lane + u * 32;
            qst[d * KST + r] = qv[u] * rq;
            float kn = kv[u] * rk;
            kst[d * KST + r] = kn;
            ws[r * 256 + d]       = base[2048 + d] * bbv;
            ws[r * 256 + 128 + d] = kn * bbv * egv;
        }
    }
    __syncthreads();

    int ti = tid >> 4, tj = tid & 15;

    // A[i][j] = beta_i (k_i . k_j) exp(gc_i - gc_j), j < i; else 0
    {
        float acc[4][4];
#pragma unroll
        for (int r = 0; r < 4; r++)
#pragma unroll
            for (int s = 0; s < 4; s++) acc[r][s] = 0.f;
        const float* ka = kst + ti * 4;
        const float* kb = kst + tj * 4;
#pragma unroll 4
        for (int d = 0; d < 128; d++) {
            float4 a = *(const float4*)(ka + d * KST);
            float4 bq = *(const float4*)(kb + d * KST);
            float ra[4] = {a.x, a.y, a.z, a.w};
            float rb[4] = {bq.x, bq.y, bq.z, bq.w};
#pragma unroll
            for (int r = 0; r < 4; r++)
#pragma unroll
                for (int s = 0; s < 4; s++) acc[r][s] += ra[r] * rb[s];
        }
#pragma unroll
        for (int r = 0; r < 4; r++) {
            int i = ti * 4 + r;
#pragma unroll
            for (int s = 0; s < 4; s++) {
                int j = tj * 4 + s;
                As[i * ASD + j] = (j < i) ? acc[r][s] * bts[i] * __expf(gc[i] - gc[j]) : 0.f;
            }
        }
    }
    __syncthreads();

    // blocked forward substitution: ws <- (I+A)^{-1} ws
    for (int blk = 0; blk < 4; blk++) {
        if (blk) {
            int tr = tid >> 7, tc = tid & 127;
            float acc[8][2];
#pragma unroll
            for (int r = 0; r < 8; r++) { acc[r][0] = 0.f; acc[r][1] = 0.f; }
            for (int j = 0; j < blk * 16; j++) {
                float2 wv = *(const float2*)(ws + j * 256 + tc * 2);
#pragma unroll
                for (int r = 0; r < 8; r++) {
                    float a = As[(blk * 16 + tr * 8 + r) * ASD + j];
                    acc[r][0] += a * wv.x;
                    acc[r][1] += a * wv.y;
                }
            }
#pragma unroll
            for (int r = 0; r < 8; r++) {
                float* w = ws + (blk * 16 + tr * 8 + r) * 256 + tc * 2;
                w[0] -= acc[r][0];
                w[1] -= acc[r][1];
            }
            __syncthreads();
        }
        {
            int c = tid;
            int i0 = blk * 16;
            for (int i = i0 + 1; i < i0 + 16; i++) {
                float acc = 0.f;
                for (int j = i0; j < i; j++) acc += As[i * ASD + j] * ws[j * 256 + c];
                ws[i * 256 + c] -= acc;
            }
        }
        __syncthreads();
    }

    // attn[i][j] = (q_i . k_j) exp(gc_i - gc_j), j <= i; else 0 (overwrite As)
    {
        float acc[4][4];
#pragma unroll
        for (int r = 0; r < 4; r++)
#pragma unroll
            for (int s = 0; s < 4; s++) acc[r][s] = 0.f;
        const float* qa = qst + ti * 4;
        const float* kb = kst + tj * 4;
#pragma unroll 4
        for (int d = 0; d < 128; d++) {
            float4 a = *(const float4*)(qa + d * KST);
            float4 bq = *(const float4*)(kb + d * KST);
            float ra[4] = {a.x, a.y, a.z, a.w};
            float rb[4] = {bq.x, bq.y, bq.z, bq.w};
#pragma unroll
            for (int r = 0; r < 4; r++)
#pragma unroll
                for (int s = 0; s < 4; s++) acc[r][s] += ra[r] * rb[s];
        }
#pragma unroll
        for (int r = 0; r < 4; r++) {
            int i = ti * 4 + r;
#pragma unroll
            for (int s = 0; s < 4; s++) {
                int j = tj * 4 + s;
                As[i * ASD + j] = (j <= i) ? acc[r][s] * __expf(gc[i] - gc[j]) : 0.f;
            }
        }
    }
    __syncthreads();

    // [L | attn@k_cum] = attn @ ws ;  P = q*e^gc - attn@k_cum
    {
        int tr = warp;
        int tc = lane;
        float acc[8][8];
#pragma unroll
        for (int r = 0; r < 8; r++)
#pragma unroll
            for (int u = 0; u < 8; u++) acc[r][u] = 0.f;
        int jmax = tr * 8 + 8;
        for (int j = 0; j < jmax; j++) {
            float av[8];
#pragma unroll
            for (int r = 0; r < 8; r++) av[r] = As[(tr * 8 + r) * ASD + j];
            float4 w0 = *(const float4*)(ws + j * 256 + tc * 8);
            float4 w1 = *(const float4*)(ws + j * 256 + tc * 8 + 4);
            float rb[8] = {w0.x, w0.y, w0.z, w0.w, w1.x, w1.y, w1.z, w1.w};
#pragma unroll
            for (int r = 0; r < 8; r++)
#pragma unroll
                for (int u = 0; u < 8; u++) acc[r][u] += av[r] * rb[u];
        }
        if (tc < 16) {
#pragma unroll
            for (int r = 0; r < 8; r++) {
                int i = tr * 8 + r;
                float* dst = Lout + ((size_t)cid * 64 + i) * 128 + tc * 8;
                *(float4*)(dst)     = make_float4(acc[r][0], acc[r][1], acc[r][2], acc[r][3]);
                *(float4*)(dst + 4) = make_float4(acc[r][4], acc[r][5], acc[r][6], acc[r][7]);
            }
        } else {
            int c0 = tc * 8 - 128;
#pragma unroll
            for (int r = 0; r < 8; r++) {
                int i = tr * 8 + r;
                float eg = egc[i];
                float v[8];
#pragma unroll
                for (int u = 0; u < 8; u++)
                    v[u] = qst[(c0 + u) * KST + i] * eg - acc[r][u];
                float* dst = Pout + ((size_t)cid * 64 + i) * 128 + c0;
                *(float4*)(dst)     = make_float4(v[0], v[1], v[2], v[3]);
                *(float4*)(dst + 4) = make_float4(v[4], v[5], v[6], v[7]);
            }
        }
    }

    // export v_new, k_cum ([i][d], coalesced) and keff^T ([a][i])
    for (int idx = tid; idx < 2048; idx += 256) {
        int row = idx >> 5, col = (idx & 31) * 4;
        *(float4*)(Vn + (size_t)cid * 8192 + row * 128 + col) =
            *(const float4*)(ws + row * 256 + col);
        *(float4*)(Kc + (size_t)cid * 8192 + row * 128 + col) =
            *(const float4*)(ws + row * 256 + 128 + col);
    }
    for (int idx = tid; idx < 2048; idx += 256) {
        int a = idx >> 4, ig = (idx & 15) * 4;
        float4 v;
        v.x = kst[a * KST + ig]     * egr[ig];
        v.y = kst[a * KST + ig + 1] * egr[ig + 1];
        v.z = kst[a * KST + ig + 2] * egr[ig + 2];
        v.w = kst[a * KST + ig + 3] * egr[ig + 3];
        *(float4*)(KfT + (size_t)cid * 8192 + a * 64 + ig) = v;
    }
    if (tid == 0) eglout[cid] = __expf(gc[63]);
}

// ---------------- Phase B: sequential scan, cp.async double-buffered ------------
// tmp = v_new - k_cum@S ; out = L + P@S ; S' = egl*S + keff^T@tmp
#define PSD 132
#define KFD 68
#define PB_BUF (64*PSD + 64*PSD + 128*KFD)       // floats per stage buffer = 25600
#define PB_SMEM ((2*PB_BUF + 64*16 + 128*16) * 4)  // 217088 bytes

__global__ __launch_bounds__(256) void phaseB_kernel(const float* __restrict__ Pm,
        const float* __restrict__ Lm, const float* __restrict__ Kcm,
        const float* __restrict__ KfTm, const float* __restrict__ Vnm,
        const float* __restrict__ eglv, float* __restrict__ core)
{
    extern __shared__ float sm[];
    float* Tm = sm + 2 * PB_BUF;     // 64 x 16
    float* Ss = Tm + 64 * 16;        // 128 x 16
    unsigned smemBase = (unsigned)__cvta_generic_to_shared(sm);

    int bh = blockIdx.x, gg = blockIdx.y;
    int b = bh >> 3, h = bh & 7;
    int tid = threadIdx.x;
    int c4g = tid & 3;
    int i0 = tid >> 2;               // 0..63
    int c0 = gg * 16;

    // per-thread staging offsets (8 chunks of 16B per array)
    int srow = tid >> 5, scol = (tid & 31) * 4;  // P/Kc pattern base (advance row by 8)
    int sa = tid >> 4, sig = (tid & 15) * 4;     // Kft pattern base (advance a by 16)

    for (int i = tid; i < 128 * 16; i += 256) Ss[i] = 0.f;
    __syncthreads();

    // stage one chunk's P/Kc/Kft into buffer bf
    auto stage = [&](int n, int bf) {
        size_t cid = (size_t)bh * 64 + n;
        const float* Pg = Pm + cid * 8192;
        const float* Kg = Kcm + cid * 8192;
        const float* Fg = KfTm + cid * 8192;
        unsigned base = smemBase + (unsigned)(bf * PB_BUF) * 4;
        unsigned kcB = base + (unsigned)(64 * PSD) * 4;
        unsigned kfB = kcB + (unsigned)(64 * PSD) * 4;
#pragma unroll
        for (int u = 0; u < 8; u++) {
            int row = srow + u * 8;
            unsigned off = (unsigned)(row * PSD + scol) * 4;
            CP_ASYNC16(base + off, Pg + row * 128 + scol);
            CP_ASYNC16(kcB + off, Kg + row * 128 + scol);
            int a = sa + u * 16;
            CP_ASYNC16(kfB + (unsigned)(a * KFD + sig) * 4, Fg + a * 64 + sig);
        }
        CP_COMMIT();
    };

    stage(0, 0);

    int buf = 0;
    for (int n = 0; n < 64; n++) {
        size_t cid = (size_t)bh * 64 + n;
        // prefetch L/Vn for this chunk (LDG latency overlaps cp.async wait)
        float4 accO = *(const float4*)(Lm + cid * 8192 + i0 * 128 + c0 + c4g * 4);
        float4 accT = *(const float4*)(Vnm + cid * 8192 + i0 * 128 + c0 + c4g * 4);
        float eg = eglv[cid];

        if (n + 1 < 64) { stage(n + 1, buf ^ 1); CP_WAIT1(); }
        else           { CP_WAIT0(); }
        __syncthreads();

        const float* Ps  = sm + buf * PB_BUF;
        const float* Kcs = Ps + 64 * PSD;
        const float* Kft = Kcs + 64 * PSD;

        // step 1+2: out[i][c] = L + P@S ; tmp[i][c] = vn - kc@S  (i = i0)
        {
            for (int a = 0; a < 128; a++) {
                float p  = Ps[i0 * PSD + a];
                float kc = Kcs[i0 * PSD + a];
                float4 s = *(const float4*)(Ss + a * 16 + c4g * 4);
                accO.x += p * s.x;  accO.y += p * s.y;  accO.z += p * s.z;  accO.w += p * s.w;
                accT.x -= kc * s.x; accT.y -= kc * s.y; accT.z -= kc * s.z; accT.w -= kc * s.w;
            }
            int t = n * 64 + i0;
            *(float4*)(core + (((size_t)(b * TT + t)) * 8 + h) * 128 + c0 + c4g * 4) = accO;
            *(float4*)(Tm + i0 * 16 + c4g * 4) = accT;
        }
        __syncthreads();

        // step 3: S'[a][c] = egl*S[a][c] + sum_i Kft[a][i]*tmp[i][c]  (a = i0, i0+64)
        float4 s0 = *(const float4*)(Ss + i0 * 16 + c4g * 4);
        float4 s1 = *(const float4*)(Ss + (i0 + 64) * 16 + c4g * 4);
        float4 ns0 = make_float4(eg * s0.x, eg * s0.y, eg * s0.z, eg * s0.w);
        float4 ns1 = make_float4(eg * s1.x, eg * s1.y, eg * s1.z, eg * s1.w);
        for (int i = 0; i < 64; i++) {
            float4 tv = *(const float4*)(Tm + i * 16 + c4g * 4);
            float f0 = Kft[i0 * KFD + i];
            float f1 = Kft[(i0 + 64) * KFD + i];
            ns0.x += f0 * tv.x; ns0.y += f0 * tv.y; ns0.z += f0 * tv.z; ns0.w += f0 * tv.w;
            ns1.x += f1 * tv.x; ns1.y += f1 * tv.y; ns1.z += f1 * tv.z; ns1.w += f1 * tv.w;
        }
        *(float4*)(Ss + i0 * 16 + c4g * 4) = ns0;
        *(float4*)(Ss + (i0 + 64) * 16 + c4g * 4) = ns1;
        __syncthreads();
        buf ^= 1;
    }
}

// ---------------- gated RMSNorm * silu(z) -> bf16 hi/lo --------------------------
__global__ __launch_bounds__(128) void norm_kernel(const float* __restrict__ core,
        const float* __restrict__ qkvz, const float* __restrict__ nw,
        __nv_bfloat16* __restrict__ hh, __nv_bfloat16* __restrict__ hl)
{
    int bth = blockIdx.x;
    int d = threadIdx.x;
    float cv = core[(size_t)bth * 128 + d];
    float ss = cv * cv;
#pragma unroll
    for (int o = 16; o; o >>= 1) ss += __shfl_xor_sync(0xffffffffu, ss, o);
    __shared__ float red[4];
    if ((d & 31) == 0) red[d >> 5] = ss;
    __syncthreads();
    float tot = red[0] + red[1] + red[2] + red[3];
    float r = rsqrtf(tot * (1.f / 128.f) + 1e-6f);
    float zz = qkvz[(size_t)bth * 512 + 384 + d];
    float sz = zz / (1.f + __expf(-zz));
    float hv = nw[d] * cv * r * sz;
    __nv_bfloat16 h = __float2bfloat16_rn(hv);
    size_t o = (size_t)bth * 128 + d;
    hh[o] = h;
    hl[o] = __float2bfloat16_rn(hv - __bfloat162float(h));
}

// ---------------- launch ---------------------------------------------------------
extern "C" void kernel_launch(void* const* d_in, const int* in_sizes, int n_in,
                              void* d_out, int out_size)
{
    (void)in_sizes; (void)n_in; (void)out_size;
    const float* x    = (const float*)d_in[0];
    const float* Wq   = (const float*)d_in[1];
    const float* Wba  = (const float*)d_in[2];
    const float* cw   = (const float*)d_in[3];
    const float* dtb  = (const float*)d_in[4];
    const float* Alog = (const float*)d_in[5];
    const float* nw   = (const float*)d_in[6];
    const float* Wout = (const float*)d_in[7];
    float* out = (float*)d_out;

    float *qkvz, *convb, *gb, *betab, *Pb, *Lb, *vnb, *kcb, *kfb, *eglb, *coreb;
    __nv_bfloat16 *xh, *xl, *w1h, *w1l, *w2h, *w2l, *hh, *hl;
    cudaGetSymbolAddress((void**)&qkvz,  g_qkvz);
    cudaGetSymbolAddress((void**)&convb, g_conv);
    cudaGetSymbolAddress((void**)&gb,    g_g);
    cudaGetSymbolAddress((void**)&betab, g_beta);
    cudaGetSymbolAddress((void**)&Pb,    g_P);
    cudaGetSymbolAddress((void**)&Lb,    g_L);
    cudaGetSymbolAddress((void**)&vnb,   g_vn);
    cudaGetSymbolAddress((void**)&kcb,   g_kc);
    cudaGetSymbolAddress((void**)&kfb,   g_kf);
    cudaGetSymbolAddress((void**)&eglb,  g_egl);
    cudaGetSymbolAddress((void**)&coreb, g_core);
    cudaGetSymbolAddress((void**)&xh,  g_xh);
    cudaGetSymbolAddress((void**)&xl,  g_xl);
    cudaGetSymbolAddress((void**)&w1h, g_w1h);
    cudaGetSymbolAddress((void**)&w1l, g_w1l);
    cudaGetSymbolAddress((void**)&w2h, g_w2h);
    cudaGetSymbolAddress((void**)&w2l, g_w2l);
    cudaGetSymbolAddress((void**)&hh,  g_hh);
    cudaGetSymbolAddress((void**)&hl,  g_hl);

    cudaFuncSetAttribute(phaseA_kernel, cudaFuncAttributeMaxDynamicSharedMemorySize, PA_SMEM);
    cudaFuncSetAttribute(phaseB_kernel, cudaFuncAttributeMaxDynamicSharedMemorySize, PB_SMEM);
    cudaFuncSetAttribute(bf16gemm128, cudaFuncAttributeMaxDynamicSharedMemorySize, GEMM_SMEM);

    // 0. operand conversion (bandwidth-bound)
    cvt_split_kernel<<<(BB * TT * CC / 4) / 256, 256>>>(x, xh, xl);
    transpose_split_kernel<<<dim3(4096 / 32, CC / 32), 256>>>(Wq, w1h, w1l, CC, 4096);
    transpose_split_kernel<<<dim3(1024 / 32, CC / 32), 256>>>(Wout, w2h, w2l, CC, 1024);

    // 1. qkvz = x @ W_qkvz
    dim3 g1(4096 / 128, 8192 / 128);
    bf16gemm128<<<g1, 256, GEMM_SMEM>>>(BB * TT, 4096, CC, xh, xl, w1h, w1l, qkvz);
    // 2. ba = x @ W_ba fused with g/beta
    ba_gbeta_kernel<<<BB * TT, 256>>>(x, Wba, dtb, Alog, gb, betab);
    // 3. conv + silu
    conv_silu_kernel<<<(BB * TT * 3072) / 256, 256>>>(qkvz, cw, convb);
    // 4. phase A (exports P, L, v_new, k_cum, keff^T)
    phaseA_kernel<<<NCID, 256, PA_SMEM>>>(convb, gb, betab, Pb, Lb, vnb, kcb, kfb, eglb);
    // 5. phase B (two-step S update, double-buffered staging)
    dim3 gB(16, 8);
    phaseB_kernel<<<gB, 256, PB_SMEM>>>(Pb, Lb, kcb, kfb, vnb, eglb, coreb);
    // 6. gated RMSNorm * silu(z) -> bf16 hi/lo
    norm_kernel<<<BB * TT * NH, 128>>>(coreb, qkvz, nw, hh, hl);
    // 7. final projection
    dim3 g2(1024 / 128, 8192 / 128);
    bf16gemm128<<<g2, 256, GEMM_SMEM>>>(BB * TT, 1024, CC, hh, hl, w2h, w2l, out);
}

// round 16
// speedup vs baseline: 1.2843x; 1.0034x over previous
#include <cuda_runtime.h>
#include <cuda_bf16.h>
#include <math.h>

// Problem constants
#define BB 2
#define TT 4096
#define CC 1024
#define NH 8
#define DD 128
#define CHK 64
#define NCHUNK 64            // T / CHK
#define NCID 1024            // BB*NH*NCHUNK

// ---------------- scratch (device globals; no allocation allowed) ----------------
__device__ float g_qkvz[(size_t)BB*TT*4096];     // x @ W_qkvz      (B,T,8,512)
__device__ float g_conv[(size_t)BB*TT*3072];     // conv+silu [q|k|v]
__device__ float g_g[(size_t)BB*TT*NH];
__device__ float g_beta[(size_t)BB*TT*NH];
__device__ float g_P[(size_t)NCID*64*128];       // qeff - attn@k_cum
__device__ float g_L[(size_t)NCID*64*128];       // attn@v_new
__device__ float g_vn[(size_t)NCID*64*128];      // v_new
__device__ float g_kc[(size_t)NCID*64*128];      // k_cum
__device__ float g_kf[(size_t)NCID*128*64];      // keff^T  [a][i]
__device__ float g_egl[NCID];                    // exp(g_last)
__device__ float g_core[(size_t)BB*TT*NH*DD];    // delta-rule output

// bf16 hi/lo split operands for the two big GEMMs
__device__ __nv_bfloat16 g_xh[(size_t)BB*TT*CC],  g_xl[(size_t)BB*TT*CC];
__device__ __nv_bfloat16 g_w1h[(size_t)4096*CC],  g_w1l[(size_t)4096*CC];   // W_qkvz^T [N][K]
__device__ __nv_bfloat16 g_w2h[(size_t)1024*CC],  g_w2l[(size_t)1024*CC];   // W_out^T  [N][K]
__device__ __nv_bfloat16 g_hh[(size_t)BB*TT*1024], g_hl[(size_t)BB*TT*1024];

// ---------------- split/transpose conversion kernels ----------------------------
__global__ __launch_bounds__(256) void cvt_split_kernel(const float* __restrict__ in,
        __nv_bfloat16* __restrict__ oh, __nv_bfloat16* __restrict__ ol)
{
    int i = blockIdx.x * 256 + threadIdx.x;            // indexes float4
    float4 v = ((const float4*)in)[i];
    float f[4] = {v.x, v.y, v.z, v.w};
    __nv_bfloat16 h[4], l[4];
#pragma unroll
    for (int e = 0; e < 4; e++) {
        h[e] = __float2bfloat16_rn(f[e]);
        l[e] = __float2bfloat16_rn(f[e] - __bfloat162float(h[e]));
    }
    __nv_bfloat162 h0; h0.x = h[0]; h0.y = h[1];
    __nv_bfloat162 h1; h1.x = h[2]; h1.y = h[3];
    __nv_bfloat162 l0; l0.x = l[0]; l0.y = l[1];
    __nv_bfloat162 l1; l1.x = l[2]; l1.y = l[3];
    ((__nv_bfloat162*)oh)[i * 2]     = h0;
    ((__nv_bfloat162*)oh)[i * 2 + 1] = h1;
    ((__nv_bfloat162*)ol)[i * 2]     = l0;
    ((__nv_bfloat162*)ol)[i * 2 + 1] = l1;
}

// W [K][N] f32 -> Wt [N][K] bf16 hi/lo
__global__ __launch_bounds__(256) void transpose_split_kernel(const float* __restrict__ W,
        __nv_bfloat16* __restrict__ oh, __nv_bfloat16* __restrict__ ol, int K, int N)
{
    __shared__ float tile[32][33];
    int n0 = blockIdx.x * 32, k0 = blockIdx.y * 32;
    int tx = threadIdx.x & 31, ty0 = threadIdx.x >> 5;
#pragma unroll
    for (int ty = ty0; ty < 32; ty += 8)
        tile[ty][tx] = W[(size_t)(k0 + ty) * N + n0 + tx];
    __syncthreads();
#pragma unroll
    for (int ty = ty0; ty < 32; ty += 8) {
        float v = tile[tx][ty];
        __nv_bfloat16 h = __float2bfloat16_rn(v);
        size_t o = (size_t)(n0 + ty) * K + k0 + tx;
        oh[o] = h;
        ol[o] = __float2bfloat16_rn(v - __bfloat162float(h));
    }
}

// ---------------- asm helpers ----------------------------------------------------
#define MMA_BF16(C, Ar, Br)                                                    \
    asm volatile("mma.sync.aligned.m16n8k16.row.col.f32.bf16.bf16.f32 "        \
        "{%0,%1,%2,%3}, {%4,%5,%6,%7}, {%8,%9}, {%0,%1,%2,%3};"                \
        : "+f"((C)[0]), "+f"((C)[1]), "+f"((C)[2]), "+f"((C)[3])               \
        : "r"((Ar)[0]), "r"((Ar)[1]), "r"((Ar)[2]), "r"((Ar)[3]),              \
          "r"((Br)[0]), "r"((Br)[1]))

#define LDSM4(R0, R1, R2, R3, ADDR)                                            \
    asm volatile("ldmatrix.sync.aligned.m8n8.x4.shared.b16 {%0,%1,%2,%3}, [%4];" \
        : "=r"(R0), "=r"(R1), "=r"(R2), "=r"(R3) : "r"(ADDR))

#define CP_ASYNC16(DST, SRC)                                                   \
    asm volatile("cp.async.cg.shared.global [%0], [%1], 16;" :: "r"(DST), "l"(SRC))
#define CP_COMMIT() asm volatile("cp.async.commit_group;" ::: "memory")
#define CP_WAIT0()  asm volatile("cp.async.wait_group 0;" ::: "memory")
#define CP_WAIT1()  asm volatile("cp.async.wait_group 1;" ::: "memory")

// packed f32x2 helpers (Blackwell FFMA2)
__device__ __forceinline__ unsigned long long pk2(float x, float y) {
    unsigned long long r;
    asm("mov.b64 %0, {%1, %2};" : "=l"(r) : "f"(x), "f"(y));
    return r;
}
__device__ __forceinline__ float2 upk2(unsigned long long v) {
    float2 r;
    asm("mov.b64 {%0, %1}, %2;" : "=f"(r.x), "=f"(r.y) : "l"(v));
    return r;
}
#define FMA2(D, A, B) \
    asm("fma.rn.f32x2 %0, %1, %2, %0;" : "+l"(D) : "l"(A), "l"(B))

// ---------------- 3xBF16-split GEMM: C = A(MxK)@B^T(NxK), pre-split bf16 --------
// R11-proven: ldmatrix + cp.async double-buffer, 128x128 tile, 2 blocks/SM.
#define GKS 40                                   // bf16 k-stride (80B rows, conflict-free)
#define STG_ELEM (4 * 128 * GKS)                 // elements per stage (4 arrays)
#define STG_BYTES (STG_ELEM * 2)                 // 40960 bytes
#define ARR_BYTES (128 * GKS * 2)                // 10240 bytes per array
#define GEMM_SMEM (2 * STG_BYTES)                // 81920 bytes

__global__ __launch_bounds__(256, 2) void bf16gemm128(int M, int N, int K,
        const __nv_bfloat16* __restrict__ Ah_, const __nv_bfloat16* __restrict__ Al_,
        const __nv_bfloat16* __restrict__ Bth_, const __nv_bfloat16* __restrict__ Btl_,
        float* __restrict__ Cm)
{
    extern __shared__ __nv_bfloat16 gsm[];
    unsigned smemBase = (unsigned)__cvta_generic_to_shared(gsm);

    int tid = threadIdx.x;
    int brow = blockIdx.y * 128, bcol = blockIdx.x * 128;
    int warp = tid >> 5, lane = tid & 31;
    int wm = (warp & 1) * 64, wn = (warp >> 1) * 32;
    int lr = lane >> 2, lc2 = (lane & 3) * 2;

    int r0s = tid >> 2, kg0 = (tid & 3) * 8;
    int r1s = (tid + 256) >> 2, kg1 = (tid & 3) * 8;
    unsigned d0 = (unsigned)(r0s * GKS + kg0) * 2;
    unsigned d1 = (unsigned)(r1s * GKS + kg1) * 2;
    const __nv_bfloat16* srcA0h = Ah_  + (size_t)(brow + r0s) * K + kg0;
    const __nv_bfloat16* srcA1h = Ah_  + (size_t)(brow + r1s) * K + kg1;
    const __nv_bfloat16* srcA0l = Al_  + (size_t)(brow + r0s) * K + kg0;
    const __nv_bfloat16* srcA1l = Al_  + (size_t)(brow + r1s) * K + kg1;
    const __nv_bfloat16* srcB0h = Bth_ + (size_t)(bcol + r0s) * K + kg0;
    const __nv_bfloat16* srcB1h = Bth_ + (size_t)(bcol + r1s) * K + kg1;
    const __nv_bfloat16* srcB0l = Btl_ + (size_t)(bcol + r0s) * K + kg0;
    const __nv_bfloat16* srcB1l = Btl_ + (size_t)(bcol + r1s) * K + kg1;

    unsigned aoff = (unsigned)(((wm + (lane & 15)) * GKS) + ((lane >> 4) * 8)) * 2;
    unsigned boff = (unsigned)(((wn + (lane & 7) + (((lane >> 4) & 1) * 8)) * GKS)
                               + (((lane >> 3) & 1) * 8)) * 2;

    float c[4][4][4];
#pragma unroll
    for (int mt = 0; mt < 4; mt++)
#pragma unroll
        for (int nt = 0; nt < 4; nt++)
#pragma unroll
            for (int e = 0; e < 4; e++) c[mt][nt][e] = 0.f;

    {
        unsigned sb = smemBase;
        CP_ASYNC16(sb + d0,                 srcA0h);
        CP_ASYNC16(sb + d1,                 srcA1h);
        CP_ASYNC16(sb + ARR_BYTES + d0,     srcA0l);
        CP_ASYNC16(sb + ARR_BYTES + d1,     srcA1l);
        CP_ASYNC16(sb + 2 * ARR_BYTES + d0, srcB0h);
        CP_ASYNC16(sb + 2 * ARR_BYTES + d1, srcB1h);
        CP_ASYNC16(sb + 3 * ARR_BYTES + d0, srcB0l);
        CP_ASYNC16(sb + 3 * ARR_BYTES + d1, srcB1l);
        CP_COMMIT();
    }

    int buf = 0;
    for (int k0 = 0; k0 < K; k0 += 32) {
        bool hasNext = (k0 + 32) < K;
        if (hasNext) {
            unsigned sb = smemBase + (buf ^ 1) * STG_BYTES;
            int kn = k0 + 32;
            CP_ASYNC16(sb + d0,                 srcA0h + kn);
            CP_ASYNC16(sb + d1,                 srcA1h + kn);
            CP_ASYNC16(sb + ARR_BYTES + d0,     srcA0l + kn);
            CP_ASYNC16(sb + ARR_BYTES + d1,     srcA1l + kn);
            CP_ASYNC16(sb + 2 * ARR_BYTES + d0, srcB0h + kn);
            CP_ASYNC16(sb + 2 * ARR_BYTES + d1, srcB1h + kn);
            CP_ASYNC16(sb + 3 * ARR_BYTES + d0, srcB0l + kn);
            CP_ASYNC16(sb + 3 * ARR_BYTES + d1, srcB1l + kn);
            CP_COMMIT();
            CP_WAIT1();
        } else {
            CP_WAIT0();
        }
        __syncthreads();

        unsigned aBh = smemBase + buf * STG_BYTES;
        unsigned aBl = aBh + ARR_BYTES;
        unsigned bBh = aBh + 2 * ARR_BYTES;
        unsigned bBl = aBh + 3 * ARR_BYTES;

#pragma unroll
        for (int kk = 0; kk < 32; kk += 16) {
            unsigned ah[4][4], al[4][4], bh[2][4], bl[2][4];
#pragma unroll
            for (int mt = 0; mt < 4; mt++) {
                unsigned off = aoff + (unsigned)(mt * 16 * GKS + kk) * 2;
                LDSM4(ah[mt][0], ah[mt][1], ah[mt][2], ah[mt][3], aBh + off);
                LDSM4(al[mt][0], al[mt][1], al[mt][2], al[mt][3], aBl + off);
            }
#pragma unroll
            for (int p = 0; p < 2; p++) {
                unsigned off = boff + (unsigned)(p * 16 * GKS + kk) * 2;
                LDSM4(bh[p][0], bh[p][1], bh[p][2], bh[p][3], bBh + off);
                LDSM4(bl[p][0], bl[p][1], bl[p][2], bl[p][3], bBl + off);
            }
#pragma unroll
            for (int mt = 0; mt < 4; mt++)
#pragma unroll
                for (int nt = 0; nt < 4; nt++)
                    MMA_BF16(c[mt][nt], ah[mt], (&bh[nt >> 1][(nt & 1) * 2]));
#pragma unroll
            for (int mt = 0; mt < 4; mt++)
#pragma unroll
                for (int nt = 0; nt < 4; nt++)
                    MMA_BF16(c[mt][nt], al[mt], (&bh[nt >> 1][(nt & 1) * 2]));
#pragma unroll
            for (int mt = 0; mt < 4; mt++)
#pragma unroll
                for (int nt = 0; nt < 4; nt++)
                    MMA_BF16(c[mt][nt], ah[mt], (&bl[nt >> 1][(nt & 1) * 2]));
        }
        __syncthreads();
        buf ^= 1;
    }

#pragma unroll
    for (int mt = 0; mt < 4; mt++) {
        int r0 = brow + wm + mt * 16 + lr;
#pragma unroll
        for (int nt = 0; nt < 4; nt++) {
            int cn = bcol + wn + nt * 8 + lc2;
            *(float2*)(Cm + (size_t)r0 * N + cn)       = make_float2(c[mt][nt][0], c[mt][nt][1]);
            *(float2*)(Cm + (size_t)(r0 + 8) * N + cn) = make_float2(c[mt][nt][2], c[mt][nt][3]);
        }
    }
}

// ---------------- fused ba = x @ W_ba -> g, beta ---------------------------------
__global__ __launch_bounds__(256) void ba_gbeta_kernel(const float* __restrict__ x,
        const float* __restrict__ Wba, const float* __restrict__ dtb,
        const float* __restrict__ Alog, float* __restrict__ g, float* __restrict__ beta)
{
    int bt = blockIdx.x;
    __shared__ float xs[1024];
    const float* xrow = x + (size_t)bt * 1024;
    for (int i = threadIdx.x; i < 256; i += 256)
        ((float4*)xs)[i] = ((const float4*)xrow)[i];
    __syncthreads();
    int o = threadIdx.x >> 4, p = threadIdx.x & 15;
    float acc = 0.f;
    for (int k = p; k < 1024; k += 16) acc += xs[k] * Wba[(size_t)k * 16 + o];
    acc += __shfl_down_sync(0xffffffffu, acc, 8);
    acc += __shfl_down_sync(0xffffffffu, acc, 4);
    acc += __shfl_down_sync(0xffffffffu, acc, 2);
    acc += __shfl_down_sync(0xffffffffu, acc, 1);
    if (p == 0) {
        int h = o >> 1;
        if ((o & 1) == 0) {
            beta[(size_t)bt * 8 + h] = 1.f / (1.f + expf(-acc));
        } else {
            float xx = acc + dtb[h];
            float sp = (xx > 20.f) ? xx : log1pf(expf(xx));
            g[(size_t)bt * 8 + h] = -expf(Alog[h]) * sp;
        }
    }
}

// ---------------- causal depthwise conv (K=4) + silu ----------------------------
__global__ __launch_bounds__(256) void conv_silu_kernel(const float* __restrict__ qkvz,
        const float* __restrict__ cw, float* __restrict__ out)
{
    int idx = blockIdx.x * 256 + threadIdx.x;
    int ch = idx % 3072;
    int btrow = idx / 3072;
    int t = btrow & (TT - 1);
    int part = ch >> 10;
    int hc = (ch & 1023) >> 7;
    int d = ch & 127;
    int po = (part == 0) ? 0 : (part == 1) ? 128 : 256;
    float acc = 0.f;
#pragma unroll
    for (int j = 0; j < 4; j++) {
        int tt2 = t - 3 + j;
        if (tt2 >= 0) {
            float v = qkvz[(((size_t)(btrow - 3 + j)) * 8 + hc) * 512 + po + d];
            acc += v * cw[ch * 4 + j];
        }
    }
    out[(size_t)idx] = acc / (1.f + __expf(-acc));
}

// ---------------- Phase A: per-chunk local operators (register-tiled) -----------
// Exports P, L, v_new, k_cum, keff^T (no M/U materialization).
#define KST 68
#define ASD 65
#define PA_SMEM ((128*KST*2 + 64*256 + 64*ASD + 256) * 4)

__global__ __launch_bounds__(256) void phaseA_kernel(const float* __restrict__ conv,
        const float* __restrict__ gbuf, const float* __restrict__ betabuf,
        float* __restrict__ Pout, float* __restrict__ Lout,
        float* __restrict__ Vn, float* __restrict__ Kc, float* __restrict__ KfT,
        float* __restrict__ eglout)
{
    extern __shared__ float sm[];
    float* kst = sm;
    float* qst = kst + 128 * KST;
    float* ws  = qst + 128 * KST;
    float* As  = ws + 64 * 256;          // 64 x ASD
    float* gc  = As + 64 * ASD;
    float* egc = gc + 64;
    float* egr = egc + 64;
    float* bts = egr + 64;

    int cid = blockIdx.x;
    int n = cid & 63, bh = cid >> 6, h = bh & 7, b = bh >> 3;
    int tid = threadIdx.x;
    int warp = tid >> 5, lane = tid & 31;
    int t0 = n * 64;

    if (tid < 64) {
        int t = t0 + tid;
        gc[tid]  = gbuf[((size_t)(b * TT + t)) * 8 + h];
        bts[tid] = betabuf[((size_t)(b * TT + t)) * 8 + h];
    }
    __syncthreads();
#pragma unroll
    for (int off = 1; off < 64; off <<= 1) {
        float v = 0.f;
        if (tid < 64 && tid >= off) v = gc[tid - off];
        __syncthreads();
        if (tid < 64 && tid >= off) gc[tid] += v;
        __syncthreads();
    }
    if (tid < 64) {
        egc[tid] = __expf(gc[tid]);
        egr[tid] = __expf(gc[63] - gc[tid]);
    }
    __syncthreads();

    for (int r = warp; r < 64; r += 8) {
        int t = t0 + r;
        const float* base = conv + ((size_t)(b * TT + t)) * 3072 + h * 128;
        float qv[4], kv[4];
        float ssq = 0.f, ssk = 0.f;
#pragma unroll
        for (int u = 0; u < 4; u++) {
            qv[u] = base[lane + u * 32];
            kv[u] = base[1024 + lane + u * 32];
            ssq += qv[u] * qv[u];
            ssk += kv[u] * kv[u];
        }
#pragma unroll
        for (int off = 16; off; off >>= 1) {
            ssq += __shfl_xor_sync(0xffffffffu, ssq, off);
            ssk += __shfl_xor_sync(0xffffffffu, ssk, off);
        }
        float rq = rsqrtf(ssq + 1e-6f) * 0.08838834764831845f;
        float rk = rsqrtf(ssk + 1e-6f);
        float bbv = bts[r], egv = egc[r];
#pragma unroll
        for (int u = 0; u < 4; u++) {
            int d = lane + u * 32;
            qst[d * KST + r] = qv[u] * rq;
            float kn = kv[u] * rk;
            kst[d * KST + r] = kn;
            ws[r * 256 + d]       = base[2048 + d] * bbv;
            ws[r * 256 + 128 + d] = kn * bbv * egv;
        }
    }
    __syncthreads();

    int ti = tid >> 4, tj = tid & 15;

    // A[i][j] = beta_i (k_i . k_j) exp(gc_i - gc_j), j < i; else 0
    {
        float acc[4][4];
#pragma unroll
        for (int r = 0; r < 4; r++)
#pragma unroll
            for (int s = 0; s < 4; s++) acc[r][s] = 0.f;
        const float* ka = kst + ti * 4;
        const float* kb = kst + tj * 4;
#pragma unroll 4
        for (int d = 0; d < 128; d++) {
            float4 a = *(const float4*)(ka + d * KST);
            float4 bq = *(const float4*)(kb + d * KST);
            float ra[4] = {a.x, a.y, a.z, a.w};
            float rb[4] = {bq.x, bq.y, bq.z, bq.w};
#pragma unroll
            for (int r = 0; r < 4; r++)
#pragma unroll
                for (int s = 0; s < 4; s++) acc[r][s] += ra[r] * rb[s];
        }
#pragma unroll
        for (int r = 0; r < 4; r++) {
            int i = ti * 4 + r;
#pragma unroll
            for (int s = 0; s < 4; s++) {
                int j = tj * 4 + s;
                As[i * ASD + j] = (j < i) ? acc[r][s] * bts[i] * __expf(gc[i] - gc[j]) : 0.f;
            }
        }
    }
    __syncthreads();

    // blocked forward substitution: ws <- (I+A)^{-1} ws
    for (int blk = 0; blk < 4; blk++) {
        if (blk) {
            int tr = tid >> 7, tc = tid & 127;
            float acc[8][2];
#pragma unroll
            for (int r = 0; r < 8; r++) { acc[r][0] = 0.f; acc[r][1] = 0.f; }
            for (int j = 0; j < blk * 16; j++) {
                float2 wv = *(const float2*)(ws + j * 256 + tc * 2);
#pragma unroll
                for (int r = 0; r < 8; r++) {
                    float a = As[(blk * 16 + tr * 8 + r) * ASD + j];
                    acc[r][0] += a * wv.x;
                    acc[r][1] += a * wv.y;
                }
            }
#pragma unroll
            for (int r = 0; r < 8; r++) {
                float* w = ws + (blk * 16 + tr * 8 + r) * 256 + tc * 2;
                w[0] -= acc[r][0];
                w[1] -= acc[r][1];
            }
            __syncthreads();
        }
        {
            int c = tid;
            int i0 = blk * 16;
            for (int i = i0 + 1; i < i0 + 16; i++) {
                float acc = 0.f;
                for (int j = i0; j < i; j++) acc += As[i * ASD + j] * ws[j * 256 + c];
                ws[i * 256 + c] -= acc;
            }
        }
        __syncthreads();
    }

    // attn[i][j] = (q_i . k_j) exp(gc_i - gc_j), j <= i; else 0 (overwrite As)
    {
        float acc[4][4];
#pragma unroll
        for (int r = 0; r < 4; r++)
#pragma unroll
            for (int s = 0; s < 4; s++) acc[r][s] = 0.f;
        const float* qa = qst + ti * 4;
        const float* kb = kst + tj * 4;
#pragma unroll 4
        for (int d = 0; d < 128; d++) {
            float4 a = *(const float4*)(qa + d * KST);
            float4 bq = *(const float4*)(kb + d * KST);
            float ra[4] = {a.x, a.y, a.z, a.w};
            float rb[4] = {bq.x, bq.y, bq.z, bq.w};
#pragma unroll
            for (int r = 0; r < 4; r++)
#pragma unroll
                for (int s = 0; s < 4; s++) acc[r][s] += ra[r] * rb[s];
        }
#pragma unroll
        for (int r = 0; r < 4; r++) {
            int i = ti * 4 + r;
#pragma unroll
            for (int s = 0; s < 4; s++) {
                int j = tj * 4 + s;
                As[i * ASD + j] = (j <= i) ? acc[r][s] * __expf(gc[i] - gc[j]) : 0.f;
            }
        }
    }
    __syncthreads();

    // [L | attn@k_cum] = attn @ ws ;  P = q*e^gc - attn@k_cum
    {
        int tr = warp;
        int tc = lane;
        float acc[8][8];
#pragma unroll
        for (int r = 0; r < 8; r++)
#pragma unroll
            for (int u = 0; u < 8; u++) acc[r][u] = 0.f;
        int jmax = tr * 8 + 8;
        for (int j = 0; j < jmax; j++) {
            float av[8];
#pragma unroll
            for (int r = 0; r < 8; r++) av[r] = As[(tr * 8 + r) * ASD + j];
            float4 w0 = *(const float4*)(ws + j * 256 + tc * 8);
            float4 w1 = *(const float4*)(ws + j * 256 + tc * 8 + 4);
            float rb[8] = {w0.x, w0.y, w0.z, w0.w, w1.x, w1.y, w1.z, w1.w};
#pragma unroll
            for (int r = 0; r < 8; r++)
#pragma unroll
                for (int u = 0; u < 8; u++) acc[r][u] += av[r] * rb[u];
        }
        if (tc < 16) {
#pragma unroll
            for (int r = 0; r < 8; r++) {
                int i = tr * 8 + r;
                float* dst = Lout + ((size_t)cid * 64 + i) * 128 + tc * 8;
                *(float4*)(dst)     = make_float4(acc[r][0], acc[r][1], acc[r][2], acc[r][3]);
                *(float4*)(dst + 4) = make_float4(acc[r][4], acc[r][5], acc[r][6], acc[r][7]);
            }
        } else {
            int c0 = tc * 8 - 128;
#pragma unroll
            for (int r = 0; r < 8; r++) {
                int i = tr * 8 + r;
                float eg = egc[i];
                float v[8];
#pragma unroll
                for (int u = 0; u < 8; u++)
                    v[u] = qst[(c0 + u) * KST + i] * eg - acc[r][u];
                float* dst = Pout + ((size_t)cid * 64 + i) * 128 + c0;
                *(float4*)(dst)     = make_float4(v[0], v[1], v[2], v[3]);
                *(float4*)(dst + 4) = make_float4(v[4], v[5], v[6], v[7]);
            }
        }
    }

    // export v_new, k_cum ([i][d], coalesced) and keff^T ([a][i])
    for (int idx = tid; idx < 2048; idx += 256) {
        int row = idx >> 5, col = (idx & 31) * 4;
        *(float4*)(Vn + (size_t)cid * 8192 + row * 128 + col) =
            *(const float4*)(ws + row * 256 + col);
        *(float4*)(Kc + (size_t)cid * 8192 + row * 128 + col) =
            *(const float4*)(ws + row * 256 + 128 + col);
    }
    for (int idx = tid; idx < 2048; idx += 256) {
        int a = idx >> 4, ig = (idx & 15) * 4;
        float4 v;
        v.x = kst[a * KST + ig]     * egr[ig];
        v.y = kst[a * KST + ig + 1] * egr[ig + 1];
        v.z = kst[a * KST + ig + 2] * egr[ig + 2];
        v.w = kst[a * KST + ig + 3] * egr[ig + 3];
        *(float4*)(KfT + (size_t)cid * 8192 + a * 64 + ig) = v;
    }
    if (tid == 0) eglout[cid] = __expf(gc[63]);
}

// ---------------- Phase B: sequential scan, cp.async double-buffered ------------
// tmp = v_new - k_cum@S ; out = L + P@S ; S' = egl*S + keff^T@tmp
// Inner loops use packed fma.rn.f32x2 (FFMA2): bit-identical fp32 math, half the
// FMA-pipe instructions.
#define PSD 132
#define KFD 68
#define PB_BUF (64*PSD + 64*PSD + 128*KFD)       // floats per stage buffer = 25600
#define PB_SMEM ((2*PB_BUF + 64*16 + 128*16) * 4)  // 217088 bytes

__global__ __launch_bounds__(256) void phaseB_kernel(const float* __restrict__ Pm,
        const float* __restrict__ Lm, const float* __restrict__ Kcm,
        const float* __restrict__ KfTm, const float* __restrict__ Vnm,
        const float* __restrict__ eglv, float* __restrict__ core)
{
    extern __shared__ float sm[];
    float* Tm = sm + 2 * PB_BUF;     // 64 x 16
    float* Ss = Tm + 64 * 16;        // 128 x 16
    unsigned smemBase = (unsigned)__cvta_generic_to_shared(sm);

    int bh = blockIdx.x, gg = blockIdx.y;
    int b = bh >> 3, h = bh & 7;
    int tid = threadIdx.x;
    int c4g = tid & 3;
    int i0 = tid >> 2;               // 0..63
    int c0 = gg * 16;

    // per-thread staging offsets (8 chunks of 16B per array)
    int srow = tid >> 5, scol = (tid & 31) * 4;  // P/Kc pattern base (advance row by 8)
    int sa = tid >> 4, sig = (tid & 15) * 4;     // Kft pattern base (advance a by 16)

    for (int i = tid; i < 128 * 16; i += 256) Ss[i] = 0.f;
    __syncthreads();

    // stage one chunk's P/Kc/Kft into buffer bf
    auto stage = [&](int n, int bf) {
        size_t cid = (size_t)bh * 64 + n;
        const float* Pg = Pm + cid * 8192;
        const float* Kg = Kcm + cid * 8192;
        const float* Fg = KfTm + cid * 8192;
        unsigned base = smemBase + (unsigned)(bf * PB_BUF) * 4;
        unsigned kcB = base + (unsigned)(64 * PSD) * 4;
        unsigned kfB = kcB + (unsigned)(64 * PSD) * 4;
#pragma unroll
        for (int u = 0; u < 8; u++) {
            int row = srow + u * 8;
            unsigned off = (unsigned)(row * PSD + scol) * 4;
            CP_ASYNC16(base + off, Pg + row * 128 + scol);
            CP_ASYNC16(kcB + off, Kg + row * 128 + scol);
            int a = sa + u * 16;
            CP_ASYNC16(kfB + (unsigned)(a * KFD + sig) * 4, Fg + a * 64 + sig);
        }
        CP_COMMIT();
    };

    stage(0, 0);

    int buf = 0;
    for (int n = 0; n < 64; n++) {
        size_t cid = (size_t)bh * 64 + n;
        // prefetch L/Vn for this chunk (LDG latency overlaps cp.async wait)
        float4 accO = *(const float4*)(Lm + cid * 8192 + i0 * 128 + c0 + c4g * 4);
        float4 accT = *(const float4*)(Vnm + cid * 8192 + i0 * 128 + c0 + c4g * 4);
        float eg = eglv[cid];

        if (n + 1 < 64) { stage(n + 1, buf ^ 1); CP_WAIT1(); }
        else           { CP_WAIT0(); }
        __syncthreads();

        const float* Ps  = sm + buf * PB_BUF;
        const float* Kcs = Ps + 64 * PSD;
        const float* Kft = Kcs + 64 * PSD;

        // step 1+2: out[i][c] = L + P@S ; tmp[i][c] = vn - kc@S  (i = i0)
        {
            unsigned long long o01 = pk2(accO.x, accO.y), o23 = pk2(accO.z, accO.w);
            unsigned long long t01 = pk2(accT.x, accT.y), t23 = pk2(accT.z, accT.w);
            for (int a = 0; a < 128; a++) {
                float p  = Ps[i0 * PSD + a];
                float nk = -Kcs[i0 * PSD + a];
                ulonglong2 s2 = *(const ulonglong2*)(Ss + a * 16 + c4g * 4);
                unsigned long long p2 = pk2(p, p);
                unsigned long long k2 = pk2(nk, nk);
                FMA2(o01, p2, s2.x); FMA2(o23, p2, s2.y);
                FMA2(t01, k2, s2.x); FMA2(t23, k2, s2.y);
            }
            float2 oa = upk2(o01), ob = upk2(o23);
            float2 ta = upk2(t01), tb = upk2(t23);
            int t = n * 64 + i0;
            *(float4*)(core + (((size_t)(b * TT + t)) * 8 + h) * 128 + c0 + c4g * 4) =
                make_float4(oa.x, oa.y, ob.x, ob.y);
            *(float4*)(Tm + i0 * 16 + c4g * 4) = make_float4(ta.x, ta.y, tb.x, tb.y);
        }
        __syncthreads();

        // step 3: S'[a][c] = egl*S[a][c] + sum_i Kft[a][i]*tmp[i][c]  (a = i0, i0+64)
        float4 s0 = *(const float4*)(Ss + i0 * 16 + c4g * 4);
        float4 s1 = *(const float4*)(Ss + (i0 + 64) * 16 + c4g * 4);
        {
            unsigned long long n0a = pk2(eg * s0.x, eg * s0.y);
            unsigned long long n0b = pk2(eg * s0.z, eg * s0.w);
            unsigned long long n1a = pk2(eg * s1.x, eg * s1.y);
            unsigned long long n1b = pk2(eg * s1.z, eg * s1.w);
            for (int i = 0; i < 64; i++) {
                ulonglong2 t2 = *(const ulonglong2*)(Tm + i * 16 + c4g * 4);
                float f0 = Kft[i0 * KFD + i];
                float f1 = Kft[(i0 + 64) * KFD + i];
                unsigned long long f02 = pk2(f0, f0);
                unsigned long long f12 = pk2(f1, f1);
                FMA2(n0a, f02, t2.x); FMA2(n0b, f02, t2.y);
                FMA2(n1a, f12, t2.x); FMA2(n1b, f12, t2.y);
            }
            float2 ua = upk2(n0a), ub = upk2(n0b);
            float2 va = upk2(n1a), vb = upk2(n1b);
            *(float4*)(Ss + i0 * 16 + c4g * 4) = make_float4(ua.x, ua.y, ub.x, ub.y);
            *(float4*)(Ss + (i0 + 64) * 16 + c4g * 4) = make_float4(va.x, va.y, vb.x, vb.y);
        }
        __syncthreads();
        buf ^= 1;
    }
}

// ---------------- gated RMSNorm * silu(z) -> bf16 hi/lo --------------------------
__global__ __launch_bounds__(128) void norm_kernel(const float* __restrict__ core,
        const float* __restrict__ qkvz, const float* __restrict__ nw,
        __nv_bfloat16* __restrict__ hh, __nv_bfloat16* __restrict__ hl)
{
    int bth = blockIdx.x;
    int d = threadIdx.x;
    float cv = core[(size_t)bth * 128 + d];
    float ss = cv * cv;
#pragma unroll
    for (int o = 16; o; o >>= 1) ss += __shfl_xor_sync(0xffffffffu, ss, o);
    __shared__ float red[4];
    if ((d & 31) == 0) red[d >> 5] = ss;
    __syncthreads();
    float tot = red[0] + red[1] + red[2] + red[3];
    float r = rsqrtf(tot * (1.f / 128.f) + 1e-6f);
    float zz = qkvz[(size_t)bth * 512 + 384 + d];
    float sz = zz / (1.f + __expf(-zz));
    float hv = nw[d] * cv * r * sz;
    __nv_bfloat16 h = __float2bfloat16_rn(hv);
    size_t o = (size_t)bth * 128 + d;
    hh[o] = h;
    hl[o] = __float2bfloat16_rn(hv - __bfloat162float(h));
}

// ---------------- launch ---------------------------------------------------------
extern "C" void kernel_launch(void* const* d_in, const int* in_sizes, int n_in,
                              void* d_out, int out_size)
{
    (void)in_sizes; (void)n_in; (void)out_size;
    const float* x    = (const float*)d_in[0];
    const float* Wq   = (const float*)d_in[1];
    const float* Wba  = (const float*)d_in[2];
    const float* cw   = (const float*)d_in[3];
    const float* dtb  = (const float*)d_in[4];
    const float* Alog = (const float*)d_in[5];
    const float* nw   = (const float*)d_in[6];
    const float* Wout = (const float*)d_in[7];
    float* out = (float*)d_out;

    float *qkvz, *convb, *gb, *betab, *Pb, *Lb, *vnb, *kcb, *kfb, *eglb, *coreb;
    __nv_bfloat16 *xh, *xl, *w1h, *w1l, *w2h, *w2l, *hh, *hl;
    cudaGetSymbolAddress((void**)&qkvz,  g_qkvz);
    cudaGetSymbolAddress((void**)&convb, g_conv);
    cudaGetSymbolAddress((void**)&gb,    g_g);
    cudaGetSymbolAddress((void**)&betab, g_beta);
    cudaGetSymbolAddress((void**)&Pb,    g_P);
    cudaGetSymbolAddress((void**)&Lb,    g_L);
    cudaGetSymbolAddress((void**)&vnb,   g_vn);
    cudaGetSymbolAddress((void**)&kcb,   g_kc);
    cudaGetSymbolAddress((void**)&kfb,   g_kf);
    cudaGetSymbolAddress((void**)&eglb,  g_egl);
    cudaGetSymbolAddress((void**)&coreb, g_core);
    cudaGetSymbolAddress((void**)&xh,  g_xh);
    cudaGetSymbolAddress((void**)&xl,  g_xl);
    cudaGetSymbolAddress((void**)&w1h, g_w1h);
    cudaGetSymbolAddress((void**)&w1l, g_w1l);
    cudaGetSymbolAddress((void**)&w2h, g_w2h);
    cudaGetSymbolAddress((void**)&w2l, g_w2l);
    cudaGetSymbolAddress((void**)&hh,  g_hh);
    cudaGetSymbolAddress((void**)&hl,  g_hl);

    cudaFuncSetAttribute(phaseA_kernel, cudaFuncAttributeMaxDynamicSharedMemorySize, PA_SMEM);
    cudaFuncSetAttribute(phaseB_kernel, cudaFuncAttributeMaxDynamicSharedMemorySize, PB_SMEM);
    cudaFuncSetAttribute(bf16gemm128, cudaFuncAttributeMaxDynamicSharedMemorySize, GEMM_SMEM);

    // 0. operand conversion (bandwidth-bound)
    cvt_split_kernel<<<(BB * TT * CC / 4) / 256, 256>>>(x, xh, xl);
    transpose_split_kernel<<<dim3(4096 / 32, CC / 32), 256>>>(Wq, w1h, w1l, CC, 4096);
    transpose_split_kernel<<<dim3(1024 / 32, CC / 32), 256>>>(Wout, w2h, w2l, CC, 1024);

    // 1. qkvz = x @ W_qkvz
    dim3 g1(4096 / 128, 8192 / 128);
    bf16gemm128<<<g1, 256, GEMM_SMEM>>>(BB * TT, 4096, CC, xh, xl, w1h, w1l, qkvz);
    // 2. ba = x @ W_ba fused with g/beta
    ba_gbeta_kernel<<<BB * TT, 256>>>(x, Wba, dtb, Alog, gb, betab);
    // 3. conv + silu
    conv_silu_kernel<<<(BB * TT * 3072) / 256, 256>>>(qkvz, cw, convb);
    // 4. phase A (exports P, L, v_new, k_cum, keff^T)
    phaseA_kernel<<<NCID, 256, PA_SMEM>>>(convb, gb, betab, Pb, Lb, vnb, kcb, kfb, eglb);
    // 5. phase B (two-step S update, double-buffered staging, FFMA2 inner loops)
    dim3 gB(16, 8);
    phaseB_kernel<<<gB, 256, PB_SMEM>>>(Pb, Lb, kcb, kfb, vnb, eglb, coreb);
    // 6. gated RMSNorm * silu(z) -> bf16 hi/lo
    norm_kernel<<<BB * TT * NH, 128>>>(coreb, qkvz, nw, hh, hl);
    // 7. final projection
    dim3 g2(1024 / 128, 8192 / 128);
    bf16gemm128<<<g2, 256, GEMM_SMEM>>>(BB * TT, 1024, CC, hh, hl, w2h, w2l, out);
}

// round 17
// speedup vs baseline: 1.4638x; 1.1398x over previous
#include <cuda_runtime.h>
#include <cuda_fp16.h>
#include <math.h>

// Problem constants
#define BB 2
#define TT 4096
#define CC 1024
#define NH 8
#define DD 128
#define CHK 64
#define NCHUNK 64            // T / CHK
#define NCID 1024            // BB*NH*NCHUNK

// ---------------- scratch (device globals; no allocation allowed) ----------------
__device__ float g_qkvz[(size_t)BB*TT*4096];     // x @ W_qkvz      (B,T,8,512)
__device__ float g_conv[(size_t)BB*TT*3072];     // conv+silu [q|k|v]
__device__ float g_g[(size_t)BB*TT*NH];
__device__ float g_beta[(size_t)BB*TT*NH];
__device__ float g_P[(size_t)NCID*64*128];       // qeff - attn@k_cum
__device__ float g_L[(size_t)NCID*64*128];       // attn@v_new
__device__ float g_vn[(size_t)NCID*64*128];      // v_new
__device__ float g_kc[(size_t)NCID*64*128];      // NEGATED k_cum
__device__ float g_kf[(size_t)NCID*128*64];      // keff^T  [a][i]
__device__ float g_egl[NCID];                    // exp(g_last)
__device__ float g_core[(size_t)BB*TT*NH*DD];    // delta-rule output

// f16 split operands for the two big GEMMs (A: hi+lo, B: hi only)
__device__ __half g_xh[(size_t)BB*TT*CC],  g_xl[(size_t)BB*TT*CC];
__device__ __half g_w1h[(size_t)4096*CC];        // W_qkvz^T [N][K] hi
__device__ __half g_w2h[(size_t)1024*CC];        // W_out^T  [N][K] hi
__device__ __half g_hh[(size_t)BB*TT*1024], g_hl[(size_t)BB*TT*1024];

// ---------------- split/transpose conversion kernels ----------------------------
__global__ __launch_bounds__(256) void cvt_split_kernel(const float* __restrict__ in,
        __half* __restrict__ oh, __half* __restrict__ ol)
{
    int i = blockIdx.x * 256 + threadIdx.x;            // indexes float4
    float4 v = ((const float4*)in)[i];
    float f[4] = {v.x, v.y, v.z, v.w};
    __half h[4], l[4];
#pragma unroll
    for (int e = 0; e < 4; e++) {
        h[e] = __float2half_rn(f[e]);
        l[e] = __float2half_rn(f[e] - __half2float(h[e]));
    }
    __half2 h0; h0.x = h[0]; h0.y = h[1];
    __half2 h1; h1.x = h[2]; h1.y = h[3];
    __half2 l0; l0.x = l[0]; l0.y = l[1];
    __half2 l1; l1.x = l[2]; l1.y = l[3];
    ((__half2*)oh)[i * 2]     = h0;
    ((__half2*)oh)[i * 2 + 1] = h1;
    ((__half2*)ol)[i * 2]     = l0;
    ((__half2*)ol)[i * 2 + 1] = l1;
}

// W [K][N] f32 -> Wt [N][K] f16 hi
__global__ __launch_bounds__(256) void transpose_h_kernel(const float* __restrict__ W,
        __half* __restrict__ oh, int K, int N)
{
    __shared__ float tile[32][33];
    int n0 = blockIdx.x * 32, k0 = blockIdx.y * 32;
    int tx = threadIdx.x & 31, ty0 = threadIdx.x >> 5;
#pragma unroll
    for (int ty = ty0; ty < 32; ty += 8)
        tile[ty][tx] = W[(size_t)(k0 + ty) * N + n0 + tx];
    __syncthreads();
#pragma unroll
    for (int ty = ty0; ty < 32; ty += 8)
        oh[(size_t)(n0 + ty) * K + k0 + tx] = __float2half_rn(tile[tx][ty]);
}

// ---------------- asm helpers ----------------------------------------------------
#define MMA_F16(C, Ar, Br)                                                     \
    asm volatile("mma.sync.aligned.m16n8k16.row.col.f32.f16.f16.f32 "          \
        "{%0,%1,%2,%3}, {%4,%5,%6,%7}, {%8,%9}, {%0,%1,%2,%3};"                \
        : "+f"((C)[0]), "+f"((C)[1]), "+f"((C)[2]), "+f"((C)[3])               \
        : "r"((Ar)[0]), "r"((Ar)[1]), "r"((Ar)[2]), "r"((Ar)[3]),              \
          "r"((Br)[0]), "r"((Br)[1]))

#define LDSM4(R0, R1, R2, R3, ADDR)                                            \
    asm volatile("ldmatrix.sync.aligned.m8n8.x4.shared.b16 {%0,%1,%2,%3}, [%4];" \
        : "=r"(R0), "=r"(R1), "=r"(R2), "=r"(R3) : "r"(ADDR))

#define CP_ASYNC16(DST, SRC)                                                   \
    asm volatile("cp.async.cg.shared.global [%0], [%1], 16;" :: "r"(DST), "l"(SRC))
#define CP_COMMIT() asm volatile("cp.async.commit_group;" ::: "memory")
#define CP_WAIT0()  asm volatile("cp.async.wait_group 0;" ::: "memory")
#define CP_WAIT1()  asm volatile("cp.async.wait_group 1;" ::: "memory")

// packed f32x2 helpers (Blackwell FFMA2)
__device__ __forceinline__ unsigned long long pk2(float x, float y) {
    unsigned long long r;
    asm("mov.b64 %0, {%1, %2};" : "=l"(r) : "f"(x), "f"(y));
    return r;
}
__device__ __forceinline__ float2 upk2(unsigned long long v) {
    float2 r;
    asm("mov.b64 {%0, %1}, %2;" : "=f"(r.x), "=f"(r.y) : "l"(v));
    return r;
}
#define FMA2(D, A, B) \
    asm("fma.rn.f32x2 %0, %1, %2, %0;" : "+l"(D) : "l"(A), "l"(B))

// ---------------- 2xF16-split GEMM: C = A(MxK)@B^T(NxK) -------------------------
// C = Ah*Bh + Al*Bh (dropped A*Bl ~2^-12 rel). ldmatrix + cp.async double-buffer,
// 128x128 tile, 2 blocks/SM.
#define GKS 40                                   // f16 k-stride (80B rows, conflict-free)
#define ARR_BYTES (128 * GKS * 2)                // 10240 bytes per array
#define STG_BYTES (3 * ARR_BYTES)                // 30720 bytes (Ah, Al, Bh)
#define GEMM_SMEM (2 * STG_BYTES)                // 61440 bytes

__global__ __launch_bounds__(256, 2) void f16gemm128(int M, int N, int K,
        const __half* __restrict__ Ah_, const __half* __restrict__ Al_,
        const __half* __restrict__ Bth_, float* __restrict__ Cm)
{
    extern __shared__ __half gsm[];
    unsigned smemBase = (unsigned)__cvta_generic_to_shared(gsm);

    int tid = threadIdx.x;
    int brow = blockIdx.y * 128, bcol = blockIdx.x * 128;
    int warp = tid >> 5, lane = tid & 31;
    int wm = (warp & 1) * 64, wn = (warp >> 1) * 32;
    int lr = lane >> 2, lc2 = (lane & 3) * 2;

    int r0s = tid >> 2, kg0 = (tid & 3) * 8;
    int r1s = (tid + 256) >> 2, kg1 = (tid & 3) * 8;
    unsigned d0 = (unsigned)(r0s * GKS + kg0) * 2;
    unsigned d1 = (unsigned)(r1s * GKS + kg1) * 2;
    const __half* srcA0h = Ah_  + (size_t)(brow + r0s) * K + kg0;
    const __half* srcA1h = Ah_  + (size_t)(brow + r1s) * K + kg1;
    const __half* srcA0l = Al_  + (size_t)(brow + r0s) * K + kg0;
    const __half* srcA1l = Al_  + (size_t)(brow + r1s) * K + kg1;
    const __half* srcB0h = Bth_ + (size_t)(bcol + r0s) * K + kg0;
    const __half* srcB1h = Bth_ + (size_t)(bcol + r1s) * K + kg1;

    unsigned aoff = (unsigned)(((wm + (lane & 15)) * GKS) + ((lane >> 4) * 8)) * 2;
    unsigned boff = (unsigned)(((wn + (lane & 7) + (((lane >> 4) & 1) * 8)) * GKS)
                               + (((lane >> 3) & 1) * 8)) * 2;

    float c[4][4][4];
#pragma unroll
    for (int mt = 0; mt < 4; mt++)
#pragma unroll
        for (int nt = 0; nt < 4; nt++)
#pragma unroll
            for (int e = 0; e < 4; e++) c[mt][nt][e] = 0.f;

    {
        unsigned sb = smemBase;
        CP_ASYNC16(sb + d0,                 srcA0h);
        CP_ASYNC16(sb + d1,                 srcA1h);
        CP_ASYNC16(sb + ARR_BYTES + d0,     srcA0l);
        CP_ASYNC16(sb + ARR_BYTES + d1,     srcA1l);
        CP_ASYNC16(sb + 2 * ARR_BYTES + d0, srcB0h);
        CP_ASYNC16(sb + 2 * ARR_BYTES + d1, srcB1h);
        CP_COMMIT();
    }

    int buf = 0;
    for (int k0 = 0; k0 < K; k0 += 32) {
        bool hasNext = (k0 + 32) < K;
        if (hasNext) {
            unsigned sb = smemBase + (buf ^ 1) * STG_BYTES;
            int kn = k0 + 32;
            CP_ASYNC16(sb + d0,                 srcA0h + kn);
            CP_ASYNC16(sb + d1,                 srcA1h + kn);
            CP_ASYNC16(sb + ARR_BYTES + d0,     srcA0l + kn);
            CP_ASYNC16(sb + ARR_BYTES + d1,     srcA1l + kn);
            CP_ASYNC16(sb + 2 * ARR_BYTES + d0, srcB0h + kn);
            CP_ASYNC16(sb + 2 * ARR_BYTES + d1, srcB1h + kn);
            CP_COMMIT();
            CP_WAIT1();
        } else {
            CP_WAIT0();
        }
        __syncthreads();

        unsigned aBh = smemBase + buf * STG_BYTES;
        unsigned aBl = aBh + ARR_BYTES;
        unsigned bBh = aBh + 2 * ARR_BYTES;

#pragma unroll
        for (int kk = 0; kk < 32; kk += 16) {
            unsigned ah[4][4], al[4][4], bh[2][4];
#pragma unroll
            for (int mt = 0; mt < 4; mt++) {
                unsigned off = aoff + (unsigned)(mt * 16 * GKS + kk) * 2;
                LDSM4(ah[mt][0], ah[mt][1], ah[mt][2], ah[mt][3], aBh + off);
                LDSM4(al[mt][0], al[mt][1], al[mt][2], al[mt][3], aBl + off);
            }
#pragma unroll
            for (int p = 0; p < 2; p++) {
                unsigned off = boff + (unsigned)(p * 16 * GKS + kk) * 2;
                LDSM4(bh[p][0], bh[p][1], bh[p][2], bh[p][3], bBh + off);
            }
#pragma unroll
            for (int mt = 0; mt < 4; mt++)
#pragma unroll
                for (int nt = 0; nt < 4; nt++)
                    MMA_F16(c[mt][nt], ah[mt], (&bh[nt >> 1][(nt & 1) * 2]));
#pragma unroll
            for (int mt = 0; mt < 4; mt++)
#pragma unroll
                for (int nt = 0; nt < 4; nt++)
                    MMA_F16(c[mt][nt], al[mt], (&bh[nt >> 1][(nt & 1) * 2]));
        }
        __syncthreads();
        buf ^= 1;
    }

#pragma unroll
    for (int mt = 0; mt < 4; mt++) {
        int r0 = brow + wm + mt * 16 + lr;
#pragma unroll
        for (int nt = 0; nt < 4; nt++) {
            int cn = bcol + wn + nt * 8 + lc2;
            *(float2*)(Cm + (size_t)r0 * N + cn)       = make_float2(c[mt][nt][0], c[mt][nt][1]);
            *(float2*)(Cm + (size_t)(r0 + 8) * N + cn) = make_float2(c[mt][nt][2], c[mt][nt][3]);
        }
    }
}

// ---------------- fused ba = x @ W_ba -> g, beta ---------------------------------
__global__ __launch_bounds__(256) void ba_gbeta_kernel(const float* __restrict__ x,
        const float* __restrict__ Wba, const float* __restrict__ dtb,
        const float* __restrict__ Alog, float* __restrict__ g, float* __restrict__ beta)
{
    int bt = blockIdx.x;
    __shared__ float xs[1024];
    const float* xrow = x + (size_t)bt * 1024;
    for (int i = threadIdx.x; i < 256; i += 256)
        ((float4*)xs)[i] = ((const float4*)xrow)[i];
    __syncthreads();
    int o = threadIdx.x >> 4, p = threadIdx.x & 15;
    float acc = 0.f;
    for (int k = p; k < 1024; k += 16) acc += xs[k] * Wba[(size_t)k * 16 + o];
    acc += __shfl_down_sync(0xffffffffu, acc, 8);
    acc += __shfl_down_sync(0xffffffffu, acc, 4);
    acc += __shfl_down_sync(0xffffffffu, acc, 2);
    acc += __shfl_down_sync(0xffffffffu, acc, 1);
    if (p == 0) {
        int h = o >> 1;
        if ((o & 1) == 0) {
            beta[(size_t)bt * 8 + h] = 1.f / (1.f + expf(-acc));
        } else {
            float xx = acc + dtb[h];
            float sp = (xx > 20.f) ? xx : log1pf(expf(xx));
            g[(size_t)bt * 8 + h] = -expf(Alog[h]) * sp;
        }
    }
}

// ---------------- causal depthwise conv (K=4) + silu ----------------------------
__global__ __launch_bounds__(256) void conv_silu_kernel(const float* __restrict__ qkvz,
        const float* __restrict__ cw, float* __restrict__ out)
{
    int idx = blockIdx.x * 256 + threadIdx.x;
    int ch = idx % 3072;
    int btrow = idx / 3072;
    int t = btrow & (TT - 1);
    int part = ch >> 10;
    int hc = (ch & 1023) >> 7;
    int d = ch & 127;
    int po = (part == 0) ? 0 : (part == 1) ? 128 : 256;
    float acc = 0.f;
#pragma unroll
    for (int j = 0; j < 4; j++) {
        int tt2 = t - 3 + j;
        if (tt2 >= 0) {
            float v = qkvz[(((size_t)(btrow - 3 + j)) * 8 + hc) * 512 + po + d];
            acc += v * cw[ch * 4 + j];
        }
    }
    out[(size_t)idx] = acc / (1.f + __expf(-acc));
}

// ---------------- Phase A: per-chunk local operators (register-tiled) -----------
// Exports P, L, v_new, NEGATED k_cum, keff^T.
#define KST 68
#define ASD 65
#define PA_SMEM ((128*KST*2 + 64*256 + 64*ASD + 256) * 4)

__global__ __launch_bounds__(256) void phaseA_kernel(const float* __restrict__ conv,
        const float* __restrict__ gbuf, const float* __restrict__ betabuf,
        float* __restrict__ Pout, float* __restrict__ Lout,
        float* __restrict__ Vn, float* __restrict__ Kc, float* __restrict__ KfT,
        float* __restrict__ eglout)
{
    extern __shared__ float sm[];
    float* kst = sm;
    float* qst = kst + 128 * KST;
    float* ws  = qst + 128 * KST;
    float* As  = ws + 64 * 256;          // 64 x ASD
    float* gc  = As + 64 * ASD;
    float* egc = gc + 64;
    float* egr = egc + 64;
    float* bts = egr + 64;

    int cid = blockIdx.x;
    int n = cid & 63, bh = cid >> 6, h = bh & 7, b = bh >> 3;
    int tid = threadIdx.x;
    int warp = tid >> 5, lane = tid & 31;
    int t0 = n * 64;

    if (tid < 64) {
        int t = t0 + tid;
        gc[tid]  = gbuf[((size_t)(b * TT + t)) * 8 + h];
        bts[tid] = betabuf[((size_t)(b * TT + t)) * 8 + h];
    }
    __syncthreads();
#pragma unroll
    for (int off = 1; off < 64; off <<= 1) {
        float v = 0.f;
        if (tid < 64 && tid >= off) v = gc[tid - off];
        __syncthreads();
        if (tid < 64 && tid >= off) gc[tid] += v;
        __syncthreads();
    }
    if (tid < 64) {
        egc[tid] = __expf(gc[tid]);
        egr[tid] = __expf(gc[63] - gc[tid]);
    }
    __syncthreads();

    for (int r = warp; r < 64; r += 8) {
        int t = t0 + r;
        const float* base = conv + ((size_t)(b * TT + t)) * 3072 + h * 128;
        float qv[4], kv[4];
        float ssq = 0.f, ssk = 0.f;
#pragma unroll
        for (int u = 0; u < 4; u++) {
            qv[u] = base[lane + u * 32];
            kv[u] = base[1024 + lane + u * 32];
            ssq += qv[u] * qv[u];
            ssk += kv[u] * kv[u];
        }
#pragma unroll
        for (int off = 16; off; off >>= 1) {
            ssq += __shfl_xor_sync(0xffffffffu, ssq, off);
            ssk += __shfl_xor_sync(0xffffffffu, ssk, off);
        }
        float rq = rsqrtf(ssq + 1e-6f) * 0.08838834764831845f;
        float rk = rsqrtf(ssk + 1e-6f);
        float bbv = bts[r], egv = egc[r];
#pragma unroll
        for (int u = 0; u < 4; u++) {
            int d = lane + u * 32;
            qst[d * KST + r] = qv[u] * rq;
            float kn = kv[u] * rk;
            kst[d * KST + r] = kn;
            ws[r * 256 + d]       = base[2048 + d] * bbv;
            ws[r * 256 + 128 + d] = kn * bbv * egv;
        }
    }
    __syncthreads();

    int ti = tid >> 4, tj = tid & 15;

    // A[i][j] = beta_i (k_i . k_j) exp(gc_i - gc_j), j < i; else 0
    {
        float acc[4][4];
#pragma unroll
        for (int r = 0; r < 4; r++)
#pragma unroll
            for (int s = 0; s < 4; s++) acc[r][s] = 0.f;
        const float* ka = kst + ti * 4;
        const float* kb = kst + tj * 4;
#pragma unroll 4
        for (int d = 0; d < 128; d++) {
            float4 a = *(const float4*)(ka + d * KST);
            float4 bq = *(const float4*)(kb + d * KST);
            float ra[4] = {a.x, a.y, a.z, a.w};
            float rb[4] = {bq.x, bq.y, bq.z, bq.w};
#pragma unroll
            for (int r = 0; r < 4; r++)
#pragma unroll
                for (int s = 0; s < 4; s++) acc[r][s] += ra[r] * rb[s];
        }
#pragma unroll
        for (int r = 0; r < 4; r++) {
            int i = ti * 4 + r;
#pragma unroll
            for (int s = 0; s < 4; s++) {
                int j = tj * 4 + s;
                As[i * ASD + j] = (j < i) ? acc[r][s] * bts[i] * __expf(gc[i] - gc[j]) : 0.f;
            }
        }
    }
    __syncthreads();

    // blocked forward substitution: ws <- (I+A)^{-1} ws
    for (int blk = 0; blk < 4; blk++) {
        if (blk) {
            int tr = tid >> 7, tc = tid & 127;
            float acc[8][2];
#pragma unroll
            for (int r = 0; r < 8; r++) { acc[r][0] = 0.f; acc[r][1] = 0.f; }
            for (int j = 0; j < blk * 16; j++) {
                float2 wv = *(const float2*)(ws + j * 256 + tc * 2);
#pragma unroll
                for (int r = 0; r < 8; r++) {
                    float a = As[(blk * 16 + tr * 8 + r) * ASD + j];
                    acc[r][0] += a * wv.x;
                    acc[r][1] += a * wv.y;
                }
            }
#pragma unroll
            for (int r = 0; r < 8; r++) {
                float* w = ws + (blk * 16 + tr * 8 + r) * 256 + tc * 2;
                w[0] -= acc[r][0];
                w[1] -= acc[r][1];
            }
            __syncthreads();
        }
        {
            int c = tid;
            int i0 = blk * 16;
            for (int i = i0 + 1; i < i0 + 16; i++) {
                float acc = 0.f;
                for (int j = i0; j < i; j++) acc += As[i * ASD + j] * ws[j * 256 + c];
                ws[i * 256 + c] -= acc;
            }
        }
        __syncthreads();
    }

    // attn[i][j] = (q_i . k_j) exp(gc_i - gc_j), j <= i; else 0 (overwrite As)
    {
        float acc[4][4];
#pragma unroll
        for (int r = 0; r < 4; r++)
#pragma unroll
            for (int s = 0; s < 4; s++) acc[r][s] = 0.f;
        const float* qa = qst + ti * 4;
        const float* kb = kst + tj * 4;
#pragma unroll 4
        for (int d = 0; d < 128; d++) {
            float4 a = *(const float4*)(qa + d * KST);
            float4 bq = *(const float4*)(kb + d * KST);
            float ra[4] = {a.x, a.y, a.z, a.w};
            float rb[4] = {bq.x, bq.y, bq.z, bq.w};
#pragma unroll
            for (int r = 0; r < 4; r++)
#pragma unroll
                for (int s = 0; s < 4; s++) acc[r][s] += ra[r] * rb[s];
        }
#pragma unroll
        for (int r = 0; r < 4; r++) {
            int i = ti * 4 + r;
#pragma unroll
            for (int s = 0; s < 4; s++) {
                int j = tj * 4 + s;
                As[i * ASD + j] = (j <= i) ? acc[r][s] * __expf(gc[i] - gc[j]) : 0.f;
            }
        }
    }
    __syncthreads();

    // [L | attn@k_cum] = attn @ ws ;  P = q*e^gc - attn@k_cum
    {
        int tr = warp;
        int tc = lane;
        float acc[8][8];
#pragma unroll
        for (int r = 0; r < 8; r++)
#pragma unroll
            for (int u = 0; u < 8; u++) acc[r][u] = 0.f;
        int jmax = tr * 8 + 8;
        for (int j = 0; j < jmax; j++) {
            float av[8];
#pragma unroll
            for (int r = 0; r < 8; r++) av[r] = As[(tr * 8 + r) * ASD + j];
            float4 w0 = *(const float4*)(ws + j * 256 + tc * 8);
            float4 w1 = *(const float4*)(ws + j * 256 + tc * 8 + 4);
            float rb[8] = {w0.x, w0.y, w0.z, w0.w, w1.x, w1.y, w1.z, w1.w};
#pragma unroll
            for (int r = 0; r < 8; r++)
#pragma unroll
                for (int u = 0; u < 8; u++) acc[r][u] += av[r] * rb[u];
        }
        if (tc < 16) {
#pragma unroll
            for (int r = 0; r < 8; r++) {
                int i = tr * 8 + r;
                float* dst = Lout + ((size_t)cid * 64 + i) * 128 + tc * 8;
                *(float4*)(dst)     = make_float4(acc[r][0], acc[r][1], acc[r][2], acc[r][3]);
                *(float4*)(dst + 4) = make_float4(acc[r][4], acc[r][5], acc[r][6], acc[r][7]);
            }
        } else {
            int c0 = tc * 8 - 128;
#pragma unroll
            for (int r = 0; r < 8; r++) {
                int i = tr * 8 + r;
                float eg = egc[i];
                float v[8];
#pragma unroll
                for (int u = 0; u < 8; u++)
                    v[u] = qst[(c0 + u) * KST + i] * eg - acc[r][u];
                float* dst = Pout + ((size_t)cid * 64 + i) * 128 + c0;
                *(float4*)(dst)     = make_float4(v[0], v[1], v[2], v[3]);
                *(float4*)(dst + 4) = make_float4(v[4], v[5], v[6], v[7]);
            }
        }
    }

    // export v_new, -k_cum ([i][d], coalesced) and keff^T ([a][i])
    for (int idx = tid; idx < 2048; idx += 256) {
        int row = idx >> 5, col = (idx & 31) * 4;
        *(float4*)(Vn + (size_t)cid * 8192 + row * 128 + col) =
            *(const float4*)(ws + row * 256 + col);
        float4 kv = *(const float4*)(ws + row * 256 + 128 + col);
        *(float4*)(Kc + (size_t)cid * 8192 + row * 128 + col) =
            make_float4(-kv.x, -kv.y, -kv.z, -kv.w);
    }
    for (int idx = tid; idx < 2048; idx += 256) {
        int a = idx >> 4, ig = (idx & 15) * 4;
        float4 v;
        v.x = kst[a * KST + ig]     * egr[ig];
        v.y = kst[a * KST + ig + 1] * egr[ig + 1];
        v.z = kst[a * KST + ig + 2] * egr[ig + 2];
        v.w = kst[a * KST + ig + 3] * egr[ig + 3];
        *(float4*)(KfT + (size_t)cid * 8192 + a * 64 + ig) = v;
    }
    if (tid == 0) eglout[cid] = __expf(gc[63]);
}

// ---------------- Phase B: sequential scan, cp.async double-buffered ------------
// tmp = v_new + (-k_cum)@S ; out = L + P@S ; S' = egl*S + keff^T@tmp  (FFMA2)
#define PSD 132
#define KFD 68
#define PB_BUF (64*PSD + 64*PSD + 128*KFD)       // floats per stage buffer = 25600
#define PB_SMEM ((2*PB_BUF + 64*16 + 128*16) * 4)  // 217088 bytes

__global__ __launch_bounds__(256) void phaseB_kernel(const float* __restrict__ Pm,
        const float* __restrict__ Lm, const float* __restrict__ Kcm,
        const float* __restrict__ KfTm, const float* __restrict__ Vnm,
        const float* __restrict__ eglv, float* __restrict__ core)
{
    extern __shared__ float sm[];
    float* Tm = sm + 2 * PB_BUF;     // 64 x 16
    float* Ss = Tm + 64 * 16;        // 128 x 16
    unsigned smemBase = (unsigned)__cvta_generic_to_shared(sm);

    int bh = blockIdx.x, gg = blockIdx.y;
    int b = bh >> 3, h = bh & 7;
    int tid = threadIdx.x;
    int c4g = tid & 3;
    int i0 = tid >> 2;               // 0..63
    int c0 = gg * 16;

    int srow = tid >> 5, scol = (tid & 31) * 4;
    int sa = tid >> 4, sig = (tid & 15) * 4;

    for (int i = tid; i < 128 * 16; i += 256) Ss[i] = 0.f;
    __syncthreads();

    auto stage = [&](int n, int bf) {
        size_t cid = (size_t)bh * 64 + n;
        const float* Pg = Pm + cid * 8192;
        const float* Kg = Kcm + cid * 8192;
        const float* Fg = KfTm + cid * 8192;
        unsigned base = smemBase + (unsigned)(bf * PB_BUF) * 4;
        unsigned kcB = base + (unsigned)(64 * PSD) * 4;
        unsigned kfB = kcB + (unsigned)(64 * PSD) * 4;
#pragma unroll
        for (int u = 0; u < 8; u++) {
            int row = srow + u * 8;
            unsigned off = (unsigned)(row * PSD + scol) * 4;
            CP_ASYNC16(base + off, Pg + row * 128 + scol);
            CP_ASYNC16(kcB + off, Kg + row * 128 + scol);
            int a = sa + u * 16;
            CP_ASYNC16(kfB + (unsigned)(a * KFD + sig) * 4, Fg + a * 64 + sig);
        }
        CP_COMMIT();
    };

    stage(0, 0);

    int buf = 0;
    for (int n = 0; n < 64; n++) {
        size_t cid = (size_t)bh * 64 + n;
        float4 accO = *(const float4*)(Lm + cid * 8192 + i0 * 128 + c0 + c4g * 4);
        float4 accT = *(const float4*)(Vnm + cid * 8192 + i0 * 128 + c0 + c4g * 4);
        float eg = eglv[cid];

        if (n + 1 < 64) { stage(n + 1, buf ^ 1); CP_WAIT1(); }
        else           { CP_WAIT0(); }
        __syncthreads();

        const float* Ps  = sm + buf * PB_BUF;
        const float* Kcs = Ps + 64 * PSD;
        const float* Kft = Kcs + 64 * PSD;

        {
            unsigned long long o01 = pk2(accO.x, accO.y), o23 = pk2(accO.z, accO.w);
            unsigned long long t01 = pk2(accT.x, accT.y), t23 = pk2(accT.z, accT.w);
            for (int a = 0; a < 128; a++) {
                float p  = Ps[i0 * PSD + a];
                float nk = Kcs[i0 * PSD + a];          // already negated
                ulonglong2 s2 = *(const ulonglong2*)(Ss + a * 16 + c4g * 4);
                unsigned long long p2 = pk2(p, p);
                unsigned long long k2 = pk2(nk, nk);
                FMA2(o01, p2, s2.x); FMA2(o23, p2, s2.y);
                FMA2(t01, k2, s2.x); FMA2(t23, k2, s2.y);
            }
            float2 oa = upk2(o01), ob = upk2(o23);
            float2 ta = upk2(t01), tb = upk2(t23);
            int t = n * 64 + i0;
            *(float4*)(core + (((size_t)(b * TT + t)) * 8 + h) * 128 + c0 + c4g * 4) =
                make_float4(oa.x, oa.y, ob.x, ob.y);
            *(float4*)(Tm + i0 * 16 + c4g * 4) = make_float4(ta.x, ta.y, tb.x, tb.y);
        }
        __syncthreads();

        float4 s0 = *(const float4*)(Ss + i0 * 16 + c4g * 4);
        float4 s1 = *(const float4*)(Ss + (i0 + 64) * 16 + c4g * 4);
        {
            unsigned long long n0a = pk2(eg * s0.x, eg * s0.y);
            unsigned long long n0b = pk2(eg * s0.z, eg * s0.w);
            unsigned long long n1a = pk2(eg * s1.x, eg * s1.y);
            unsigned long long n1b = pk2(eg * s1.z, eg * s1.w);
            for (int i = 0; i < 64; i++) {
                ulonglong2 t2 = *(const ulonglong2*)(Tm + i * 16 + c4g * 4);
                float f0 = Kft[i0 * KFD + i];
                float f1 = Kft[(i0 + 64) * KFD + i];
                unsigned long long f02 = pk2(f0, f0);
                unsigned long long f12 = pk2(f1, f1);
                FMA2(n0a, f02, t2.x); FMA2(n0b, f02, t2.y);
                FMA2(n1a, f12, t2.x); FMA2(n1b, f12, t2.y);
            }
            float2 ua = upk2(n0a), ub = upk2(n0b);
            float2 va = upk2(n1a), vb = upk2(n1b);
            *(float4*)(Ss + i0 * 16 + c4g * 4) = make_float4(ua.x, ua.y, ub.x, ub.y);
            *(float4*)(Ss + (i0 + 64) * 16 + c4g * 4) = make_float4(va.x, va.y, vb.x, vb.y);
        }
        __syncthreads();
        buf ^= 1;
    }
}

// ---------------- gated RMSNorm * silu(z) -> f16 hi/lo ---------------------------
__global__ __launch_bounds__(128) void norm_kernel(const float* __restrict__ core,
        const float* __restrict__ qkvz, const float* __restrict__ nw,
        __half* __restrict__ hh, __half* __restrict__ hl)
{
    int bth = blockIdx.x;
    int d = threadIdx.x;
    float cv = core[(size_t)bth * 128 + d];
    float ss = cv * cv;
#pragma unroll
    for (int o = 16; o; o >>= 1) ss += __shfl_xor_sync(0xffffffffu, ss, o);
    __shared__ float red[4];
    if ((d & 31) == 0) red[d >> 5] = ss;
    __syncthreads();
    float tot = red[0] + red[1] + red[2] + red[3];
    float r = rsqrtf(tot * (1.f / 128.f) + 1e-6f);
    float zz = qkvz[(size_t)bth * 512 + 384 + d];
    float sz = zz / (1.f + __expf(-zz));
    float hv = nw[d] * cv * r * sz;
    __half h = __float2half_rn(hv);
    size_t o = (size_t)bth * 128 + d;
    hh[o] = h;
    hl[o] = __float2half_rn(hv - __half2float(h));
}

// ---------------- launch ---------------------------------------------------------
extern "C" void kernel_launch(void* const* d_in, const int* in_sizes, int n_in,
                              void* d_out, int out_size)
{
    (void)in_sizes; (void)n_in; (void)out_size;
    const float* x    = (const float*)d_in[0];
    const float* Wq   = (const float*)d_in[1];
    const float* Wba  = (const float*)d_in[2];
    const float* cw   = (const float*)d_in[3];
    const float* dtb  = (const float*)d_in[4];
    const float* Alog = (const float*)d_in[5];
    const float* nw   = (const float*)d_in[6];
    const float* Wout = (const float*)d_in[7];
    float* out = (float*)d_out;

    float *qkvz, *convb, *gb, *betab, *Pb, *Lb, *vnb, *kcb, *kfb, *eglb, *coreb;
    __half *xh, *xl, *w1h, *w2h, *hh, *hl;
    cudaGetSymbolAddress((void**)&qkvz,  g_qkvz);
    cudaGetSymbolAddress((void**)&convb, g_conv);
    cudaGetSymbolAddress((void**)&gb,    g_g);
    cudaGetSymbolAddress((void**)&betab, g_beta);
    cudaGetSymbolAddress((void**)&Pb,    g_P);
    cudaGetSymbolAddress((void**)&Lb,    g_L);
    cudaGetSymbolAddress((void**)&vnb,   g_vn);
    cudaGetSymbolAddress((void**)&kcb,   g_kc);
    cudaGetSymbolAddress((void**)&kfb,   g_kf);
    cudaGetSymbolAddress((void**)&eglb,  g_egl);
    cudaGetSymbolAddress((void**)&coreb, g_core);
    cudaGetSymbolAddress((void**)&xh,  g_xh);
    cudaGetSymbolAddress((void**)&xl,  g_xl);
    cudaGetSymbolAddress((void**)&w1h, g_w1h);
    cudaGetSymbolAddress((void**)&w2h, g_w2h);
    cudaGetSymbolAddress((void**)&hh,  g_hh);
    cudaGetSymbolAddress((void**)&hl,  g_hl);

    cudaFuncSetAttribute(phaseA_kernel, cudaFuncAttributeMaxDynamicSharedMemorySize, PA_SMEM);
    cudaFuncSetAttribute(phaseB_kernel, cudaFuncAttributeMaxDynamicSharedMemorySize, PB_SMEM);
    cudaFuncSetAttribute(f16gemm128, cudaFuncAttributeMaxDynamicSharedMemorySize, GEMM_SMEM);

    // 0. operand conversion (bandwidth-bound)
    cvt_split_kernel<<<(BB * TT * CC / 4) / 256, 256>>>(x, xh, xl);
    transpose_h_kernel<<<dim3(4096 / 32, CC / 32), 256>>>(Wq, w1h, CC, 4096);
    transpose_h_kernel<<<dim3(1024 / 32, CC / 32), 256>>>(Wout, w2h, CC, 1024);

    // 1. qkvz = x @ W_qkvz  (2xf16-split)
    dim3 g1(4096 / 128, 8192 / 128);
    f16gemm128<<<g1, 256, GEMM_SMEM>>>(BB * TT, 4096, CC, xh, xl, w1h, qkvz);
    // 2. ba = x @ W_ba fused with g/beta
    ba_gbeta_kernel<<<BB * TT, 256>>>(x, Wba, dtb, Alog, gb, betab);
    // 3. conv + silu
    conv_silu_kernel<<<(BB * TT * 3072) / 256, 256>>>(qkvz, cw, convb);
    // 4. phase A (exports P, L, v_new, -k_cum, keff^T)
    phaseA_kernel<<<NCID, 256, PA_SMEM>>>(convb, gb, betab, Pb, Lb, vnb, kcb, kfb, eglb);
    // 5. phase B
    dim3 gB(16, 8);
    phaseB_kernel<<<gB, 256, PB_SMEM>>>(Pb, Lb, kcb, kfb, vnb, eglb, coreb);
    // 6. gated RMSNorm * silu(z) -> f16 hi/lo
    norm_kernel<<<BB * TT * NH, 128>>>(coreb, qkvz, nw, hh, hl);
    // 7. final projection (2xf16-split)
    dim3 g2(1024 / 128, 8192 / 128);
    f16gemm128<<<g2, 256, GEMM_SMEM>>>(BB * TT, 1024, CC, hh, hl, w2h, out);
}